// round 9
// baseline (speedup 1.0000x reference)
#include <cuda_runtime.h>
#include <cuda_bf16.h>
#include <math.h>
#include <cstdint>

#define SEQ 2048
#define NH  16
#define HD  80
#define HDP 96              // padded head dim for Q/K (K chunks of 32)
#define HDV 128             // padded head dim for V^T (one 128-col N tile)
#define DIM 1280            // NH*HD
#define QKV_N 3840          // 3*DIM
#define ATTN_SCALE 0.11180339887498949f   // 80^-0.5

// ---------------- scratch (device globals; no allocations allowed) ----------
__device__ float g_qkv[SEQ * QKV_N];          // 31.5 MB
__device__ float g_s[(size_t)NH * SEQ * SEQ]; // 256 MB scores
__device__ float g_o[SEQ * DIM];

__device__ __nv_bfloat16 g_qh[NH * SEQ * HDP];
__device__ __nv_bfloat16 g_ql[NH * SEQ * HDP];
__device__ __nv_bfloat16 g_kh[NH * SEQ * HDP];
__device__ __nv_bfloat16 g_kl[NH * SEQ * HDP];
__device__ __nv_bfloat16 g_vth[NH * HDV * SEQ];   // V^T padded
__device__ __nv_bfloat16 g_vtl[NH * HDV * SEQ];
__device__ __nv_bfloat16 g_ph[(size_t)NH * SEQ * SEQ];  // 128 MB
__device__ __nv_bfloat16 g_pl[(size_t)NH * SEQ * SEQ];

__device__ __nv_bfloat16 g_hid_hi[SEQ * DIM];
__device__ __nv_bfloat16 g_hid_lo[SEQ * DIM];
__device__ __nv_bfloat16 g_wqkv_hi[QKV_N * DIM];
__device__ __nv_bfloat16 g_wqkv_lo[QKV_N * DIM];
__device__ __nv_bfloat16 g_o_hi[SEQ * DIM];
__device__ __nv_bfloat16 g_o_lo[SEQ * DIM];
__device__ __nv_bfloat16 g_wproj_hi[DIM * DIM];
__device__ __nv_bfloat16 g_wproj_lo[DIM * DIM];

// ================= helpers ====================================================
__device__ __forceinline__ uint32_t smem_u32(const void* p) {
    uint32_t a;
    asm("{ .reg .u64 t; cvta.to.shared.u64 t, %1; cvt.u32.u64 %0, t; }" : "=r"(a) : "l"(p));
    return a;
}
#define CP_ASYNC16(dst, src) \
    asm volatile("cp.async.cg.shared.global [%0], [%1], 16;" :: "r"(dst), "l"(src) : "memory")
#define CP_COMMIT() asm volatile("cp.async.commit_group;" ::: "memory")
#define CP_WAIT1()  asm volatile("cp.async.wait_group 1;" ::: "memory")
#define CP_WAIT0()  asm volatile("cp.async.wait_group 0;" ::: "memory")

#define LDSM_X4(r0, r1, r2, r3, addr) \
    asm volatile("ldmatrix.sync.aligned.m8n8.x4.shared.b16 {%0,%1,%2,%3}, [%4];" \
        : "=r"(r0), "=r"(r1), "=r"(r2), "=r"(r3) : "r"(addr))

#define MMA16816(c, a, b0, b1) \
    asm volatile("mma.sync.aligned.m16n8k16.row.col.f32.bf16.bf16.f32 " \
        "{%0,%1,%2,%3}, {%4,%5,%6,%7}, {%8,%9}, {%0,%1,%2,%3};" \
        : "+f"((c)[0]), "+f"((c)[1]), "+f"((c)[2]), "+f"((c)[3]) \
        : "r"((a)[0]), "r"((a)[1]), "r"((a)[2]), "r"((a)[3]), "r"(b0), "r"(b1))

__device__ __forceinline__ void split1(float v, __nv_bfloat16& h, __nv_bfloat16& l) {
    h = __float2bfloat16(v);
    l = __float2bfloat16(v - __bfloat162float(h));
}

// ================= fp32 -> bf16 hi/lo split ==================================
__global__ __launch_bounds__(256) void split_bf16(
    const float* __restrict__ x, __nv_bfloat16* __restrict__ hi,
    __nv_bfloat16* __restrict__ lo, int n)
{
    int i = blockIdx.x * blockDim.x + threadIdx.x;
    if (i >= n) return;
    float v = x[i];
    __nv_bfloat16 h = __float2bfloat16(v);
    hi[i] = h;
    lo[i] = __float2bfloat16(v - __bfloat162float(h));
}

// ================= mma.sync bf16x3 NT GEMM ===================================
// C (+bz*sC offset)[m, n] = alpha * sum_k A[bz][m,k]*B[bz][n,k] + bias[n],
// cols written only when n < n_valid.  M%128==0, (N tile)=128, K%32==0.
// Warp columns whose 32-wide tile starts at/past n_valid skip all MMA work.
#define MM_TILE_B 10240        // 128 rows * 80 bytes (40 bf16, padded from 32)
#define MM_BUF_B  (4 * MM_TILE_B)
#define MM_SMEM   (2 * MM_BUF_B)   // 81920

__global__ __launch_bounds__(256, 2) void gemm_mma_nt(
    const __nv_bfloat16* __restrict__ Ah, const __nv_bfloat16* __restrict__ Al,
    const __nv_bfloat16* __restrict__ Bh, const __nv_bfloat16* __restrict__ Bl,
    const float* __restrict__ bias, float* __restrict__ C,
    int K, size_t sA, size_t sB, size_t sC, int ldc, float alpha, int n_valid)
{
    extern __shared__ char sm[];
    const uint32_t sbase = smem_u32(sm);
    const int tid = threadIdx.x;
    const int lane = tid & 31;
    const int wid = tid >> 5;
    const int wy = wid >> 2;          // 0..1
    const int wx = wid & 3;           // 0..3
    const int m0 = blockIdx.y * 128;
    const int n0 = blockIdx.x * 128;
    const int bz = blockIdx.z;
    const int NC = K >> 5;
    const bool warp_active = (n0 + wx * 32) < n_valid;

    const __nv_bfloat16* srcs[4] = {Ah + bz * sA, Al + bz * sA,
                                    Bh + bz * sB, Bl + bz * sB};
    const int rb0 = m0, rb1 = n0;

    float acc[4][4][4];
    #pragma unroll
    for (int i = 0; i < 4; i++)
        #pragma unroll
        for (int j = 0; j < 4; j++)
            #pragma unroll
            for (int k = 0; k < 4; k++) acc[i][j][k] = 0.0f;

    auto load_chunk = [&](int c, int b) {
        const int k0 = c << 5;
        #pragma unroll
        for (int t = 0; t < 4; t++) {
            const __nv_bfloat16* src = srcs[t];
            const int rbase = (t < 2) ? rb0 : rb1;
            const uint32_t tb = sbase + b * MM_BUF_B + t * MM_TILE_B;
            #pragma unroll
            for (int i = 0; i < 2; i++) {
                const int g = tid + i * 256;       // 0..511
                const int row = g >> 2, q = g & 3;
                const uint32_t dst = tb + row * 80 + q * 16;
                const void* s = (const void*)(src + (size_t)(rbase + row) * K + k0 + q * 8);
                CP_ASYNC16(dst, s);
            }
        }
    };

    load_chunk(0, 0);
    CP_COMMIT();

    for (int c = 0; c < NC; c++) {
        if (c + 1 < NC) {
            load_chunk(c + 1, (c + 1) & 1);
            CP_COMMIT();
            CP_WAIT1();
        } else {
            CP_WAIT0();
        }
        __syncthreads();

        const int b = c & 1;
        const uint32_t bufb = sbase + b * MM_BUF_B;
        if (warp_active) {
            #pragma unroll
            for (int ks = 0; ks < 2; ks++) {
                const int fcol = ks * 16 + (lane >> 4) * 8;
                uint32_t bh[2][4], bl[2][4];
                #pragma unroll
                for (int np = 0; np < 2; np++) {
                    const int r = wx * 32 + np * 16 + (lane & 15);
                    const uint32_t bd = bufb + 2 * MM_TILE_B + r * 80 + fcol * 2;
                    LDSM_X4(bh[np][0], bh[np][1], bh[np][2], bh[np][3], bd);
                    LDSM_X4(bl[np][0], bl[np][1], bl[np][2], bl[np][3], bd + MM_TILE_B);
                }
                #pragma unroll
                for (int mt = 0; mt < 4; mt++) {
                    const int r = wy * 64 + mt * 16 + (lane & 15);
                    const uint32_t ad = bufb + r * 80 + fcol * 2;
                    uint32_t ah[4], al[4];
                    LDSM_X4(ah[0], ah[1], ah[2], ah[3], ad);
                    LDSM_X4(al[0], al[1], al[2], al[3], ad + MM_TILE_B);
                    #pragma unroll
                    for (int np = 0; np < 2; np++) {
                        MMA16816(acc[mt][np * 2],     ah, bh[np][0], bh[np][2]);
                        MMA16816(acc[mt][np * 2 + 1], ah, bh[np][1], bh[np][3]);
                    }
                    #pragma unroll
                    for (int np = 0; np < 2; np++) {
                        MMA16816(acc[mt][np * 2],     ah, bl[np][0], bl[np][2]);
                        MMA16816(acc[mt][np * 2 + 1], ah, bl[np][1], bl[np][3]);
                    }
                    #pragma unroll
                    for (int np = 0; np < 2; np++) {
                        MMA16816(acc[mt][np * 2],     al, bh[np][0], bh[np][2]);
                        MMA16816(acc[mt][np * 2 + 1], al, bh[np][1], bh[np][3]);
                    }
                }
            }
        }
        __syncthreads();
    }

    // ---- epilogue ----
    if (warp_active) {
        float* Cb = C + bz * sC;
        const int quad = lane >> 2, tq = lane & 3;
        #pragma unroll
        for (int mt = 0; mt < 4; mt++) {
            #pragma unroll
            for (int nt = 0; nt < 4; nt++) {
                const int col = n0 + wx * 32 + nt * 8 + tq * 2;
                if (col >= n_valid) continue;
                const int row = m0 + wy * 64 + mt * 16 + quad;
                float b0 = bias ? bias[col] : 0.0f;
                float b1 = bias ? bias[col + 1] : 0.0f;
                float2 v0 = make_float2(acc[mt][nt][0] * alpha + b0,
                                        acc[mt][nt][1] * alpha + b1);
                float2 v1 = make_float2(acc[mt][nt][2] * alpha + b0,
                                        acc[mt][nt][3] * alpha + b1);
                *reinterpret_cast<float2*>(Cb + (size_t)row * ldc + col) = v0;
                *reinterpret_cast<float2*>(Cb + (size_t)(row + 8) * ldc + col) = v1;
            }
        }
    }
}

// ---------------- RoPE + split to bf16 hi/lo per-head layouts ---------------
__global__ __launch_bounds__(256) void rope_split_bf16(
    const float* __restrict__ qkv, const float* __restrict__ cosp,
    const float* __restrict__ sinp,
    __nv_bfloat16* __restrict__ Qh, __nv_bfloat16* __restrict__ Ql,
    __nv_bfloat16* __restrict__ Kh, __nv_bfloat16* __restrict__ Kl,
    __nv_bfloat16* __restrict__ Vth, __nv_bfloat16* __restrict__ Vtl)
{
    int idx = blockIdx.x * blockDim.x + threadIdx.x;
    if (idx >= SEQ * DIM) return;
    const int d = idx % HD;
    const int h = (idx / HD) % NH;
    const int s = idx / DIM;

    const float c = cosp[s * HD + d];
    const float sn = sinp[s * HD + d];
    const int d2 = (d < HD / 2) ? d + HD / 2 : d - HD / 2;
    const float sign = (d < HD / 2) ? -1.0f : 1.0f;

    const size_t rowbase = (size_t)s * QKV_N + h * HD;
    const size_t oqk = ((size_t)h * SEQ + s) * HDP + d;
    const size_t ovt = ((size_t)h * HDV + d) * SEQ + s;

    const float qv = qkv[rowbase + d];
    const float q2 = qkv[rowbase + d2];
    float qr = fmaf(qv, c, sign * q2 * sn);
    split1(qr, Qh[oqk], Ql[oqk]);

    const float kv = qkv[rowbase + DIM + d];
    const float k2 = qkv[rowbase + DIM + d2];
    float kr = fmaf(kv, c, sign * k2 * sn);
    split1(kr, Kh[oqk], Kl[oqk]);

    split1(qkv[rowbase + 2 * DIM + d], Vth[ovt], Vtl[ovt]);
}

// ---------------- zero-fill pad regions --------------------------------------
__global__ __launch_bounds__(256) void pad_qk(
    __nv_bfloat16* __restrict__ Qh, __nv_bfloat16* __restrict__ Ql,
    __nv_bfloat16* __restrict__ Kh, __nv_bfloat16* __restrict__ Kl)
{
    int i = blockIdx.x * blockDim.x + threadIdx.x;      // NH*SEQ*16
    if (i >= NH * SEQ * 16) return;
    const int d = HD + (i & 15);
    const int row = i >> 4;                              // h*SEQ + s
    const size_t o = (size_t)row * HDP + d;
    Qh[o] = __nv_bfloat16(0.0f); Ql[o] = __nv_bfloat16(0.0f);
    Kh[o] = __nv_bfloat16(0.0f); Kl[o] = __nv_bfloat16(0.0f);
}
__global__ __launch_bounds__(256) void pad_vt(
    __nv_bfloat16* __restrict__ Vth, __nv_bfloat16* __restrict__ Vtl)
{
    int i = blockIdx.x * blockDim.x + threadIdx.x;      // NH*48*SEQ
    if (i >= NH * (HDV - HD) * SEQ) return;
    const int s = i % SEQ;
    const int r = (i / SEQ) % (HDV - HD);
    const int h = i / (SEQ * (HDV - HD));
    const size_t o = ((size_t)h * HDV + HD + r) * SEQ + s;
    Vth[o] = __nv_bfloat16(0.0f); Vtl[o] = __nv_bfloat16(0.0f);
}

// ---------------- row softmax, fused bf16 hi/lo split ------------------------
__global__ __launch_bounds__(256) void softmax_split(
    const float* __restrict__ S, __nv_bfloat16* __restrict__ Ph,
    __nv_bfloat16* __restrict__ Pl)
{
    const size_t base = (size_t)blockIdx.x * SEQ;
    const float* row = S + base;
    const int tid = threadIdx.x;
    __shared__ float red[256];

    float v[8];
    float mx = -1e30f;
    #pragma unroll
    for (int i = 0; i < 8; i++) {
        v[i] = row[tid + i * 256];
        mx = fmaxf(mx, v[i]);
    }
    red[tid] = mx;
    __syncthreads();
    for (int s = 128; s > 0; s >>= 1) {
        if (tid < s) red[tid] = fmaxf(red[tid], red[tid + s]);
        __syncthreads();
    }
    mx = red[0];
    __syncthreads();

    float sum = 0.0f;
    #pragma unroll
    for (int i = 0; i < 8; i++) {
        v[i] = __expf(v[i] - mx);
        sum += v[i];
    }
    red[tid] = sum;
    __syncthreads();
    for (int s = 128; s > 0; s >>= 1) {
        if (tid < s) red[tid] += red[tid + s];
        __syncthreads();
    }
    const float inv = 1.0f / red[0];
    #pragma unroll
    for (int i = 0; i < 8; i++) {
        float p = v[i] * inv;
        __nv_bfloat16 h, l;
        split1(p, h, l);
        Ph[base + tid + i * 256] = h;
        Pl[base + tid + i * 256] = l;
    }
}

// ---------------- launch -----------------------------------------------------
extern "C" void kernel_launch(void* const* d_in, const int* in_sizes, int n_in,
                              void* d_out, int out_size)
{
    const float* hidden = (const float*)d_in[0];
    const float* cosp   = (const float*)d_in[2];
    const float* sinp   = (const float*)d_in[3];
    const float* w_qkv  = (const float*)d_in[4];
    const float* b_qkv  = (const float*)d_in[5];
    const float* w_proj = (const float*)d_in[6];
    const float* b_proj = (const float*)d_in[7];
    float* out = (float*)d_out;

    float *qkv, *S, *O;
    cudaGetSymbolAddress((void**)&qkv, g_qkv);
    cudaGetSymbolAddress((void**)&S, g_s);
    cudaGetSymbolAddress((void**)&O, g_o);

    __nv_bfloat16 *hh, *hl, *wh, *wl, *oh, *ol, *prh, *prl;
    __nv_bfloat16 *qh, *ql, *kh, *kl, *vth, *vtl, *ph, *pl;
    cudaGetSymbolAddress((void**)&hh, g_hid_hi);
    cudaGetSymbolAddress((void**)&hl, g_hid_lo);
    cudaGetSymbolAddress((void**)&wh, g_wqkv_hi);
    cudaGetSymbolAddress((void**)&wl, g_wqkv_lo);
    cudaGetSymbolAddress((void**)&oh, g_o_hi);
    cudaGetSymbolAddress((void**)&ol, g_o_lo);
    cudaGetSymbolAddress((void**)&prh, g_wproj_hi);
    cudaGetSymbolAddress((void**)&prl, g_wproj_lo);
    cudaGetSymbolAddress((void**)&qh, g_qh);
    cudaGetSymbolAddress((void**)&ql, g_ql);
    cudaGetSymbolAddress((void**)&kh, g_kh);
    cudaGetSymbolAddress((void**)&kl, g_kl);
    cudaGetSymbolAddress((void**)&vth, g_vth);
    cudaGetSymbolAddress((void**)&vtl, g_vtl);
    cudaGetSymbolAddress((void**)&ph, g_ph);
    cudaGetSymbolAddress((void**)&pl, g_pl);

    cudaFuncSetAttribute(gemm_mma_nt, cudaFuncAttributeMaxDynamicSharedMemorySize,
                         MM_SMEM);

    // 0) split inputs
    split_bf16<<<(SEQ * DIM + 255) / 256, 256>>>(hidden, hh, hl, SEQ * DIM);
    split_bf16<<<(QKV_N * DIM + 255) / 256, 256>>>(w_qkv, wh, wl, QKV_N * DIM);
    split_bf16<<<(DIM * DIM + 255) / 256, 256>>>(w_proj, prh, prl, DIM * DIM);

    // 1) QKV = hidden @ w_qkv^T + b_qkv
    {
        dim3 grid(QKV_N / 128, SEQ / 128, 1);
        gemm_mma_nt<<<grid, 256, MM_SMEM>>>(hh, hl, wh, wl, b_qkv, qkv,
                                            DIM, 0, 0, 0, QKV_N, 1.0f, QKV_N);
    }
    // 2) RoPE + per-head bf16 layouts (+ pad zeros)
    pad_qk<<<(NH * SEQ * 16 + 255) / 256, 256>>>(qh, ql, kh, kl);
    pad_vt<<<(NH * (HDV - HD) * SEQ + 255) / 256, 256>>>(vth, vtl);
    rope_split_bf16<<<(SEQ * DIM + 255) / 256, 256>>>(qkv, cosp, sinp,
                                                      qh, ql, kh, kl, vth, vtl);

    // 3) S[h] = scale * Q[h] @ K[h]^T   (mma, K=96)
    {
        dim3 grid(SEQ / 128, SEQ / 128, NH);
        gemm_mma_nt<<<grid, 256, MM_SMEM>>>(qh, ql, kh, kl, nullptr, S,
                                            HDP, (size_t)SEQ * HDP, (size_t)SEQ * HDP,
                                            (size_t)SEQ * SEQ, SEQ, ATTN_SCALE, SEQ);
    }
    // 4) softmax + split P to bf16 hi/lo
    softmax_split<<<NH * SEQ, 256>>>(S, ph, pl);

    // 5) O[s, h*80+d] = P[h] @ V[h]  (mma: A=P, B=V^T, N=128 padded, 80 valid)
    {
        dim3 grid(1, SEQ / 128, NH);
        gemm_mma_nt<<<grid, 256, MM_SMEM>>>(ph, pl, vth, vtl, nullptr, O,
                                            SEQ, (size_t)SEQ * SEQ, (size_t)HDV * SEQ,
                                            (size_t)HD, DIM, 1.0f, HD);
    }
    // 6) out = O @ w_proj^T + b_proj
    split_bf16<<<(SEQ * DIM + 255) / 256, 256>>>(O, oh, ol, SEQ * DIM);
    {
        dim3 grid(DIM / 128, SEQ / 128, 1);
        gemm_mma_nt<<<grid, 256, MM_SMEM>>>(oh, ol, prh, prl, b_proj, out,
                                            DIM, 0, 0, 0, DIM, 1.0f, DIM);
    }
}

// round 10
// speedup vs baseline: 1.0491x; 1.0491x over previous
#include <cuda_runtime.h>
#include <cuda_bf16.h>
#include <math.h>
#include <cstdint>

#define SEQ 2048
#define NH  16
#define HD  80
#define HDP 96              // padded head dim for Q/K (K chunks of 32)
#define HDV 128             // padded head dim for V^T (one 128-col N tile)
#define DIM 1280            // NH*HD
#define QKV_N 3840          // 3*DIM
#define ATTN_SCALE 0.11180339887498949f   // 80^-0.5

// ---------------- scratch (device globals; no allocations allowed) ----------
__device__ float g_qkv[SEQ * QKV_N];          // 31.5 MB
__device__ float g_o[SEQ * DIM];
__device__ float g_psum[NH * 16 * SEQ];       // per-(head, n-tile) row partial sums
__device__ float g_rowinv[NH * SEQ];          // 1 / rowsum

__device__ __nv_bfloat16 g_qh[NH * SEQ * HDP];
__device__ __nv_bfloat16 g_ql[NH * SEQ * HDP];
__device__ __nv_bfloat16 g_kh[NH * SEQ * HDP];
__device__ __nv_bfloat16 g_kl[NH * SEQ * HDP];
__device__ __nv_bfloat16 g_vth[NH * HDV * SEQ];   // V^T padded
__device__ __nv_bfloat16 g_vtl[NH * HDV * SEQ];
__device__ __nv_bfloat16 g_ph[(size_t)NH * SEQ * SEQ];  // 128 MB (unnormalized expS)
__device__ __nv_bfloat16 g_pl[(size_t)NH * SEQ * SEQ];

__device__ __nv_bfloat16 g_hid_hi[SEQ * DIM];
__device__ __nv_bfloat16 g_hid_lo[SEQ * DIM];
__device__ __nv_bfloat16 g_wqkv_hi[QKV_N * DIM];
__device__ __nv_bfloat16 g_wqkv_lo[QKV_N * DIM];
__device__ __nv_bfloat16 g_o_hi[SEQ * DIM];
__device__ __nv_bfloat16 g_o_lo[SEQ * DIM];
__device__ __nv_bfloat16 g_wproj_hi[DIM * DIM];
__device__ __nv_bfloat16 g_wproj_lo[DIM * DIM];

// ================= helpers ====================================================
__device__ __forceinline__ uint32_t smem_u32(const void* p) {
    uint32_t a;
    asm("{ .reg .u64 t; cvta.to.shared.u64 t, %1; cvt.u32.u64 %0, t; }" : "=r"(a) : "l"(p));
    return a;
}
#define CP_ASYNC16(dst, src) \
    asm volatile("cp.async.cg.shared.global [%0], [%1], 16;" :: "r"(dst), "l"(src) : "memory")
#define CP_COMMIT() asm volatile("cp.async.commit_group;" ::: "memory")
#define CP_WAIT1()  asm volatile("cp.async.wait_group 1;" ::: "memory")
#define CP_WAIT0()  asm volatile("cp.async.wait_group 0;" ::: "memory")

#define LDSM_X4(r0, r1, r2, r3, addr) \
    asm volatile("ldmatrix.sync.aligned.m8n8.x4.shared.b16 {%0,%1,%2,%3}, [%4];" \
        : "=r"(r0), "=r"(r1), "=r"(r2), "=r"(r3) : "r"(addr))

#define MMA16816(c, a, b0, b1) \
    asm volatile("mma.sync.aligned.m16n8k16.row.col.f32.bf16.bf16.f32 " \
        "{%0,%1,%2,%3}, {%4,%5,%6,%7}, {%8,%9}, {%0,%1,%2,%3};" \
        : "+f"((c)[0]), "+f"((c)[1]), "+f"((c)[2]), "+f"((c)[3]) \
        : "r"((a)[0]), "r"((a)[1]), "r"((a)[2]), "r"((a)[3]), "r"(b0), "r"(b1))

__device__ __forceinline__ void split1(float v, __nv_bfloat16& h, __nv_bfloat16& l) {
    h = __float2bfloat16(v);
    l = __float2bfloat16(v - __bfloat162float(h));
}

// ================= fp32 -> bf16 hi/lo split ==================================
__global__ __launch_bounds__(256) void split_bf16(
    const float* __restrict__ x, __nv_bfloat16* __restrict__ hi,
    __nv_bfloat16* __restrict__ lo, int n)
{
    int i = blockIdx.x * blockDim.x + threadIdx.x;
    if (i >= n) return;
    float v = x[i];
    __nv_bfloat16 h = __float2bfloat16(v);
    hi[i] = h;
    lo[i] = __float2bfloat16(v - __bfloat162float(h));
}

// ================= mma.sync bf16x3 NT GEMM ===================================
// Common mainloop; two epilogues:
//  - Ph == nullptr: C[m,n] = alpha*acc (*rowinv[m] if given) + bias[n], n<n_valid
//  - Ph != nullptr: exp-split epilogue (softmax fusion):
//        e = expf(alpha*acc); Ph/Pl get hi/lo bf16 of e;
//        per-CTA row sums of e -> psum[(bz*gridDim.x + bx)*M + m]
#define MM_TILE_B 10240        // 128 rows * 80 bytes (40 bf16, padded from 32)
#define MM_BUF_B  (4 * MM_TILE_B)
#define MM_SMEM   (2 * MM_BUF_B)   // 81920

__global__ __launch_bounds__(256, 2) void gemm_mma_nt(
    const __nv_bfloat16* __restrict__ Ah, const __nv_bfloat16* __restrict__ Al,
    const __nv_bfloat16* __restrict__ Bh, const __nv_bfloat16* __restrict__ Bl,
    const float* __restrict__ bias, float* __restrict__ C,
    int K, size_t sA, size_t sB, size_t sC, int ldc, float alpha, int n_valid,
    __nv_bfloat16* __restrict__ Ph, __nv_bfloat16* __restrict__ Pl,
    float* __restrict__ psum, const float* __restrict__ rowinv)
{
    extern __shared__ char sm[];
    const uint32_t sbase = smem_u32(sm);
    const int tid = threadIdx.x;
    const int lane = tid & 31;
    const int wid = tid >> 5;
    const int wy = wid >> 2;          // 0..1
    const int wx = wid & 3;           // 0..3
    const int m0 = blockIdx.y * 128;
    const int n0 = blockIdx.x * 128;
    const int bz = blockIdx.z;
    const int NC = K >> 5;
    const bool warp_active = (n0 + wx * 32) < n_valid;

    const __nv_bfloat16* srcs[4] = {Ah + bz * sA, Al + bz * sA,
                                    Bh + bz * sB, Bl + bz * sB};
    const int rb0 = m0, rb1 = n0;

    float acc[4][4][4];
    #pragma unroll
    for (int i = 0; i < 4; i++)
        #pragma unroll
        for (int j = 0; j < 4; j++)
            #pragma unroll
            for (int k = 0; k < 4; k++) acc[i][j][k] = 0.0f;

    auto load_chunk = [&](int c, int b) {
        const int k0 = c << 5;
        #pragma unroll
        for (int t = 0; t < 4; t++) {
            const __nv_bfloat16* src = srcs[t];
            const int rbase = (t < 2) ? rb0 : rb1;
            const uint32_t tb = sbase + b * MM_BUF_B + t * MM_TILE_B;
            #pragma unroll
            for (int i = 0; i < 2; i++) {
                const int g = tid + i * 256;       // 0..511
                const int row = g >> 2, q = g & 3;
                const uint32_t dst = tb + row * 80 + q * 16;
                const void* s = (const void*)(src + (size_t)(rbase + row) * K + k0 + q * 8);
                CP_ASYNC16(dst, s);
            }
        }
    };

    load_chunk(0, 0);
    CP_COMMIT();

    for (int c = 0; c < NC; c++) {
        if (c + 1 < NC) {
            load_chunk(c + 1, (c + 1) & 1);
            CP_COMMIT();
            CP_WAIT1();
        } else {
            CP_WAIT0();
        }
        __syncthreads();

        const int b = c & 1;
        const uint32_t bufb = sbase + b * MM_BUF_B;
        if (warp_active) {
            #pragma unroll
            for (int ks = 0; ks < 2; ks++) {
                const int fcol = ks * 16 + (lane >> 4) * 8;
                uint32_t bh[2][4], bl[2][4];
                #pragma unroll
                for (int np = 0; np < 2; np++) {
                    const int r = wx * 32 + np * 16 + (lane & 15);
                    const uint32_t bd = bufb + 2 * MM_TILE_B + r * 80 + fcol * 2;
                    LDSM_X4(bh[np][0], bh[np][1], bh[np][2], bh[np][3], bd);
                    LDSM_X4(bl[np][0], bl[np][1], bl[np][2], bl[np][3], bd + MM_TILE_B);
                }
                #pragma unroll
                for (int mt = 0; mt < 4; mt++) {
                    const int r = wy * 64 + mt * 16 + (lane & 15);
                    const uint32_t ad = bufb + r * 80 + fcol * 2;
                    uint32_t ah[4], al[4];
                    LDSM_X4(ah[0], ah[1], ah[2], ah[3], ad);
                    LDSM_X4(al[0], al[1], al[2], al[3], ad + MM_TILE_B);
                    #pragma unroll
                    for (int np = 0; np < 2; np++) {
                        MMA16816(acc[mt][np * 2],     ah, bh[np][0], bh[np][2]);
                        MMA16816(acc[mt][np * 2 + 1], ah, bh[np][1], bh[np][3]);
                    }
                    #pragma unroll
                    for (int np = 0; np < 2; np++) {
                        MMA16816(acc[mt][np * 2],     ah, bl[np][0], bl[np][2]);
                        MMA16816(acc[mt][np * 2 + 1], ah, bl[np][1], bl[np][3]);
                    }
                    #pragma unroll
                    for (int np = 0; np < 2; np++) {
                        MMA16816(acc[mt][np * 2],     al, bh[np][0], bh[np][2]);
                        MMA16816(acc[mt][np * 2 + 1], al, bh[np][1], bh[np][3]);
                    }
                }
            }
        }
        __syncthreads();
    }

    const int quad = lane >> 2, tq = lane & 3;

    if (Ph) {
        // ---- exp + hi/lo split epilogue (fused unnormalized softmax) ----
        const int Mtot = gridDim.y * 128;
        __nv_bfloat16* Phb = Ph + (size_t)bz * sC;
        __nv_bfloat16* Plb = Pl + (size_t)bz * sC;
        float rs[4][2];
        #pragma unroll
        for (int mt = 0; mt < 4; mt++) { rs[mt][0] = 0.0f; rs[mt][1] = 0.0f; }

        #pragma unroll
        for (int mt = 0; mt < 4; mt++) {
            const int row = m0 + wy * 64 + mt * 16 + quad;
            #pragma unroll
            for (int nt = 0; nt < 4; nt++) {
                const int col = n0 + wx * 32 + nt * 8 + tq * 2;
                float e0 = __expf(acc[mt][nt][0] * alpha);
                float e1 = __expf(acc[mt][nt][1] * alpha);
                float e2 = __expf(acc[mt][nt][2] * alpha);
                float e3 = __expf(acc[mt][nt][3] * alpha);
                rs[mt][0] += e0 + e1;
                rs[mt][1] += e2 + e3;
                __nv_bfloat16 h0, l0, h1, l1, h2, l2, h3, l3;
                split1(e0, h0, l0); split1(e1, h1, l1);
                split1(e2, h2, l2); split1(e3, h3, l3);
                __nv_bfloat162 ph01 = {h0, h1}, pl01 = {l0, l1};
                __nv_bfloat162 ph23 = {h2, h3}, pl23 = {l2, l3};
                *reinterpret_cast<__nv_bfloat162*>(Phb + (size_t)row * ldc + col) = ph01;
                *reinterpret_cast<__nv_bfloat162*>(Plb + (size_t)row * ldc + col) = pl01;
                *reinterpret_cast<__nv_bfloat162*>(Phb + (size_t)(row + 8) * ldc + col) = ph23;
                *reinterpret_cast<__nv_bfloat162*>(Plb + (size_t)(row + 8) * ldc + col) = pl23;
            }
            #pragma unroll
            for (int j = 0; j < 2; j++) {
                rs[mt][j] += __shfl_xor_sync(0xffffffff, rs[mt][j], 1);
                rs[mt][j] += __shfl_xor_sync(0xffffffff, rs[mt][j], 2);
            }
        }
        // cross-warp row-sum reduction (reuse smem tiles; safe: mainloop done)
        float* red = reinterpret_cast<float*>(sm);
        if (tq == 0) {
            #pragma unroll
            for (int mt = 0; mt < 4; mt++) {
                red[(wy * 64 + mt * 16 + quad) * 4 + wx] = rs[mt][0];
                red[(wy * 64 + mt * 16 + quad + 8) * 4 + wx] = rs[mt][1];
            }
        }
        __syncthreads();
        if (tid < 128) {
            float s = red[tid * 4] + red[tid * 4 + 1] + red[tid * 4 + 2] + red[tid * 4 + 3];
            psum[((size_t)bz * gridDim.x + blockIdx.x) * Mtot + m0 + tid] = s;
        }
    } else if (warp_active) {
        // ---- standard epilogue (optional per-row normalization) ----
        const float* rinv = rowinv ? rowinv + (size_t)bz * (gridDim.y * 128) : nullptr;
        float* Cb = C + bz * sC;
        #pragma unroll
        for (int mt = 0; mt < 4; mt++) {
            const int row = m0 + wy * 64 + mt * 16 + quad;
            const float s0 = rinv ? rinv[row] : 1.0f;
            const float s1 = rinv ? rinv[row + 8] : 1.0f;
            #pragma unroll
            for (int nt = 0; nt < 4; nt++) {
                const int col = n0 + wx * 32 + nt * 8 + tq * 2;
                if (col >= n_valid) continue;
                float b0 = bias ? bias[col] : 0.0f;
                float b1 = bias ? bias[col + 1] : 0.0f;
                float2 v0 = make_float2(acc[mt][nt][0] * alpha * s0 + b0,
                                        acc[mt][nt][1] * alpha * s0 + b1);
                float2 v1 = make_float2(acc[mt][nt][2] * alpha * s1 + b0,
                                        acc[mt][nt][3] * alpha * s1 + b1);
                *reinterpret_cast<float2*>(Cb + (size_t)row * ldc + col) = v0;
                *reinterpret_cast<float2*>(Cb + (size_t)(row + 8) * ldc + col) = v1;
            }
        }
    }
}

// ---------------- reduce per-tile partials -> 1/rowsum ----------------------
__global__ __launch_bounds__(256) void reduce_psum(
    const float* __restrict__ psum, float* __restrict__ rowinv)
{
    int i = blockIdx.x * blockDim.x + threadIdx.x;
    if (i >= NH * SEQ) return;
    const int h = i / SEQ, r = i % SEQ;
    float s = 0.0f;
    #pragma unroll
    for (int x = 0; x < 16; x++)
        s += psum[((size_t)h * 16 + x) * SEQ + r];
    rowinv[i] = 1.0f / s;
}

// ---------------- RoPE + split to bf16 hi/lo per-head layouts ---------------
__global__ __launch_bounds__(256) void rope_split_bf16(
    const float* __restrict__ qkv, const float* __restrict__ cosp,
    const float* __restrict__ sinp,
    __nv_bfloat16* __restrict__ Qh, __nv_bfloat16* __restrict__ Ql,
    __nv_bfloat16* __restrict__ Kh, __nv_bfloat16* __restrict__ Kl,
    __nv_bfloat16* __restrict__ Vth, __nv_bfloat16* __restrict__ Vtl)
{
    int idx = blockIdx.x * blockDim.x + threadIdx.x;
    if (idx >= SEQ * DIM) return;
    const int d = idx % HD;
    const int h = (idx / HD) % NH;
    const int s = idx / DIM;

    const float c = cosp[s * HD + d];
    const float sn = sinp[s * HD + d];
    const int d2 = (d < HD / 2) ? d + HD / 2 : d - HD / 2;
    const float sign = (d < HD / 2) ? -1.0f : 1.0f;

    const size_t rowbase = (size_t)s * QKV_N + h * HD;
    const size_t oqk = ((size_t)h * SEQ + s) * HDP + d;
    const size_t ovt = ((size_t)h * HDV + d) * SEQ + s;

    const float qv = qkv[rowbase + d];
    const float q2 = qkv[rowbase + d2];
    float qr = fmaf(qv, c, sign * q2 * sn);
    split1(qr, Qh[oqk], Ql[oqk]);

    const float kv = qkv[rowbase + DIM + d];
    const float k2 = qkv[rowbase + DIM + d2];
    float kr = fmaf(kv, c, sign * k2 * sn);
    split1(kr, Kh[oqk], Kl[oqk]);

    split1(qkv[rowbase + 2 * DIM + d], Vth[ovt], Vtl[ovt]);
}

// ---------------- zero-fill pad regions --------------------------------------
__global__ __launch_bounds__(256) void pad_qk(
    __nv_bfloat16* __restrict__ Qh, __nv_bfloat16* __restrict__ Ql,
    __nv_bfloat16* __restrict__ Kh, __nv_bfloat16* __restrict__ Kl)
{
    int i = blockIdx.x * blockDim.x + threadIdx.x;      // NH*SEQ*16
    if (i >= NH * SEQ * 16) return;
    const int d = HD + (i & 15);
    const int row = i >> 4;                              // h*SEQ + s
    const size_t o = (size_t)row * HDP + d;
    Qh[o] = __nv_bfloat16(0.0f); Ql[o] = __nv_bfloat16(0.0f);
    Kh[o] = __nv_bfloat16(0.0f); Kl[o] = __nv_bfloat16(0.0f);
}
__global__ __launch_bounds__(256) void pad_vt(
    __nv_bfloat16* __restrict__ Vth, __nv_bfloat16* __restrict__ Vtl)
{
    int i = blockIdx.x * blockDim.x + threadIdx.x;      // NH*48*SEQ
    if (i >= NH * (HDV - HD) * SEQ) return;
    const int s = i % SEQ;
    const int r = (i / SEQ) % (HDV - HD);
    const int h = i / (SEQ * (HDV - HD));
    const size_t o = ((size_t)h * HDV + HD + r) * SEQ + s;
    Vth[o] = __nv_bfloat16(0.0f); Vtl[o] = __nv_bfloat16(0.0f);
}

// ---------------- launch -----------------------------------------------------
extern "C" void kernel_launch(void* const* d_in, const int* in_sizes, int n_in,
                              void* d_out, int out_size)
{
    const float* hidden = (const float*)d_in[0];
    const float* cosp   = (const float*)d_in[2];
    const float* sinp   = (const float*)d_in[3];
    const float* w_qkv  = (const float*)d_in[4];
    const float* b_qkv  = (const float*)d_in[5];
    const float* w_proj = (const float*)d_in[6];
    const float* b_proj = (const float*)d_in[7];
    float* out = (float*)d_out;

    float *qkv, *O, *psum, *rowinv;
    cudaGetSymbolAddress((void**)&qkv, g_qkv);
    cudaGetSymbolAddress((void**)&O, g_o);
    cudaGetSymbolAddress((void**)&psum, g_psum);
    cudaGetSymbolAddress((void**)&rowinv, g_rowinv);

    __nv_bfloat16 *hh, *hl, *wh, *wl, *oh, *ol, *prh, *prl;
    __nv_bfloat16 *qh, *ql, *kh, *kl, *vth, *vtl, *ph, *pl;
    cudaGetSymbolAddress((void**)&hh, g_hid_hi);
    cudaGetSymbolAddress((void**)&hl, g_hid_lo);
    cudaGetSymbolAddress((void**)&wh, g_wqkv_hi);
    cudaGetSymbolAddress((void**)&wl, g_wqkv_lo);
    cudaGetSymbolAddress((void**)&oh, g_o_hi);
    cudaGetSymbolAddress((void**)&ol, g_o_lo);
    cudaGetSymbolAddress((void**)&prh, g_wproj_hi);
    cudaGetSymbolAddress((void**)&prl, g_wproj_lo);
    cudaGetSymbolAddress((void**)&qh, g_qh);
    cudaGetSymbolAddress((void**)&ql, g_ql);
    cudaGetSymbolAddress((void**)&kh, g_kh);
    cudaGetSymbolAddress((void**)&kl, g_kl);
    cudaGetSymbolAddress((void**)&vth, g_vth);
    cudaGetSymbolAddress((void**)&vtl, g_vtl);
    cudaGetSymbolAddress((void**)&ph, g_ph);
    cudaGetSymbolAddress((void**)&pl, g_pl);

    cudaFuncSetAttribute(gemm_mma_nt, cudaFuncAttributeMaxDynamicSharedMemorySize,
                         MM_SMEM);

    // 0) split inputs
    split_bf16<<<(SEQ * DIM + 255) / 256, 256>>>(hidden, hh, hl, SEQ * DIM);
    split_bf16<<<(QKV_N * DIM + 255) / 256, 256>>>(w_qkv, wh, wl, QKV_N * DIM);
    split_bf16<<<(DIM * DIM + 255) / 256, 256>>>(w_proj, prh, prl, DIM * DIM);

    // 1) QKV = hidden @ w_qkv^T + b_qkv
    {
        dim3 grid(QKV_N / 128, SEQ / 128, 1);
        gemm_mma_nt<<<grid, 256, MM_SMEM>>>(hh, hl, wh, wl, b_qkv, qkv,
                                            DIM, 0, 0, 0, QKV_N, 1.0f, QKV_N,
                                            nullptr, nullptr, nullptr, nullptr);
    }
    // 2) RoPE + per-head bf16 layouts (+ pad zeros)
    pad_qk<<<(NH * SEQ * 16 + 255) / 256, 256>>>(qh, ql, kh, kl);
    pad_vt<<<(NH * (HDV - HD) * SEQ + 255) / 256, 256>>>(vth, vtl);
    rope_split_bf16<<<(SEQ * DIM + 255) / 256, 256>>>(qkv, cosp, sinp,
                                                      qh, ql, kh, kl, vth, vtl);

    // 3) fused scores + exp: P_unnorm[h] = exp(scale * Q[h] @ K[h]^T), row partials
    {
        dim3 grid(SEQ / 128, SEQ / 128, NH);
        gemm_mma_nt<<<grid, 256, MM_SMEM>>>(qh, ql, kh, kl, nullptr, nullptr,
                                            HDP, (size_t)SEQ * HDP, (size_t)SEQ * HDP,
                                            (size_t)SEQ * SEQ, SEQ, ATTN_SCALE, SEQ,
                                            ph, pl, psum, nullptr);
    }
    // 4) rowsum partials -> 1/rowsum
    reduce_psum<<<(NH * SEQ + 255) / 256, 256>>>(psum, rowinv);

    // 5) O = (P_unnorm @ V) * rowinv   (normalization folded into epilogue)
    {
        dim3 grid(1, SEQ / 128, NH);
        gemm_mma_nt<<<grid, 256, MM_SMEM>>>(ph, pl, vth, vtl, nullptr, O,
                                            SEQ, (size_t)SEQ * SEQ, (size_t)HDV * SEQ,
                                            (size_t)HD, DIM, 1.0f, HD,
                                            nullptr, nullptr, nullptr, rowinv);
    }
    // 6) out = O @ w_proj^T + b_proj
    split_bf16<<<(SEQ * DIM + 255) / 256, 256>>>(O, oh, ol, SEQ * DIM);
    {
        dim3 grid(DIM / 128, SEQ / 128, 1);
        gemm_mma_nt<<<grid, 256, MM_SMEM>>>(oh, ol, prh, prl, b_proj, out,
                                            DIM, 0, 0, 0, DIM, 1.0f, DIM,
                                            nullptr, nullptr, nullptr, nullptr);
    }
}

// round 11
// speedup vs baseline: 1.0856x; 1.0348x over previous
#include <cuda_runtime.h>
#include <cuda_bf16.h>
#include <math.h>
#include <cstdint>

#define SEQ 2048
#define NH  16
#define HD  80
#define HDV 128             // padded head dim for V^T (one 128-col N tile)
#define DIM 1280            // NH*HD
#define QKV_N 3840          // 3*DIM
#define ATTN_SCALE 0.11180339887498949f   // 80^-0.5

// ---------------- scratch (device globals; no allocations allowed) ----------
__device__ float g_qkv[SEQ * QKV_N];          // 31.5 MB
__device__ float g_psum[NH * 16 * SEQ];       // per-(head, n-tile) row partial sums
__device__ float g_rowinv[NH * SEQ];          // 1 / rowsum

__device__ __nv_bfloat16 g_qh[NH * SEQ * HD];
__device__ __nv_bfloat16 g_ql[NH * SEQ * HD];
__device__ __nv_bfloat16 g_kh[NH * SEQ * HD];
__device__ __nv_bfloat16 g_kl[NH * SEQ * HD];
__device__ __nv_bfloat16 g_vth[NH * HDV * SEQ];   // V^T (rows >= HD unused)
__device__ __nv_bfloat16 g_vtl[NH * HDV * SEQ];
__device__ __nv_bfloat16 g_ph[(size_t)NH * SEQ * SEQ];  // 128 MB (unnormalized expS)
__device__ __nv_bfloat16 g_pl[(size_t)NH * SEQ * SEQ];

__device__ __nv_bfloat16 g_hid_hi[SEQ * DIM];
__device__ __nv_bfloat16 g_hid_lo[SEQ * DIM];
__device__ __nv_bfloat16 g_wqkv_hi[QKV_N * DIM];
__device__ __nv_bfloat16 g_wqkv_lo[QKV_N * DIM];
__device__ __nv_bfloat16 g_o_hi[SEQ * DIM];
__device__ __nv_bfloat16 g_o_lo[SEQ * DIM];
__device__ __nv_bfloat16 g_wproj_hi[DIM * DIM];
__device__ __nv_bfloat16 g_wproj_lo[DIM * DIM];

// ================= helpers ====================================================
__device__ __forceinline__ uint32_t smem_u32(const void* p) {
    uint32_t a;
    asm("{ .reg .u64 t; cvta.to.shared.u64 t, %1; cvt.u32.u64 %0, t; }" : "=r"(a) : "l"(p));
    return a;
}
#define CP_ASYNC16(dst, src) \
    asm volatile("cp.async.cg.shared.global [%0], [%1], 16;" :: "r"(dst), "l"(src) : "memory")
#define CP_COMMIT() asm volatile("cp.async.commit_group;" ::: "memory")
#define CP_WAIT1()  asm volatile("cp.async.wait_group 1;" ::: "memory")
#define CP_WAIT0()  asm volatile("cp.async.wait_group 0;" ::: "memory")

#define LDSM_X4(r0, r1, r2, r3, addr) \
    asm volatile("ldmatrix.sync.aligned.m8n8.x4.shared.b16 {%0,%1,%2,%3}, [%4];" \
        : "=r"(r0), "=r"(r1), "=r"(r2), "=r"(r3) : "r"(addr))

#define MMA16816(c, a, b0, b1) \
    asm volatile("mma.sync.aligned.m16n8k16.row.col.f32.bf16.bf16.f32 " \
        "{%0,%1,%2,%3}, {%4,%5,%6,%7}, {%8,%9}, {%0,%1,%2,%3};" \
        : "+f"((c)[0]), "+f"((c)[1]), "+f"((c)[2]), "+f"((c)[3]) \
        : "r"((a)[0]), "r"((a)[1]), "r"((a)[2]), "r"((a)[3]), "r"(b0), "r"(b1))

__device__ __forceinline__ void split1(float v, __nv_bfloat16& h, __nv_bfloat16& l) {
    h = __float2bfloat16(v);
    l = __float2bfloat16(v - __bfloat162float(h));
}

// ================= fp32 -> bf16 hi/lo split ==================================
__global__ __launch_bounds__(256) void split_bf16(
    const float* __restrict__ x, __nv_bfloat16* __restrict__ hi,
    __nv_bfloat16* __restrict__ lo, int n)
{
    int i = blockIdx.x * blockDim.x + threadIdx.x;
    if (i >= n) return;
    float v = x[i];
    __nv_bfloat16 h = __float2bfloat16(v);
    hi[i] = h;
    lo[i] = __float2bfloat16(v - __bfloat162float(h));
}

// ================= mma.sync bf16x3 NT GEMM ===================================
// K may be a multiple of 16 (K%32 in {0,16}); tail handled as a half chunk.
// Epilogue modes:
//   psum != null            : exp-split (fused softmax numerator + row partials)
//   Ph != null, psum == null: normalize-by-rowinv and write bf16 hi/lo (PV out)
//   else                    : C = alpha*acc (*rowinv) + bias, cols < n_valid
#define MM_TILE_B 10240        // 128 rows * 80 bytes (40 bf16, padded from 32)
#define MM_BUF_B  (4 * MM_TILE_B)
#define MM_SMEM   (2 * MM_BUF_B)   // 81920

__global__ __launch_bounds__(256, 2) void gemm_mma_nt(
    const __nv_bfloat16* __restrict__ Ah, const __nv_bfloat16* __restrict__ Al,
    const __nv_bfloat16* __restrict__ Bh, const __nv_bfloat16* __restrict__ Bl,
    const float* __restrict__ bias, float* __restrict__ C,
    int K, size_t sA, size_t sB, size_t sC, int ldc, float alpha, int n_valid,
    __nv_bfloat16* __restrict__ Ph, __nv_bfloat16* __restrict__ Pl,
    float* __restrict__ psum, const float* __restrict__ rowinv)
{
    extern __shared__ char sm[];
    const uint32_t sbase = smem_u32(sm);
    const int tid = threadIdx.x;
    const int lane = tid & 31;
    const int wid = tid >> 5;
    const int wy = wid >> 2;          // 0..1
    const int wx = wid & 3;           // 0..3
    const int m0 = blockIdx.y * 128;
    const int n0 = blockIdx.x * 128;
    const int bz = blockIdx.z;
    const int NC = (K + 31) >> 5;     // chunks; last may be half (16)

    bool npok[2];
    #pragma unroll
    for (int np = 0; np < 2; np++)
        npok[np] = (n0 + wx * 32 + np * 16) < n_valid;

    const __nv_bfloat16* srcs[4] = {Ah + bz * sA, Al + bz * sA,
                                    Bh + bz * sB, Bl + bz * sB};
    const int rb0 = m0, rb1 = n0;

    float acc[4][4][4];
    #pragma unroll
    for (int i = 0; i < 4; i++)
        #pragma unroll
        for (int j = 0; j < 4; j++)
            #pragma unroll
            for (int k = 0; k < 4; k++) acc[i][j][k] = 0.0f;

    auto load_chunk = [&](int c, int b) {
        const int k0 = c << 5;
        const bool half = (k0 + 32 > K);
        #pragma unroll
        for (int t = 0; t < 4; t++) {
            const __nv_bfloat16* src = srcs[t];
            const int rbase = (t < 2) ? rb0 : rb1;
            const uint32_t tb = sbase + b * MM_BUF_B + t * MM_TILE_B;
            if (!half) {
                #pragma unroll
                for (int i = 0; i < 2; i++) {
                    const int g = tid + i * 256;       // 0..511
                    const int row = g >> 2, q = g & 3;
                    const uint32_t dst = tb + row * 80 + q * 16;
                    const void* s = (const void*)(src + (size_t)(rbase + row) * K + k0 + q * 8);
                    CP_ASYNC16(dst, s);
                }
            } else {
                const int row = tid >> 1, q = tid & 1;  // 16 cols only
                const uint32_t dst = tb + row * 80 + q * 16;
                const void* s = (const void*)(src + (size_t)(rbase + row) * K + k0 + q * 8);
                CP_ASYNC16(dst, s);
            }
        }
    };

    load_chunk(0, 0);
    CP_COMMIT();

    for (int c = 0; c < NC; c++) {
        if (c + 1 < NC) {
            load_chunk(c + 1, (c + 1) & 1);
            CP_COMMIT();
            CP_WAIT1();
        } else {
            CP_WAIT0();
        }
        __syncthreads();

        const int b = c & 1;
        const bool half = ((c << 5) + 32 > K);
        const uint32_t bufb = sbase + b * MM_BUF_B;
        if (npok[0]) {
            #pragma unroll
            for (int ks = 0; ks < 2; ks++) {
                if (ks == 1 && half) break;
                const int fcol = ks * 16 + (lane >> 4) * 8;
                uint32_t bh[2][4], bl[2][4];
                #pragma unroll
                for (int np = 0; np < 2; np++) {
                    if (!npok[np]) continue;
                    const int r = wx * 32 + np * 16 + (lane & 15);
                    const uint32_t bd = bufb + 2 * MM_TILE_B + r * 80 + fcol * 2;
                    LDSM_X4(bh[np][0], bh[np][1], bh[np][2], bh[np][3], bd);
                    LDSM_X4(bl[np][0], bl[np][1], bl[np][2], bl[np][3], bd + MM_TILE_B);
                }
                #pragma unroll
                for (int mt = 0; mt < 4; mt++) {
                    const int r = wy * 64 + mt * 16 + (lane & 15);
                    const uint32_t ad = bufb + r * 80 + fcol * 2;
                    uint32_t ah[4], al[4];
                    LDSM_X4(ah[0], ah[1], ah[2], ah[3], ad);
                    LDSM_X4(al[0], al[1], al[2], al[3], ad + MM_TILE_B);
                    #pragma unroll
                    for (int np = 0; np < 2; np++) {
                        if (!npok[np]) continue;
                        MMA16816(acc[mt][np * 2],     ah, bh[np][0], bh[np][2]);
                        MMA16816(acc[mt][np * 2 + 1], ah, bh[np][1], bh[np][3]);
                    }
                    #pragma unroll
                    for (int np = 0; np < 2; np++) {
                        if (!npok[np]) continue;
                        MMA16816(acc[mt][np * 2],     ah, bl[np][0], bl[np][2]);
                        MMA16816(acc[mt][np * 2 + 1], ah, bl[np][1], bl[np][3]);
                    }
                    #pragma unroll
                    for (int np = 0; np < 2; np++) {
                        if (!npok[np]) continue;
                        MMA16816(acc[mt][np * 2],     al, bh[np][0], bh[np][2]);
                        MMA16816(acc[mt][np * 2 + 1], al, bh[np][1], bh[np][3]);
                    }
                }
            }
        }
        __syncthreads();
    }

    const int quad = lane >> 2, tq = lane & 3;

    if (psum) {
        // ---- exp + hi/lo split epilogue (fused unnormalized softmax) ----
        const int Mtot = gridDim.y * 128;
        __nv_bfloat16* Phb = Ph + (size_t)bz * sC;
        __nv_bfloat16* Plb = Pl + (size_t)bz * sC;
        float rs[4][2];
        #pragma unroll
        for (int mt = 0; mt < 4; mt++) { rs[mt][0] = 0.0f; rs[mt][1] = 0.0f; }

        #pragma unroll
        for (int mt = 0; mt < 4; mt++) {
            const int row = m0 + wy * 64 + mt * 16 + quad;
            #pragma unroll
            for (int nt = 0; nt < 4; nt++) {
                const int col = n0 + wx * 32 + nt * 8 + tq * 2;
                float e0 = __expf(acc[mt][nt][0] * alpha);
                float e1 = __expf(acc[mt][nt][1] * alpha);
                float e2 = __expf(acc[mt][nt][2] * alpha);
                float e3 = __expf(acc[mt][nt][3] * alpha);
                rs[mt][0] += e0 + e1;
                rs[mt][1] += e2 + e3;
                __nv_bfloat16 h0, l0, h1, l1, h2, l2, h3, l3;
                split1(e0, h0, l0); split1(e1, h1, l1);
                split1(e2, h2, l2); split1(e3, h3, l3);
                __nv_bfloat162 ph01 = {h0, h1}, pl01 = {l0, l1};
                __nv_bfloat162 ph23 = {h2, h3}, pl23 = {l2, l3};
                *reinterpret_cast<__nv_bfloat162*>(Phb + (size_t)row * ldc + col) = ph01;
                *reinterpret_cast<__nv_bfloat162*>(Plb + (size_t)row * ldc + col) = pl01;
                *reinterpret_cast<__nv_bfloat162*>(Phb + (size_t)(row + 8) * ldc + col) = ph23;
                *reinterpret_cast<__nv_bfloat162*>(Plb + (size_t)(row + 8) * ldc + col) = pl23;
            }
            #pragma unroll
            for (int j = 0; j < 2; j++) {
                rs[mt][j] += __shfl_xor_sync(0xffffffff, rs[mt][j], 1);
                rs[mt][j] += __shfl_xor_sync(0xffffffff, rs[mt][j], 2);
            }
        }
        float* red = reinterpret_cast<float*>(sm);
        if (tq == 0) {
            #pragma unroll
            for (int mt = 0; mt < 4; mt++) {
                red[(wy * 64 + mt * 16 + quad) * 4 + wx] = rs[mt][0];
                red[(wy * 64 + mt * 16 + quad + 8) * 4 + wx] = rs[mt][1];
            }
        }
        __syncthreads();
        if (tid < 128) {
            float s = red[tid * 4] + red[tid * 4 + 1] + red[tid * 4 + 2] + red[tid * 4 + 3];
            psum[((size_t)bz * gridDim.x + blockIdx.x) * Mtot + m0 + tid] = s;
        }
    } else if (Ph) {
        // ---- normalize + bf16 hi/lo split epilogue (PV output) ----
        if (npok[0]) {
            const float* rinv = rowinv + (size_t)bz * (gridDim.y * 128);
            __nv_bfloat16* Phb = Ph + (size_t)bz * sC;
            __nv_bfloat16* Plb = Pl + (size_t)bz * sC;
            #pragma unroll
            for (int mt = 0; mt < 4; mt++) {
                const int row = m0 + wy * 64 + mt * 16 + quad;
                const float s0 = rinv[row];
                const float s1 = rinv[row + 8];
                #pragma unroll
                for (int nt = 0; nt < 4; nt++) {
                    const int col = n0 + wx * 32 + nt * 8 + tq * 2;
                    if (col >= n_valid) continue;
                    __nv_bfloat16 h0, l0, h1, l1, h2, l2, h3, l3;
                    split1(acc[mt][nt][0] * alpha * s0, h0, l0);
                    split1(acc[mt][nt][1] * alpha * s0, h1, l1);
                    split1(acc[mt][nt][2] * alpha * s1, h2, l2);
                    split1(acc[mt][nt][3] * alpha * s1, h3, l3);
                    __nv_bfloat162 ph01 = {h0, h1}, pl01 = {l0, l1};
                    __nv_bfloat162 ph23 = {h2, h3}, pl23 = {l2, l3};
                    *reinterpret_cast<__nv_bfloat162*>(Phb + (size_t)row * ldc + col) = ph01;
                    *reinterpret_cast<__nv_bfloat162*>(Plb + (size_t)row * ldc + col) = pl01;
                    *reinterpret_cast<__nv_bfloat162*>(Phb + (size_t)(row + 8) * ldc + col) = ph23;
                    *reinterpret_cast<__nv_bfloat162*>(Plb + (size_t)(row + 8) * ldc + col) = pl23;
                }
            }
        }
    } else if (npok[0]) {
        // ---- standard epilogue ----
        const float* rinv = rowinv ? rowinv + (size_t)bz * (gridDim.y * 128) : nullptr;
        float* Cb = C + bz * sC;
        #pragma unroll
        for (int mt = 0; mt < 4; mt++) {
            const int row = m0 + wy * 64 + mt * 16 + quad;
            const float s0 = rinv ? rinv[row] : 1.0f;
            const float s1 = rinv ? rinv[row + 8] : 1.0f;
            #pragma unroll
            for (int nt = 0; nt < 4; nt++) {
                const int col = n0 + wx * 32 + nt * 8 + tq * 2;
                if (col >= n_valid) continue;
                float b0 = bias ? bias[col] : 0.0f;
                float b1 = bias ? bias[col + 1] : 0.0f;
                float2 v0 = make_float2(acc[mt][nt][0] * alpha * s0 + b0,
                                        acc[mt][nt][1] * alpha * s0 + b1);
                float2 v1 = make_float2(acc[mt][nt][2] * alpha * s1 + b0,
                                        acc[mt][nt][3] * alpha * s1 + b1);
                *reinterpret_cast<float2*>(Cb + (size_t)row * ldc + col) = v0;
                *reinterpret_cast<float2*>(Cb + (size_t)(row + 8) * ldc + col) = v1;
            }
        }
    }
}

// ---------------- reduce per-tile partials -> 1/rowsum ----------------------
__global__ __launch_bounds__(256) void reduce_psum(
    const float* __restrict__ psum, float* __restrict__ rowinv)
{
    int i = blockIdx.x * blockDim.x + threadIdx.x;
    if (i >= NH * SEQ) return;
    const int h = i / SEQ, r = i % SEQ;
    float s = 0.0f;
    #pragma unroll
    for (int x = 0; x < 16; x++)
        s += psum[((size_t)h * 16 + x) * SEQ + r];
    rowinv[i] = 1.0f / s;
}

// ---------------- RoPE + split to bf16 hi/lo per-head layouts ---------------
// Q,K: [h][s][80] (unpadded). V^T: [h][d][s] (rows >= 80 left as-is; never read).
__global__ __launch_bounds__(256) void rope_split_bf16(
    const float* __restrict__ qkv, const float* __restrict__ cosp,
    const float* __restrict__ sinp,
    __nv_bfloat16* __restrict__ Qh, __nv_bfloat16* __restrict__ Ql,
    __nv_bfloat16* __restrict__ Kh, __nv_bfloat16* __restrict__ Kl,
    __nv_bfloat16* __restrict__ Vth, __nv_bfloat16* __restrict__ Vtl)
{
    int idx = blockIdx.x * blockDim.x + threadIdx.x;
    if (idx >= SEQ * DIM) return;
    const int d = idx % HD;
    const int h = (idx / HD) % NH;
    const int s = idx / DIM;

    const float c = cosp[s * HD + d];
    const float sn = sinp[s * HD + d];
    const int d2 = (d < HD / 2) ? d + HD / 2 : d - HD / 2;
    const float sign = (d < HD / 2) ? -1.0f : 1.0f;

    const size_t rowbase = (size_t)s * QKV_N + h * HD;
    const size_t oqk = ((size_t)h * SEQ + s) * HD + d;
    const size_t ovt = ((size_t)h * HDV + d) * SEQ + s;

    const float qv = qkv[rowbase + d];
    const float q2 = qkv[rowbase + d2];
    float qr = fmaf(qv, c, sign * q2 * sn);
    split1(qr, Qh[oqk], Ql[oqk]);

    const float kv = qkv[rowbase + DIM + d];
    const float k2 = qkv[rowbase + DIM + d2];
    float kr = fmaf(kv, c, sign * k2 * sn);
    split1(kr, Kh[oqk], Kl[oqk]);

    split1(qkv[rowbase + 2 * DIM + d], Vth[ovt], Vtl[ovt]);
}

// ---------------- launch -----------------------------------------------------
extern "C" void kernel_launch(void* const* d_in, const int* in_sizes, int n_in,
                              void* d_out, int out_size)
{
    const float* hidden = (const float*)d_in[0];
    const float* cosp   = (const float*)d_in[2];
    const float* sinp   = (const float*)d_in[3];
    const float* w_qkv  = (const float*)d_in[4];
    const float* b_qkv  = (const float*)d_in[5];
    const float* w_proj = (const float*)d_in[6];
    const float* b_proj = (const float*)d_in[7];
    float* out = (float*)d_out;

    float *qkv, *psum, *rowinv;
    cudaGetSymbolAddress((void**)&qkv, g_qkv);
    cudaGetSymbolAddress((void**)&psum, g_psum);
    cudaGetSymbolAddress((void**)&rowinv, g_rowinv);

    __nv_bfloat16 *hh, *hl, *wh, *wl, *oh, *ol, *prh, *prl;
    __nv_bfloat16 *qh, *ql, *kh, *kl, *vth, *vtl, *ph, *pl;
    cudaGetSymbolAddress((void**)&hh, g_hid_hi);
    cudaGetSymbolAddress((void**)&hl, g_hid_lo);
    cudaGetSymbolAddress((void**)&wh, g_wqkv_hi);
    cudaGetSymbolAddress((void**)&wl, g_wqkv_lo);
    cudaGetSymbolAddress((void**)&oh, g_o_hi);
    cudaGetSymbolAddress((void**)&ol, g_o_lo);
    cudaGetSymbolAddress((void**)&prh, g_wproj_hi);
    cudaGetSymbolAddress((void**)&prl, g_wproj_lo);
    cudaGetSymbolAddress((void**)&qh, g_qh);
    cudaGetSymbolAddress((void**)&ql, g_ql);
    cudaGetSymbolAddress((void**)&kh, g_kh);
    cudaGetSymbolAddress((void**)&kl, g_kl);
    cudaGetSymbolAddress((void**)&vth, g_vth);
    cudaGetSymbolAddress((void**)&vtl, g_vtl);
    cudaGetSymbolAddress((void**)&ph, g_ph);
    cudaGetSymbolAddress((void**)&pl, g_pl);

    cudaFuncSetAttribute(gemm_mma_nt, cudaFuncAttributeMaxDynamicSharedMemorySize,
                         MM_SMEM);

    // 0) split inputs
    split_bf16<<<(SEQ * DIM + 255) / 256, 256>>>(hidden, hh, hl, SEQ * DIM);
    split_bf16<<<(QKV_N * DIM + 255) / 256, 256>>>(w_qkv, wh, wl, QKV_N * DIM);
    split_bf16<<<(DIM * DIM + 255) / 256, 256>>>(w_proj, prh, prl, DIM * DIM);

    // 1) QKV = hidden @ w_qkv^T + b_qkv
    {
        dim3 grid(QKV_N / 128, SEQ / 128, 1);
        gemm_mma_nt<<<grid, 256, MM_SMEM>>>(hh, hl, wh, wl, b_qkv, qkv,
                                            DIM, 0, 0, 0, QKV_N, 1.0f, QKV_N,
                                            nullptr, nullptr, nullptr, nullptr);
    }
    // 2) RoPE + per-head bf16 layouts (unpadded K=80)
    rope_split_bf16<<<(SEQ * DIM + 255) / 256, 256>>>(qkv, cosp, sinp,
                                                      qh, ql, kh, kl, vth, vtl);

    // 3) fused scores + exp: P_unnorm[h] = exp(scale * Q[h] @ K[h]^T), row partials
    //    K = 80 (2 full chunks + 1 half chunk)
    {
        dim3 grid(SEQ / 128, SEQ / 128, NH);
        gemm_mma_nt<<<grid, 256, MM_SMEM>>>(qh, ql, kh, kl, nullptr, nullptr,
                                            HD, (size_t)SEQ * HD, (size_t)SEQ * HD,
                                            (size_t)SEQ * SEQ, SEQ, ATTN_SCALE, SEQ,
                                            ph, pl, psum, nullptr);
    }
    // 4) rowsum partials -> 1/rowsum
    reduce_psum<<<(NH * SEQ + 255) / 256, 256>>>(psum, rowinv);

    // 5) O_hi/lo = split((P_unnorm @ V) * rowinv)  — fused normalize+split epilogue
    {
        dim3 grid(1, SEQ / 128, NH);
        gemm_mma_nt<<<grid, 256, MM_SMEM>>>(ph, pl, vth, vtl, nullptr, nullptr,
                                            SEQ, (size_t)SEQ * SEQ, (size_t)HDV * SEQ,
                                            (size_t)HD, DIM, 1.0f, HD,
                                            oh, ol, nullptr, rowinv);
    }
    // 6) out = O @ w_proj^T + b_proj
    {
        dim3 grid(DIM / 128, SEQ / 128, 1);
        gemm_mma_nt<<<grid, 256, MM_SMEM>>>(oh, ol, prh, prl, b_proj, out,
                                            DIM, 0, 0, 0, DIM, 1.0f, DIM,
                                            nullptr, nullptr, nullptr, nullptr);
    }
}

// round 12
// speedup vs baseline: 1.4874x; 1.3701x over previous
#include <cuda_runtime.h>
#include <cuda_fp16.h>
#include <math.h>
#include <cstdint>

#define SEQ 2048
#define NH  16
#define HD  80
#define HDV 128             // padded head dim for V^T (one 128-col N tile)
#define DIM 1280            // NH*HD
#define QKV_N 3840          // 3*DIM
#define ATTN_SCALE 0.11180339887498949f   // 80^-0.5
#define PSCALE 0.0625f      // 2^-4 headroom factor for fp16 exp storage (cancels in rowinv)

// ---------------- scratch (device globals; no allocations allowed) ----------
__device__ float g_qkv[SEQ * QKV_N];          // 31.5 MB
__device__ float g_psum[NH * 16 * SEQ];       // per-(head, n-tile) row partial sums
__device__ float g_rowinv[NH * SEQ];          // 1 / rowsum (of scaled exp)

__device__ __half g_hid_h[SEQ * DIM];
__device__ __half g_hid_l[SEQ * DIM];
__device__ __half g_wqkv_h[QKV_N * DIM];      // weights: single fp16 limb
__device__ __half g_wproj_h[DIM * DIM];
__device__ __half g_qh[NH * SEQ * HD];
__device__ __half g_ql[NH * SEQ * HD];
__device__ __half g_kh[NH * SEQ * HD];        // K: single limb (B side of scores)
__device__ __half g_vth[NH * HDV * SEQ];      // V^T: two limbs (rows >= HD unused)
__device__ __half g_vtl[NH * HDV * SEQ];
__device__ __half g_ph[(size_t)NH * SEQ * SEQ];  // 64 MB (scaled unnormalized expS, single limb)
__device__ __half g_oh[SEQ * DIM];
__device__ __half g_ol[SEQ * DIM];

// ================= helpers ====================================================
__device__ __forceinline__ uint32_t smem_u32(const void* p) {
    uint32_t a;
    asm("{ .reg .u64 t; cvta.to.shared.u64 t, %1; cvt.u32.u64 %0, t; }" : "=r"(a) : "l"(p));
    return a;
}
#define CP_ASYNC16(dst, src) \
    asm volatile("cp.async.cg.shared.global [%0], [%1], 16;" :: "r"(dst), "l"(src) : "memory")
#define CP_COMMIT() asm volatile("cp.async.commit_group;" ::: "memory")
#define CP_WAIT1()  asm volatile("cp.async.wait_group 1;" ::: "memory")
#define CP_WAIT0()  asm volatile("cp.async.wait_group 0;" ::: "memory")

#define LDSM_X4(r0, r1, r2, r3, addr) \
    asm volatile("ldmatrix.sync.aligned.m8n8.x4.shared.b16 {%0,%1,%2,%3}, [%4];" \
        : "=r"(r0), "=r"(r1), "=r"(r2), "=r"(r3) : "r"(addr))

#define MMA16816(c, a, b0, b1) \
    asm volatile("mma.sync.aligned.m16n8k16.row.col.f32.f16.f16.f32 " \
        "{%0,%1,%2,%3}, {%4,%5,%6,%7}, {%8,%9}, {%0,%1,%2,%3};" \
        : "+f"((c)[0]), "+f"((c)[1]), "+f"((c)[2]), "+f"((c)[3]) \
        : "r"((a)[0]), "r"((a)[1]), "r"((a)[2]), "r"((a)[3]), "r"(b0), "r"(b1))

__device__ __forceinline__ void split1h(float v, __half& h, __half& l) {
    h = __float2half(v);
    l = __float2half(v - __half2float(h));
}

// ================= fp32 -> fp16 splits =======================================
__global__ __launch_bounds__(256) void split_fp16(
    const float* __restrict__ x, __half* __restrict__ hi,
    __half* __restrict__ lo, int n)
{
    int i = blockIdx.x * blockDim.x + threadIdx.x;
    if (i >= n) return;
    split1h(x[i], hi[i], lo[i]);
}
__global__ __launch_bounds__(256) void round_fp16(
    const float* __restrict__ x, __half* __restrict__ hi, int n)
{
    int i = blockIdx.x * blockDim.x + threadIdx.x;
    if (i >= n) return;
    hi[i] = __float2half(x[i]);
}

// ================= mma.sync fp16x2 NT GEMM ===================================
// C = alpha * A(MxK) @ B(NxK)^T (+bias), 2-term limb product:
//   ASPLIT=true : A = A0 + X1 (two limbs), B = B0       -> A0*B0 + X1*B0
//   ASPLIT=false: A = A0,                 B = B0 + X1   -> A0*B0 + A0*X1
// K%16==0 (tail handled as half chunk). Epilogues:
//   psum != null : e = expf(alpha*acc)*PSCALE -> Ph (fp16), row partials -> psum
//   Oh   != null : v = acc*alpha*rowinv[row]  -> (Oh, Ol) fp16 two-limb
//   else         : C = alpha*acc (*rowinv) + bias, cols < n_valid
#define MM_TILE_B 10240        // 128 rows * 80 bytes (40 halves, padded from 32)
#define MM_BUF_B  (3 * MM_TILE_B)
#define MM_SMEM   (2 * MM_BUF_B)   // 61440

template<bool ASPLIT>
__global__ __launch_bounds__(256, 2) void gemm_fp16x2(
    const __half* __restrict__ A0, const __half* __restrict__ X1,
    const __half* __restrict__ B0,
    const float* __restrict__ bias, float* __restrict__ C,
    int K, size_t sA, size_t sB, size_t sC, int ldc, float alpha, int n_valid,
    __half* __restrict__ Ph, float* __restrict__ psum,
    const float* __restrict__ rowinv,
    __half* __restrict__ Oh, __half* __restrict__ Ol)
{
    extern __shared__ char sm[];
    const uint32_t sbase = smem_u32(sm);
    const int tid = threadIdx.x;
    const int lane = tid & 31;
    const int wid = tid >> 5;
    const int wy = wid >> 2;          // 0..1
    const int wx = wid & 3;           // 0..3
    const int m0 = blockIdx.y * 128;
    const int n0 = blockIdx.x * 128;
    const int bz = blockIdx.z;
    const int NC = (K + 31) >> 5;     // chunks; last may be half (16)

    bool npok[2];
    #pragma unroll
    for (int np = 0; np < 2; np++)
        npok[np] = (n0 + wx * 32 + np * 16) < n_valid;

    // tiles: T0 = A limb0, T1 = (A limb1 | B limb1), T2 = B limb0
    const __half* srcs[3] = {A0 + bz * sA,
                             ASPLIT ? X1 + bz * sA : X1 + bz * sB,
                             B0 + bz * sB};
    const int rbases[3] = {m0, ASPLIT ? m0 : n0, n0};

    float acc[4][4][4];
    #pragma unroll
    for (int i = 0; i < 4; i++)
        #pragma unroll
        for (int j = 0; j < 4; j++)
            #pragma unroll
            for (int k = 0; k < 4; k++) acc[i][j][k] = 0.0f;

    auto load_chunk = [&](int c, int b) {
        const int k0 = c << 5;
        const bool hc = (k0 + 32 > K);
        #pragma unroll
        for (int t = 0; t < 3; t++) {
            const __half* src = srcs[t];
            const int rbase = rbases[t];
            const uint32_t tb = sbase + b * MM_BUF_B + t * MM_TILE_B;
            if (!hc) {
                #pragma unroll
                for (int i = 0; i < 2; i++) {
                    const int g = tid + i * 256;       // 0..511
                    const int row = g >> 2, q = g & 3;
                    const uint32_t dst = tb + row * 80 + q * 16;
                    const void* s = (const void*)(src + (size_t)(rbase + row) * K + k0 + q * 8);
                    CP_ASYNC16(dst, s);
                }
            } else {
                const int row = tid >> 1, q = tid & 1;  // 16 cols only
                const uint32_t dst = tb + row * 80 + q * 16;
                const void* s = (const void*)(src + (size_t)(rbase + row) * K + k0 + q * 8);
                CP_ASYNC16(dst, s);
            }
        }
    };

    load_chunk(0, 0);
    CP_COMMIT();

    for (int c = 0; c < NC; c++) {
        if (c + 1 < NC) {
            load_chunk(c + 1, (c + 1) & 1);
            CP_COMMIT();
            CP_WAIT1();
        } else {
            CP_WAIT0();
        }
        __syncthreads();

        const int b = c & 1;
        const bool hc = ((c << 5) + 32 > K);
        const uint32_t bufb = sbase + b * MM_BUF_B;
        if (npok[0]) {
            #pragma unroll
            for (int ks = 0; ks < 2; ks++) {
                if (ks == 1 && hc) break;
                const int fcol = ks * 16 + (lane >> 4) * 8;
                uint32_t b0f[2][4], b1f[2][4];
                #pragma unroll
                for (int np = 0; np < 2; np++) {
                    if (!npok[np]) continue;
                    const int r = wx * 32 + np * 16 + (lane & 15);
                    const uint32_t bd = bufb + 2 * MM_TILE_B + r * 80 + fcol * 2;
                    LDSM_X4(b0f[np][0], b0f[np][1], b0f[np][2], b0f[np][3], bd);
                    if (!ASPLIT) {
                        const uint32_t bd1 = bufb + 1 * MM_TILE_B + r * 80 + fcol * 2;
                        LDSM_X4(b1f[np][0], b1f[np][1], b1f[np][2], b1f[np][3], bd1);
                    }
                }
                #pragma unroll
                for (int mt = 0; mt < 4; mt++) {
                    const int r = wy * 64 + mt * 16 + (lane & 15);
                    const uint32_t ad = bufb + r * 80 + fcol * 2;
                    uint32_t a0f[4], a1f[4];
                    LDSM_X4(a0f[0], a0f[1], a0f[2], a0f[3], ad);
                    if (ASPLIT) {
                        const uint32_t ad1 = ad + MM_TILE_B;
                        LDSM_X4(a1f[0], a1f[1], a1f[2], a1f[3], ad1);
                    }
                    #pragma unroll
                    for (int np = 0; np < 2; np++) {
                        if (!npok[np]) continue;
                        MMA16816(acc[mt][np * 2],     a0f, b0f[np][0], b0f[np][2]);
                        MMA16816(acc[mt][np * 2 + 1], a0f, b0f[np][1], b0f[np][3]);
                    }
                    #pragma unroll
                    for (int np = 0; np < 2; np++) {
                        if (!npok[np]) continue;
                        if (ASPLIT) {
                            MMA16816(acc[mt][np * 2],     a1f, b0f[np][0], b0f[np][2]);
                            MMA16816(acc[mt][np * 2 + 1], a1f, b0f[np][1], b0f[np][3]);
                        } else {
                            MMA16816(acc[mt][np * 2],     a0f, b1f[np][0], b1f[np][2]);
                            MMA16816(acc[mt][np * 2 + 1], a0f, b1f[np][1], b1f[np][3]);
                        }
                    }
                }
            }
        }
        __syncthreads();
    }

    const int quad = lane >> 2, tq = lane & 3;

    if (psum) {
        // ---- exp epilogue (fused unnormalized softmax, single-limb fp16 P) ----
        const int Mtot = gridDim.y * 128;
        __half* Phb = Ph + (size_t)bz * sC;
        float rs[4][2];
        #pragma unroll
        for (int mt = 0; mt < 4; mt++) { rs[mt][0] = 0.0f; rs[mt][1] = 0.0f; }

        #pragma unroll
        for (int mt = 0; mt < 4; mt++) {
            const int row = m0 + wy * 64 + mt * 16 + quad;
            #pragma unroll
            for (int nt = 0; nt < 4; nt++) {
                const int col = n0 + wx * 32 + nt * 8 + tq * 2;
                float e0 = __expf(acc[mt][nt][0] * alpha) * PSCALE;
                float e1 = __expf(acc[mt][nt][1] * alpha) * PSCALE;
                float e2 = __expf(acc[mt][nt][2] * alpha) * PSCALE;
                float e3 = __expf(acc[mt][nt][3] * alpha) * PSCALE;
                rs[mt][0] += e0 + e1;
                rs[mt][1] += e2 + e3;
                __half2 p01 = {__float2half(e0), __float2half(e1)};
                __half2 p23 = {__float2half(e2), __float2half(e3)};
                *reinterpret_cast<__half2*>(Phb + (size_t)row * ldc + col) = p01;
                *reinterpret_cast<__half2*>(Phb + (size_t)(row + 8) * ldc + col) = p23;
            }
            #pragma unroll
            for (int j = 0; j < 2; j++) {
                rs[mt][j] += __shfl_xor_sync(0xffffffff, rs[mt][j], 1);
                rs[mt][j] += __shfl_xor_sync(0xffffffff, rs[mt][j], 2);
            }
        }
        float* red = reinterpret_cast<float*>(sm);
        if (tq == 0) {
            #pragma unroll
            for (int mt = 0; mt < 4; mt++) {
                red[(wy * 64 + mt * 16 + quad) * 4 + wx] = rs[mt][0];
                red[(wy * 64 + mt * 16 + quad + 8) * 4 + wx] = rs[mt][1];
            }
        }
        __syncthreads();
        if (tid < 128) {
            float s = red[tid * 4] + red[tid * 4 + 1] + red[tid * 4 + 2] + red[tid * 4 + 3];
            psum[((size_t)bz * gridDim.x + blockIdx.x) * Mtot + m0 + tid] = s;
        }
    } else if (Oh) {
        // ---- normalize + fp16 two-limb epilogue (PV output) ----
        if (npok[0]) {
            const float* rinv = rowinv + (size_t)bz * (gridDim.y * 128);
            __half* Ohb = Oh + (size_t)bz * sC;
            __half* Olb = Ol + (size_t)bz * sC;
            #pragma unroll
            for (int mt = 0; mt < 4; mt++) {
                const int row = m0 + wy * 64 + mt * 16 + quad;
                const float s0 = rinv[row];
                const float s1 = rinv[row + 8];
                #pragma unroll
                for (int nt = 0; nt < 4; nt++) {
                    const int col = n0 + wx * 32 + nt * 8 + tq * 2;
                    if (col >= n_valid) continue;
                    __half h0, l0, h1, l1, h2, l2, h3, l3;
                    split1h(acc[mt][nt][0] * alpha * s0, h0, l0);
                    split1h(acc[mt][nt][1] * alpha * s0, h1, l1);
                    split1h(acc[mt][nt][2] * alpha * s1, h2, l2);
                    split1h(acc[mt][nt][3] * alpha * s1, h3, l3);
                    __half2 oh01 = {h0, h1}, ol01 = {l0, l1};
                    __half2 oh23 = {h2, h3}, ol23 = {l2, l3};
                    *reinterpret_cast<__half2*>(Ohb + (size_t)row * ldc + col) = oh01;
                    *reinterpret_cast<__half2*>(Olb + (size_t)row * ldc + col) = ol01;
                    *reinterpret_cast<__half2*>(Ohb + (size_t)(row + 8) * ldc + col) = oh23;
                    *reinterpret_cast<__half2*>(Olb + (size_t)(row + 8) * ldc + col) = ol23;
                }
            }
        }
    } else if (npok[0]) {
        // ---- standard epilogue ----
        float* Cb = C + bz * sC;
        #pragma unroll
        for (int mt = 0; mt < 4; mt++) {
            const int row = m0 + wy * 64 + mt * 16 + quad;
            #pragma unroll
            for (int nt = 0; nt < 4; nt++) {
                const int col = n0 + wx * 32 + nt * 8 + tq * 2;
                if (col >= n_valid) continue;
                float b0 = bias ? bias[col] : 0.0f;
                float b1 = bias ? bias[col + 1] : 0.0f;
                float2 v0 = make_float2(acc[mt][nt][0] * alpha + b0,
                                        acc[mt][nt][1] * alpha + b1);
                float2 v1 = make_float2(acc[mt][nt][2] * alpha + b0,
                                        acc[mt][nt][3] * alpha + b1);
                *reinterpret_cast<float2*>(Cb + (size_t)row * ldc + col) = v0;
                *reinterpret_cast<float2*>(Cb + (size_t)(row + 8) * ldc + col) = v1;
            }
        }
    }
}

// ---------------- reduce per-tile partials -> 1/rowsum ----------------------
__global__ __launch_bounds__(256) void reduce_psum(
    const float* __restrict__ psum, float* __restrict__ rowinv)
{
    int i = blockIdx.x * blockDim.x + threadIdx.x;
    if (i >= NH * SEQ) return;
    const int h = i / SEQ, r = i % SEQ;
    float s = 0.0f;
    #pragma unroll
    for (int x = 0; x < 16; x++)
        s += psum[((size_t)h * 16 + x) * SEQ + r];
    rowinv[i] = 1.0f / s;
}

// ---------------- RoPE + split to fp16 per-head layouts ----------------------
// Q: two limbs [h][s][80]. K: one limb. V^T: two limbs [h][d][s] (rows>=80 unused).
__global__ __launch_bounds__(256) void rope_split_fp16(
    const float* __restrict__ qkv, const float* __restrict__ cosp,
    const float* __restrict__ sinp,
    __half* __restrict__ Qh, __half* __restrict__ Ql,
    __half* __restrict__ Kh,
    __half* __restrict__ Vth, __half* __restrict__ Vtl)
{
    int idx = blockIdx.x * blockDim.x + threadIdx.x;
    if (idx >= SEQ * DIM) return;
    const int d = idx % HD;
    const int h = (idx / HD) % NH;
    const int s = idx / DIM;

    const float c = cosp[s * HD + d];
    const float sn = sinp[s * HD + d];
    const int d2 = (d < HD / 2) ? d + HD / 2 : d - HD / 2;
    const float sign = (d < HD / 2) ? -1.0f : 1.0f;

    const size_t rowbase = (size_t)s * QKV_N + h * HD;
    const size_t oqk = ((size_t)h * SEQ + s) * HD + d;
    const size_t ovt = ((size_t)h * HDV + d) * SEQ + s;

    const float qv = qkv[rowbase + d];
    const float q2 = qkv[rowbase + d2];
    float qr = fmaf(qv, c, sign * q2 * sn);
    split1h(qr, Qh[oqk], Ql[oqk]);

    const float kv = qkv[rowbase + DIM + d];
    const float k2 = qkv[rowbase + DIM + d2];
    float kr = fmaf(kv, c, sign * k2 * sn);
    Kh[oqk] = __float2half(kr);

    split1h(qkv[rowbase + 2 * DIM + d], Vth[ovt], Vtl[ovt]);
}

// ---------------- launch -----------------------------------------------------
extern "C" void kernel_launch(void* const* d_in, const int* in_sizes, int n_in,
                              void* d_out, int out_size)
{
    const float* hidden = (const float*)d_in[0];
    const float* cosp   = (const float*)d_in[2];
    const float* sinp   = (const float*)d_in[3];
    const float* w_qkv  = (const float*)d_in[4];
    const float* b_qkv  = (const float*)d_in[5];
    const float* w_proj = (const float*)d_in[6];
    const float* b_proj = (const float*)d_in[7];
    float* out = (float*)d_out;

    float *qkv, *psum, *rowinv;
    cudaGetSymbolAddress((void**)&qkv, g_qkv);
    cudaGetSymbolAddress((void**)&psum, g_psum);
    cudaGetSymbolAddress((void**)&rowinv, g_rowinv);

    __half *hh, *hl, *wqh, *wph, *qh, *ql, *kh, *vth, *vtl, *ph, *oh, *ol;
    cudaGetSymbolAddress((void**)&hh, g_hid_h);
    cudaGetSymbolAddress((void**)&hl, g_hid_l);
    cudaGetSymbolAddress((void**)&wqh, g_wqkv_h);
    cudaGetSymbolAddress((void**)&wph, g_wproj_h);
    cudaGetSymbolAddress((void**)&qh, g_qh);
    cudaGetSymbolAddress((void**)&ql, g_ql);
    cudaGetSymbolAddress((void**)&kh, g_kh);
    cudaGetSymbolAddress((void**)&vth, g_vth);
    cudaGetSymbolAddress((void**)&vtl, g_vtl);
    cudaGetSymbolAddress((void**)&ph, g_ph);
    cudaGetSymbolAddress((void**)&oh, g_oh);
    cudaGetSymbolAddress((void**)&ol, g_ol);

    cudaFuncSetAttribute(gemm_fp16x2<true>,
                         cudaFuncAttributeMaxDynamicSharedMemorySize, MM_SMEM);
    cudaFuncSetAttribute(gemm_fp16x2<false>,
                         cudaFuncAttributeMaxDynamicSharedMemorySize, MM_SMEM);

    // 0) prepare fp16 operands
    split_fp16<<<(SEQ * DIM + 255) / 256, 256>>>(hidden, hh, hl, SEQ * DIM);
    round_fp16<<<(QKV_N * DIM + 255) / 256, 256>>>(w_qkv, wqh, QKV_N * DIM);
    round_fp16<<<(DIM * DIM + 255) / 256, 256>>>(w_proj, wph, DIM * DIM);

    // 1) QKV = hidden @ w_qkv^T + b_qkv
    {
        dim3 grid(QKV_N / 128, SEQ / 128, 1);
        gemm_fp16x2<true><<<grid, 256, MM_SMEM>>>(
            hh, hl, wqh, b_qkv, qkv,
            DIM, 0, 0, 0, QKV_N, 1.0f, QKV_N,
            nullptr, nullptr, nullptr, nullptr, nullptr);
    }
    // 2) RoPE + per-head fp16 layouts (K=80 unpadded)
    rope_split_fp16<<<(SEQ * DIM + 255) / 256, 256>>>(qkv, cosp, sinp,
                                                      qh, ql, kh, vth, vtl);

    // 3) fused scores + exp: Ph = fp16(exp(scale*Q@K^T)*PSCALE), row partials
    {
        dim3 grid(SEQ / 128, SEQ / 128, NH);
        gemm_fp16x2<true><<<grid, 256, MM_SMEM>>>(
            qh, ql, kh, nullptr, nullptr,
            HD, (size_t)SEQ * HD, (size_t)SEQ * HD,
            (size_t)SEQ * SEQ, SEQ, ATTN_SCALE, SEQ,
            ph, psum, nullptr, nullptr, nullptr);
    }
    // 4) rowsum partials -> 1/rowsum
    reduce_psum<<<(NH * SEQ + 255) / 256, 256>>>(psum, rowinv);

    // 5) O(h/l) = split((Ph @ (Vh+Vl)) * rowinv)   — A single-limb, B two-limb
    {
        dim3 grid(1, SEQ / 128, NH);
        gemm_fp16x2<false><<<grid, 256, MM_SMEM>>>(
            ph, vtl, vth, nullptr, nullptr,
            SEQ, (size_t)SEQ * SEQ, (size_t)HDV * SEQ,
            (size_t)HD, DIM, 1.0f, HD,
            nullptr, nullptr, rowinv, oh, ol);
    }
    // 6) out = O @ w_proj^T + b_proj
    {
        dim3 grid(DIM / 128, SEQ / 128, 1);
        gemm_fp16x2<true><<<grid, 256, MM_SMEM>>>(
            oh, ol, wph, b_proj, out,
            DIM, 0, 0, 0, DIM, 1.0f, DIM,
            nullptr, nullptr, nullptr, nullptr, nullptr);
    }
}

// round 13
// speedup vs baseline: 1.4985x; 1.0074x over previous
#include <cuda_runtime.h>
#include <cuda_fp16.h>
#include <math.h>
#include <cstdint>

#define SEQ 2048
#define NH  16
#define HD  80
#define HDV 128             // padded head dim for V^T (one 128-col N tile)
#define DIM 1280            // NH*HD
#define QKV_N 3840          // 3*DIM
#define ATTN_SCALE 0.11180339887498949f   // 80^-0.5
#define PSCALE 0.0625f      // 2^-4 headroom factor for fp16 exp storage (cancels in rowinv)

// ---------------- scratch (device globals; no allocations allowed) ----------
__device__ float g_qkv[SEQ * QKV_N];          // 31.5 MB
__device__ float g_psum[NH * 16 * SEQ];       // per-(head, n-tile) row partial sums
__device__ float g_rowinv[NH * SEQ];          // 1 / rowsum (of scaled exp)

__device__ __half g_hid_h[SEQ * DIM];
__device__ __half g_hid_l[SEQ * DIM];
__device__ __half g_wqkv_h[QKV_N * DIM];      // weights: single fp16 limb
__device__ __half g_wproj_h[DIM * DIM];
__device__ __half g_qh[NH * SEQ * HD];
__device__ __half g_ql[NH * SEQ * HD];
__device__ __half g_kh[NH * SEQ * HD];        // K: single limb (B side of scores)
__device__ __half g_vth[NH * HDV * SEQ];      // V^T: two limbs (rows >= HD unused)
__device__ __half g_vtl[NH * HDV * SEQ];
__device__ __half g_ph[(size_t)NH * SEQ * SEQ];  // 64 MB (scaled unnormalized expS, single limb)
__device__ __half g_oh[SEQ * DIM];
__device__ __half g_ol[SEQ * DIM];

// ================= helpers ====================================================
__device__ __forceinline__ uint32_t smem_u32(const void* p) {
    uint32_t a;
    asm("{ .reg .u64 t; cvta.to.shared.u64 t, %1; cvt.u32.u64 %0, t; }" : "=r"(a) : "l"(p));
    return a;
}
#define CP_ASYNC16(dst, src) \
    asm volatile("cp.async.cg.shared.global [%0], [%1], 16;" :: "r"(dst), "l"(src) : "memory")
#define CP_COMMIT() asm volatile("cp.async.commit_group;" ::: "memory")
#define CP_WAIT1()  asm volatile("cp.async.wait_group 1;" ::: "memory")

#define LDSM_X4(r0, r1, r2, r3, addr) \
    asm volatile("ldmatrix.sync.aligned.m8n8.x4.shared.b16 {%0,%1,%2,%3}, [%4];" \
        : "=r"(r0), "=r"(r1), "=r"(r2), "=r"(r3) : "r"(addr))

#define MMA16816(c, a, b0, b1) \
    asm volatile("mma.sync.aligned.m16n8k16.row.col.f32.f16.f16.f32 " \
        "{%0,%1,%2,%3}, {%4,%5,%6,%7}, {%8,%9}, {%0,%1,%2,%3};" \
        : "+f"((c)[0]), "+f"((c)[1]), "+f"((c)[2]), "+f"((c)[3]) \
        : "r"((a)[0]), "r"((a)[1]), "r"((a)[2]), "r"((a)[3]), "r"(b0), "r"(b1))

__device__ __forceinline__ void split1h(float v, __half& h, __half& l) {
    h = __float2half(v);
    l = __float2half(v - __half2float(h));
}

// ================= fp32 -> fp16 splits =======================================
__global__ __launch_bounds__(256) void split_fp16(
    const float* __restrict__ x, __half* __restrict__ hi,
    __half* __restrict__ lo, int n)
{
    int i = blockIdx.x * blockDim.x + threadIdx.x;
    if (i >= n) return;
    split1h(x[i], hi[i], lo[i]);
}
__global__ __launch_bounds__(256) void round_fp16(
    const float* __restrict__ x, __half* __restrict__ hi, int n)
{
    int i = blockIdx.x * blockDim.x + threadIdx.x;
    if (i >= n) return;
    hi[i] = __float2half(x[i]);
}

// ================= mma.sync fp16x2 NT GEMM (3-stage pipeline) ================
// C = alpha * A(MxK) @ B(NxK)^T (+bias), 2-term limb product:
//   ASPLIT=true : A = A0 + X1 (two limbs), B = B0       -> A0*B0 + X1*B0
//   ASPLIT=false: A = A0,                 B = B0 + X1   -> A0*B0 + A0*X1
// K%16==0 (tail handled as half chunk). Epilogues:
//   psum != null : e = expf(alpha*acc)*PSCALE -> Ph (fp16), row partials -> psum
//   Oh   != null : v = acc*alpha*rowinv[row]  -> (Oh, Ol) fp16 two-limb
//   else         : C = alpha*acc (*rowinv) + bias, cols < n_valid
#define MM_TILE_B 10240        // 128 rows * 80 bytes (40 halves, padded from 32)
#define MM_BUF_B  (3 * MM_TILE_B)
#define MM_SMEM   (3 * MM_BUF_B)   // 92160 (3 pipeline stages)

template<bool ASPLIT>
__global__ __launch_bounds__(256, 2) void gemm_fp16x2(
    const __half* __restrict__ A0, const __half* __restrict__ X1,
    const __half* __restrict__ B0,
    const float* __restrict__ bias, float* __restrict__ C,
    int K, size_t sA, size_t sB, size_t sC, int ldc, float alpha, int n_valid,
    __half* __restrict__ Ph, float* __restrict__ psum,
    const float* __restrict__ rowinv,
    __half* __restrict__ Oh, __half* __restrict__ Ol)
{
    extern __shared__ char sm[];
    const uint32_t sbase = smem_u32(sm);
    const int tid = threadIdx.x;
    const int lane = tid & 31;
    const int wid = tid >> 5;
    const int wy = wid >> 2;          // 0..1
    const int wx = wid & 3;           // 0..3
    const int m0 = blockIdx.y * 128;
    const int n0 = blockIdx.x * 128;
    const int bz = blockIdx.z;
    const int NC = (K + 31) >> 5;     // chunks; last may be half (16)

    bool npok[2];
    #pragma unroll
    for (int np = 0; np < 2; np++)
        npok[np] = (n0 + wx * 32 + np * 16) < n_valid;

    // tiles: T0 = A limb0, T1 = (A limb1 | B limb1), T2 = B limb0
    const __half* srcs[3] = {A0 + bz * sA,
                             ASPLIT ? X1 + bz * sA : X1 + bz * sB,
                             B0 + bz * sB};
    const int rbases[3] = {m0, ASPLIT ? m0 : n0, n0};

    float acc[4][4][4];
    #pragma unroll
    for (int i = 0; i < 4; i++)
        #pragma unroll
        for (int j = 0; j < 4; j++)
            #pragma unroll
            for (int k = 0; k < 4; k++) acc[i][j][k] = 0.0f;

    auto load_chunk = [&](int c, int b) {
        const int k0 = c << 5;
        const bool hc = (k0 + 32 > K);
        #pragma unroll
        for (int t = 0; t < 3; t++) {
            const __half* src = srcs[t];
            const int rbase = rbases[t];
            const uint32_t tb = sbase + b * MM_BUF_B + t * MM_TILE_B;
            if (!hc) {
                #pragma unroll
                for (int i = 0; i < 2; i++) {
                    const int g = tid + i * 256;       // 0..511
                    const int row = g >> 2, q = g & 3;
                    const uint32_t dst = tb + row * 80 + q * 16;
                    const void* s = (const void*)(src + (size_t)(rbase + row) * K + k0 + q * 8);
                    CP_ASYNC16(dst, s);
                }
            } else {
                const int row = tid >> 1, q = tid & 1;  // 16 cols only
                const uint32_t dst = tb + row * 80 + q * 16;
                const void* s = (const void*)(src + (size_t)(rbase + row) * K + k0 + q * 8);
                CP_ASYNC16(dst, s);
            }
        }
    };

    // ---- prologue: stage chunks 0 and 1 ----
    load_chunk(0, 0);
    CP_COMMIT();
    if (NC > 1) load_chunk(1, 1);
    CP_COMMIT();                      // (possibly empty group; keeps count exact)

    int bc = 0;                       // buffer of chunk c
    int lb = 2;                       // buffer for chunk c+2
    for (int c = 0; c < NC; c++) {
        CP_WAIT1();                   // chunk c resident (newest pending: c+1)
        __syncthreads();              // all warps past chunk c-1 MMAs -> buf lb reusable

        if (c + 2 < NC) load_chunk(c + 2, lb);
        CP_COMMIT();                  // one group per iteration (may be empty)

        const bool hc = ((c << 5) + 32 > K);
        const uint32_t bufb = sbase + bc * MM_BUF_B;
        if (npok[0]) {
            #pragma unroll
            for (int ks = 0; ks < 2; ks++) {
                if (ks == 1 && hc) break;
                const int fcol = ks * 16 + (lane >> 4) * 8;
                uint32_t b0f[2][4], b1f[2][4];
                #pragma unroll
                for (int np = 0; np < 2; np++) {
                    if (!npok[np]) continue;
                    const int r = wx * 32 + np * 16 + (lane & 15);
                    const uint32_t bd = bufb + 2 * MM_TILE_B + r * 80 + fcol * 2;
                    LDSM_X4(b0f[np][0], b0f[np][1], b0f[np][2], b0f[np][3], bd);
                    if (!ASPLIT) {
                        const uint32_t bd1 = bufb + 1 * MM_TILE_B + r * 80 + fcol * 2;
                        LDSM_X4(b1f[np][0], b1f[np][1], b1f[np][2], b1f[np][3], bd1);
                    }
                }
                #pragma unroll
                for (int mt = 0; mt < 4; mt++) {
                    const int r = wy * 64 + mt * 16 + (lane & 15);
                    const uint32_t ad = bufb + r * 80 + fcol * 2;
                    uint32_t a0f[4], a1f[4];
                    LDSM_X4(a0f[0], a0f[1], a0f[2], a0f[3], ad);
                    if (ASPLIT) {
                        const uint32_t ad1 = ad + MM_TILE_B;
                        LDSM_X4(a1f[0], a1f[1], a1f[2], a1f[3], ad1);
                    }
                    #pragma unroll
                    for (int np = 0; np < 2; np++) {
                        if (!npok[np]) continue;
                        MMA16816(acc[mt][np * 2],     a0f, b0f[np][0], b0f[np][2]);
                        MMA16816(acc[mt][np * 2 + 1], a0f, b0f[np][1], b0f[np][3]);
                    }
                    #pragma unroll
                    for (int np = 0; np < 2; np++) {
                        if (!npok[np]) continue;
                        if (ASPLIT) {
                            MMA16816(acc[mt][np * 2],     a1f, b0f[np][0], b0f[np][2]);
                            MMA16816(acc[mt][np * 2 + 1], a1f, b0f[np][1], b0f[np][3]);
                        } else {
                            MMA16816(acc[mt][np * 2],     a0f, b1f[np][0], b1f[np][2]);
                            MMA16816(acc[mt][np * 2 + 1], a0f, b1f[np][1], b1f[np][3]);
                        }
                    }
                }
            }
        }
        bc = (bc == 2) ? 0 : bc + 1;
        lb = (lb == 2) ? 0 : lb + 1;
    }
    __syncthreads();                  // protect epilogue smem reuse

    const int quad = lane >> 2, tq = lane & 3;

    if (psum) {
        // ---- exp epilogue (fused unnormalized softmax, single-limb fp16 P) ----
        const int Mtot = gridDim.y * 128;
        __half* Phb = Ph + (size_t)bz * sC;
        float rs[4][2];
        #pragma unroll
        for (int mt = 0; mt < 4; mt++) { rs[mt][0] = 0.0f; rs[mt][1] = 0.0f; }

        #pragma unroll
        for (int mt = 0; mt < 4; mt++) {
            const int row = m0 + wy * 64 + mt * 16 + quad;
            #pragma unroll
            for (int nt = 0; nt < 4; nt++) {
                const int col = n0 + wx * 32 + nt * 8 + tq * 2;
                float e0 = __expf(acc[mt][nt][0] * alpha) * PSCALE;
                float e1 = __expf(acc[mt][nt][1] * alpha) * PSCALE;
                float e2 = __expf(acc[mt][nt][2] * alpha) * PSCALE;
                float e3 = __expf(acc[mt][nt][3] * alpha) * PSCALE;
                rs[mt][0] += e0 + e1;
                rs[mt][1] += e2 + e3;
                __half2 p01 = {__float2half(e0), __float2half(e1)};
                __half2 p23 = {__float2half(e2), __float2half(e3)};
                *reinterpret_cast<__half2*>(Phb + (size_t)row * ldc + col) = p01;
                *reinterpret_cast<__half2*>(Phb + (size_t)(row + 8) * ldc + col) = p23;
            }
            #pragma unroll
            for (int j = 0; j < 2; j++) {
                rs[mt][j] += __shfl_xor_sync(0xffffffff, rs[mt][j], 1);
                rs[mt][j] += __shfl_xor_sync(0xffffffff, rs[mt][j], 2);
            }
        }
        float* red = reinterpret_cast<float*>(sm);
        if (tq == 0) {
            #pragma unroll
            for (int mt = 0; mt < 4; mt++) {
                red[(wy * 64 + mt * 16 + quad) * 4 + wx] = rs[mt][0];
                red[(wy * 64 + mt * 16 + quad + 8) * 4 + wx] = rs[mt][1];
            }
        }
        __syncthreads();
        if (tid < 128) {
            float s = red[tid * 4] + red[tid * 4 + 1] + red[tid * 4 + 2] + red[tid * 4 + 3];
            psum[((size_t)bz * gridDim.x + blockIdx.x) * Mtot + m0 + tid] = s;
        }
    } else if (Oh) {
        // ---- normalize + fp16 two-limb epilogue (PV output) ----
        if (npok[0]) {
            const float* rinv = rowinv + (size_t)bz * (gridDim.y * 128);
            __half* Ohb = Oh + (size_t)bz * sC;
            __half* Olb = Ol + (size_t)bz * sC;
            #pragma unroll
            for (int mt = 0; mt < 4; mt++) {
                const int row = m0 + wy * 64 + mt * 16 + quad;
                const float s0 = rinv[row];
                const float s1 = rinv[row + 8];
                #pragma unroll
                for (int nt = 0; nt < 4; nt++) {
                    const int col = n0 + wx * 32 + nt * 8 + tq * 2;
                    if (col >= n_valid) continue;
                    __half h0, l0, h1, l1, h2, l2, h3, l3;
                    split1h(acc[mt][nt][0] * alpha * s0, h0, l0);
                    split1h(acc[mt][nt][1] * alpha * s0, h1, l1);
                    split1h(acc[mt][nt][2] * alpha * s1, h2, l2);
                    split1h(acc[mt][nt][3] * alpha * s1, h3, l3);
                    __half2 oh01 = {h0, h1}, ol01 = {l0, l1};
                    __half2 oh23 = {h2, h3}, ol23 = {l2, l3};
                    *reinterpret_cast<__half2*>(Ohb + (size_t)row * ldc + col) = oh01;
                    *reinterpret_cast<__half2*>(Olb + (size_t)row * ldc + col) = ol01;
                    *reinterpret_cast<__half2*>(Ohb + (size_t)(row + 8) * ldc + col) = oh23;
                    *reinterpret_cast<__half2*>(Olb + (size_t)(row + 8) * ldc + col) = ol23;
                }
            }
        }
    } else if (npok[0]) {
        // ---- standard epilogue ----
        float* Cb = C + bz * sC;
        #pragma unroll
        for (int mt = 0; mt < 4; mt++) {
            const int row = m0 + wy * 64 + mt * 16 + quad;
            #pragma unroll
            for (int nt = 0; nt < 4; nt++) {
                const int col = n0 + wx * 32 + nt * 8 + tq * 2;
                if (col >= n_valid) continue;
                float b0 = bias ? bias[col] : 0.0f;
                float b1 = bias ? bias[col + 1] : 0.0f;
                float2 v0 = make_float2(acc[mt][nt][0] * alpha + b0,
                                        acc[mt][nt][1] * alpha + b1);
                float2 v1 = make_float2(acc[mt][nt][2] * alpha + b0,
                                        acc[mt][nt][3] * alpha + b1);
                *reinterpret_cast<float2*>(Cb + (size_t)row * ldc + col) = v0;
                *reinterpret_cast<float2*>(Cb + (size_t)(row + 8) * ldc + col) = v1;
            }
        }
    }
}

// ---------------- reduce per-tile partials -> 1/rowsum ----------------------
__global__ __launch_bounds__(256) void reduce_psum(
    const float* __restrict__ psum, float* __restrict__ rowinv)
{
    int i = blockIdx.x * blockDim.x + threadIdx.x;
    if (i >= NH * SEQ) return;
    const int h = i / SEQ, r = i % SEQ;
    float s = 0.0f;
    #pragma unroll
    for (int x = 0; x < 16; x++)
        s += psum[((size_t)h * 16 + x) * SEQ + r];
    rowinv[i] = 1.0f / s;
}

// ---------------- RoPE + split to fp16 per-head layouts ----------------------
// Q: two limbs [h][s][80]. K: one limb. V^T: two limbs [h][d][s] (rows>=80 unused).
__global__ __launch_bounds__(256) void rope_split_fp16(
    const float* __restrict__ qkv, const float* __restrict__ cosp,
    const float* __restrict__ sinp,
    __half* __restrict__ Qh, __half* __restrict__ Ql,
    __half* __restrict__ Kh,
    __half* __restrict__ Vth, __half* __restrict__ Vtl)
{
    int idx = blockIdx.x * blockDim.x + threadIdx.x;
    if (idx >= SEQ * DIM) return;
    const int d = idx % HD;
    const int h = (idx / HD) % NH;
    const int s = idx / DIM;

    const float c = cosp[s * HD + d];
    const float sn = sinp[s * HD + d];
    const int d2 = (d < HD / 2) ? d + HD / 2 : d - HD / 2;
    const float sign = (d < HD / 2) ? -1.0f : 1.0f;

    const size_t rowbase = (size_t)s * QKV_N + h * HD;
    const size_t oqk = ((size_t)h * SEQ + s) * HD + d;
    const size_t ovt = ((size_t)h * HDV + d) * SEQ + s;

    const float qv = qkv[rowbase + d];
    const float q2 = qkv[rowbase + d2];
    float qr = fmaf(qv, c, sign * q2 * sn);
    split1h(qr, Qh[oqk], Ql[oqk]);

    const float kv = qkv[rowbase + DIM + d];
    const float k2 = qkv[rowbase + DIM + d2];
    float kr = fmaf(kv, c, sign * k2 * sn);
    Kh[oqk] = __float2half(kr);

    split1h(qkv[rowbase + 2 * DIM + d], Vth[ovt], Vtl[ovt]);
}

// ---------------- launch -----------------------------------------------------
extern "C" void kernel_launch(void* const* d_in, const int* in_sizes, int n_in,
                              void* d_out, int out_size)
{
    const float* hidden = (const float*)d_in[0];
    const float* cosp   = (const float*)d_in[2];
    const float* sinp   = (const float*)d_in[3];
    const float* w_qkv  = (const float*)d_in[4];
    const float* b_qkv  = (const float*)d_in[5];
    const float* w_proj = (const float*)d_in[6];
    const float* b_proj = (const float*)d_in[7];
    float* out = (float*)d_out;

    float *qkv, *psum, *rowinv;
    cudaGetSymbolAddress((void**)&qkv, g_qkv);
    cudaGetSymbolAddress((void**)&psum, g_psum);
    cudaGetSymbolAddress((void**)&rowinv, g_rowinv);

    __half *hh, *hl, *wqh, *wph, *qh, *ql, *kh, *vth, *vtl, *ph, *oh, *ol;
    cudaGetSymbolAddress((void**)&hh, g_hid_h);
    cudaGetSymbolAddress((void**)&hl, g_hid_l);
    cudaGetSymbolAddress((void**)&wqh, g_wqkv_h);
    cudaGetSymbolAddress((void**)&wph, g_wproj_h);
    cudaGetSymbolAddress((void**)&qh, g_qh);
    cudaGetSymbolAddress((void**)&ql, g_ql);
    cudaGetSymbolAddress((void**)&kh, g_kh);
    cudaGetSymbolAddress((void**)&vth, g_vth);
    cudaGetSymbolAddress((void**)&vtl, g_vtl);
    cudaGetSymbolAddress((void**)&ph, g_ph);
    cudaGetSymbolAddress((void**)&oh, g_oh);
    cudaGetSymbolAddress((void**)&ol, g_ol);

    cudaFuncSetAttribute(gemm_fp16x2<true>,
                         cudaFuncAttributeMaxDynamicSharedMemorySize, MM_SMEM);
    cudaFuncSetAttribute(gemm_fp16x2<false>,
                         cudaFuncAttributeMaxDynamicSharedMemorySize, MM_SMEM);

    // 0) prepare fp16 operands
    split_fp16<<<(SEQ * DIM + 255) / 256, 256>>>(hidden, hh, hl, SEQ * DIM);
    round_fp16<<<(QKV_N * DIM + 255) / 256, 256>>>(w_qkv, wqh, QKV_N * DIM);
    round_fp16<<<(DIM * DIM + 255) / 256, 256>>>(w_proj, wph, DIM * DIM);

    // 1) QKV = hidden @ w_qkv^T + b_qkv
    {
        dim3 grid(QKV_N / 128, SEQ / 128, 1);
        gemm_fp16x2<true><<<grid, 256, MM_SMEM>>>(
            hh, hl, wqh, b_qkv, qkv,
            DIM, 0, 0, 0, QKV_N, 1.0f, QKV_N,
            nullptr, nullptr, nullptr, nullptr, nullptr);
    }
    // 2) RoPE + per-head fp16 layouts (K=80 unpadded)
    rope_split_fp16<<<(SEQ * DIM + 255) / 256, 256>>>(qkv, cosp, sinp,
                                                      qh, ql, kh, vth, vtl);

    // 3) fused scores + exp: Ph = fp16(exp(scale*Q@K^T)*PSCALE), row partials
    {
        dim3 grid(SEQ / 128, SEQ / 128, NH);
        gemm_fp16x2<true><<<grid, 256, MM_SMEM>>>(
            qh, ql, kh, nullptr, nullptr,
            HD, (size_t)SEQ * HD, (size_t)SEQ * HD,
            (size_t)SEQ * SEQ, SEQ, ATTN_SCALE, SEQ,
            ph, psum, nullptr, nullptr, nullptr);
    }
    // 4) rowsum partials -> 1/rowsum
    reduce_psum<<<(NH * SEQ + 255) / 256, 256>>>(psum, rowinv);

    // 5) O(h/l) = split((Ph @ (Vh+Vl)) * rowinv)   — A single-limb, B two-limb
    {
        dim3 grid(1, SEQ / 128, NH);
        gemm_fp16x2<false><<<grid, 256, MM_SMEM>>>(
            ph, vtl, vth, nullptr, nullptr,
            SEQ, (size_t)SEQ * SEQ, (size_t)HDV * SEQ,
            (size_t)HD, DIM, 1.0f, HD,
            nullptr, nullptr, rowinv, oh, ol);
    }
    // 6) out = O @ w_proj^T + b_proj
    {
        dim3 grid(DIM / 128, SEQ / 128, 1);
        gemm_fp16x2<true><<<grid, 256, MM_SMEM>>>(
            oh, ol, wph, b_proj, out,
            DIM, 0, 0, 0, DIM, 1.0f, DIM,
            nullptr, nullptr, nullptr, nullptr, nullptr);
    }
}

// round 14
// speedup vs baseline: 1.5825x; 1.0561x over previous
#include <cuda_runtime.h>
#include <cuda_fp16.h>
#include <math.h>
#include <cstdint>

#define SEQ 2048
#define NH  16
#define HD  80
#define HDV 128             // padded head dim for V^T (one 128-col N tile)
#define DIM 1280            // NH*HD
#define QKV_N 3840          // 3*DIM
#define ATTN_SCALE 0.11180339887498949f   // 80^-0.5
#define PSCALE 0.0625f      // 2^-4 headroom for fp16 exp storage (cancels in rowinv)

// ---------------- scratch (device globals; no allocations allowed) ----------
__device__ float g_qkv[SEQ * QKV_N];          // 31.5 MB
__device__ float g_psum[NH * 16 * SEQ];       // per-(head, n-tile) row partial sums
__device__ float g_rowinv[NH * SEQ];          // 1 / rowsum (of scaled exp)

__device__ __half g_hid_h[SEQ * DIM];
__device__ __half g_hid_l[SEQ * DIM];
__device__ __half g_wqkv_h[QKV_N * DIM];      // weights: single fp16 limb
__device__ __half g_wproj_h[DIM * DIM];
__device__ __half g_qh[NH * SEQ * HD];        // Q: single limb (scores is 1x1-limb)
__device__ __half g_kh[NH * SEQ * HD];        // K: single limb
__device__ __half g_vth[NH * HDV * SEQ];      // V^T: two limbs (rows >= HD unused)
__device__ __half g_vtl[NH * HDV * SEQ];
__device__ __half g_ph[(size_t)NH * SEQ * SEQ];  // 64 MB (scaled unnormalized expS)
__device__ __half g_oh[SEQ * DIM];
__device__ __half g_ol[SEQ * DIM];

// ================= helpers ====================================================
__device__ __forceinline__ uint32_t smem_u32(const void* p) {
    uint32_t a;
    asm("{ .reg .u64 t; cvta.to.shared.u64 t, %1; cvt.u32.u64 %0, t; }" : "=r"(a) : "l"(p));
    return a;
}
#define CP_ASYNC16(dst, src) \
    asm volatile("cp.async.cg.shared.global [%0], [%1], 16;" :: "r"(dst), "l"(src) : "memory")
#define CP_COMMIT() asm volatile("cp.async.commit_group;" ::: "memory")
#define CP_WAIT1()  asm volatile("cp.async.wait_group 1;" ::: "memory")

#define LDSM_X4(r0, r1, r2, r3, addr) \
    asm volatile("ldmatrix.sync.aligned.m8n8.x4.shared.b16 {%0,%1,%2,%3}, [%4];" \
        : "=r"(r0), "=r"(r1), "=r"(r2), "=r"(r3) : "r"(addr))

#define MMA16816(c, a, b0, b1) \
    asm volatile("mma.sync.aligned.m16n8k16.row.col.f32.f16.f16.f32 " \
        "{%0,%1,%2,%3}, {%4,%5,%6,%7}, {%8,%9}, {%0,%1,%2,%3};" \
        : "+f"((c)[0]), "+f"((c)[1]), "+f"((c)[2]), "+f"((c)[3]) \
        : "r"((a)[0]), "r"((a)[1]), "r"((a)[2]), "r"((a)[3]), "r"(b0), "r"(b1))

__device__ __forceinline__ void split1h(float v, __half& h, __half& l) {
    h = __float2half(v);
    l = __float2half(v - __half2float(h));
}

// ================= fp32 -> fp16 splits =======================================
__global__ __launch_bounds__(256) void split_fp16(
    const float* __restrict__ x, __half* __restrict__ hi,
    __half* __restrict__ lo, int n)
{
    int i = blockIdx.x * blockDim.x + threadIdx.x;
    if (i >= n) return;
    split1h(x[i], hi[i], lo[i]);
}
__global__ __launch_bounds__(256) void round_fp16(
    const float* __restrict__ x, __half* __restrict__ hi, int n)
{
    int i = blockIdx.x * blockDim.x + threadIdx.x;
    if (i >= n) return;
    hi[i] = __float2half(x[i]);
}

// ================= mma.sync fp16 limb GEMM (3-stage pipeline) ================
// C = alpha * A(MxK) @ B(NxK)^T (+bias), limb product with ALIMBS/BLIMBS in {1,2}:
//   (2,1): (A0+X1A)*B0   (1,2): A0*(B0+X1B)   (1,1): A0*B0
// X1 is the lo-limb pointer (for A if ALIMBS==2, for B if BLIMBS==2).
// Warp layout: (2,1) -> 4x2 warps (32x64 warp tile, min smem traffic);
//              else  -> 2x4 warps (64x32 warp tile).
// K%16==0 (tail = half chunk). Epilogues:
//   psum != null : e = expf(alpha*acc)*PSCALE -> Ph (fp16), row partials -> psum
//   Oh   != null : v = acc*alpha*rowinv[row]  -> (Oh, Ol) fp16 two-limb
//   else         : C = alpha*acc + bias, cols < n_valid
#define MM_TILE_B 10240        // 128 rows * 80 bytes (40 halves, padded from 32)

template<int ALIMBS, int BLIMBS>
__global__ __launch_bounds__(256, 2) void gemm_fp16(
    const __half* __restrict__ A0, const __half* __restrict__ X1,
    const __half* __restrict__ B0,
    const float* __restrict__ bias, float* __restrict__ C,
    int K, size_t sA, size_t sB, size_t sC, int ldc, float alpha, int n_valid,
    __half* __restrict__ Ph, float* __restrict__ psum,
    const float* __restrict__ rowinv,
    __half* __restrict__ Oh, __half* __restrict__ Ol)
{
    constexpr int NWY = (ALIMBS == 2) ? 4 : 2;
    constexpr int NWX = 8 / NWY;
    constexpr int MT  = 128 / (NWY * 16);     // 2 or 4
    constexpr int NP  = 128 / (NWX * 16);     // 4 or 2
    constexpr int NTILES = ALIMBS + BLIMBS;
    constexpr int BUF_B = NTILES * MM_TILE_B;

    extern __shared__ char sm[];
    const uint32_t sbase = smem_u32(sm);
    const int tid = threadIdx.x;
    const int lane = tid & 31;
    const int wid = tid >> 5;
    const int wy = wid / NWX;
    const int wx = wid % NWX;
    const int m0 = blockIdx.y * 128;
    const int n0 = blockIdx.x * 128;
    const int bz = blockIdx.z;
    const int NC = (K + 31) >> 5;     // chunks; last may be half (16)

    bool npok[NP];
    #pragma unroll
    for (int np = 0; np < NP; np++)
        npok[np] = (n0 + wx * (NP * 16) + np * 16) < n_valid;

    const __half* srcs[NTILES];
    int rbases[NTILES];
    srcs[0] = A0 + bz * sA; rbases[0] = m0;
    if constexpr (ALIMBS == 2) { srcs[1] = X1 + bz * sA; rbases[1] = m0; }
    srcs[ALIMBS] = B0 + bz * sB; rbases[ALIMBS] = n0;
    if constexpr (BLIMBS == 2) { srcs[ALIMBS + 1] = X1 + bz * sB; rbases[ALIMBS + 1] = n0; }

    float acc[MT][2 * NP][4];
    #pragma unroll
    for (int i = 0; i < MT; i++)
        #pragma unroll
        for (int j = 0; j < 2 * NP; j++)
            #pragma unroll
            for (int k = 0; k < 4; k++) acc[i][j][k] = 0.0f;

    auto load_chunk = [&](int c, int b) {
        const int k0 = c << 5;
        const bool hc = (k0 + 32 > K);
        #pragma unroll
        for (int t = 0; t < NTILES; t++) {
            const __half* src = srcs[t];
            const int rbase = rbases[t];
            const uint32_t tb = sbase + b * BUF_B + t * MM_TILE_B;
            if (!hc) {
                #pragma unroll
                for (int i = 0; i < 2; i++) {
                    const int g = tid + i * 256;       // 0..511
                    const int row = g >> 2, q = g & 3;
                    const uint32_t dst = tb + row * 80 + q * 16;
                    const void* s = (const void*)(src + (size_t)(rbase + row) * K + k0 + q * 8);
                    CP_ASYNC16(dst, s);
                }
            } else {
                const int row = tid >> 1, q = tid & 1;  // 16 cols only
                const uint32_t dst = tb + row * 80 + q * 16;
                const void* s = (const void*)(src + (size_t)(rbase + row) * K + k0 + q * 8);
                CP_ASYNC16(dst, s);
            }
        }
    };

    // ---- prologue: stage chunks 0 and 1 ----
    load_chunk(0, 0);
    CP_COMMIT();
    if (NC > 1) load_chunk(1, 1);
    CP_COMMIT();

    int bc = 0, lb = 2;
    for (int c = 0; c < NC; c++) {
        CP_WAIT1();
        __syncthreads();

        if (c + 2 < NC) load_chunk(c + 2, lb);
        CP_COMMIT();

        const bool hc = ((c << 5) + 32 > K);
        const uint32_t bufb = sbase + bc * BUF_B;
        if (npok[0]) {
            #pragma unroll
            for (int ks = 0; ks < 2; ks++) {
                if (ks == 1 && hc) break;
                const int fcol = ks * 16 + (lane >> 4) * 8;
                uint32_t b0f[NP][4], b1f[NP][4];
                #pragma unroll
                for (int np = 0; np < NP; np++) {
                    if (!npok[np]) continue;
                    const int r = wx * (NP * 16) + np * 16 + (lane & 15);
                    const uint32_t bd = bufb + ALIMBS * MM_TILE_B + r * 80 + fcol * 2;
                    LDSM_X4(b0f[np][0], b0f[np][1], b0f[np][2], b0f[np][3], bd);
                    if constexpr (BLIMBS == 2) {
                        LDSM_X4(b1f[np][0], b1f[np][1], b1f[np][2], b1f[np][3],
                                bd + MM_TILE_B);
                    }
                }
                #pragma unroll
                for (int mt = 0; mt < MT; mt++) {
                    const int r = wy * (MT * 16) + mt * 16 + (lane & 15);
                    const uint32_t ad = bufb + r * 80 + fcol * 2;
                    uint32_t a0f[4], a1f[4];
                    LDSM_X4(a0f[0], a0f[1], a0f[2], a0f[3], ad);
                    if constexpr (ALIMBS == 2) {
                        LDSM_X4(a1f[0], a1f[1], a1f[2], a1f[3], ad + MM_TILE_B);
                    }
                    #pragma unroll
                    for (int np = 0; np < NP; np++) {
                        if (!npok[np]) continue;
                        MMA16816(acc[mt][np * 2],     a0f, b0f[np][0], b0f[np][2]);
                        MMA16816(acc[mt][np * 2 + 1], a0f, b0f[np][1], b0f[np][3]);
                    }
                    if constexpr (ALIMBS == 2) {
                        #pragma unroll
                        for (int np = 0; np < NP; np++) {
                            if (!npok[np]) continue;
                            MMA16816(acc[mt][np * 2],     a1f, b0f[np][0], b0f[np][2]);
                            MMA16816(acc[mt][np * 2 + 1], a1f, b0f[np][1], b0f[np][3]);
                        }
                    } else if constexpr (BLIMBS == 2) {
                        #pragma unroll
                        for (int np = 0; np < NP; np++) {
                            if (!npok[np]) continue;
                            MMA16816(acc[mt][np * 2],     a0f, b1f[np][0], b1f[np][2]);
                            MMA16816(acc[mt][np * 2 + 1], a0f, b1f[np][1], b1f[np][3]);
                        }
                    }
                }
            }
        }
        bc = (bc == 2) ? 0 : bc + 1;
        lb = (lb == 2) ? 0 : lb + 1;
    }
    __syncthreads();                  // protect epilogue smem reuse

    const int quad = lane >> 2, tq = lane & 3;

    if (psum) {
        // ---- exp epilogue (fused unnormalized softmax, single-limb fp16 P) ----
        const int Mtot = gridDim.y * 128;
        __half* Phb = Ph + (size_t)bz * sC;
        float rs[MT][2];
        #pragma unroll
        for (int mt = 0; mt < MT; mt++) { rs[mt][0] = 0.0f; rs[mt][1] = 0.0f; }

        #pragma unroll
        for (int mt = 0; mt < MT; mt++) {
            const int row = m0 + wy * (MT * 16) + mt * 16 + quad;
            #pragma unroll
            for (int nt = 0; nt < 2 * NP; nt++) {
                const int col = n0 + wx * (NP * 16) + nt * 8 + tq * 2;
                float e0 = __expf(acc[mt][nt][0] * alpha) * PSCALE;
                float e1 = __expf(acc[mt][nt][1] * alpha) * PSCALE;
                float e2 = __expf(acc[mt][nt][2] * alpha) * PSCALE;
                float e3 = __expf(acc[mt][nt][3] * alpha) * PSCALE;
                rs[mt][0] += e0 + e1;
                rs[mt][1] += e2 + e3;
                __half2 p01 = {__float2half(e0), __float2half(e1)};
                __half2 p23 = {__float2half(e2), __float2half(e3)};
                *reinterpret_cast<__half2*>(Phb + (size_t)row * ldc + col) = p01;
                *reinterpret_cast<__half2*>(Phb + (size_t)(row + 8) * ldc + col) = p23;
            }
            #pragma unroll
            for (int j = 0; j < 2; j++) {
                rs[mt][j] += __shfl_xor_sync(0xffffffff, rs[mt][j], 1);
                rs[mt][j] += __shfl_xor_sync(0xffffffff, rs[mt][j], 2);
            }
        }
        float* red = reinterpret_cast<float*>(sm);
        if (tq == 0) {
            #pragma unroll
            for (int mt = 0; mt < MT; mt++) {
                red[(wy * (MT * 16) + mt * 16 + quad) * NWX + wx] = rs[mt][0];
                red[(wy * (MT * 16) + mt * 16 + quad + 8) * NWX + wx] = rs[mt][1];
            }
        }
        __syncthreads();
        if (tid < 128) {
            float s = 0.0f;
            #pragma unroll
            for (int x = 0; x < NWX; x++) s += red[tid * NWX + x];
            psum[((size_t)bz * gridDim.x + blockIdx.x) * Mtot + m0 + tid] = s;
        }
    } else if (Oh) {
        // ---- normalize + fp16 two-limb epilogue (PV output) ----
        if (npok[0]) {
            const float* rinv = rowinv + (size_t)bz * (gridDim.y * 128);
            __half* Ohb = Oh + (size_t)bz * sC;
            __half* Olb = Ol + (size_t)bz * sC;
            #pragma unroll
            for (int mt = 0; mt < MT; mt++) {
                const int row = m0 + wy * (MT * 16) + mt * 16 + quad;
                const float s0 = rinv[row];
                const float s1 = rinv[row + 8];
                #pragma unroll
                for (int nt = 0; nt < 2 * NP; nt++) {
                    const int col = n0 + wx * (NP * 16) + nt * 8 + tq * 2;
                    if (col >= n_valid) continue;
                    __half h0, l0, h1, l1, h2, l2, h3, l3;
                    split1h(acc[mt][nt][0] * alpha * s0, h0, l0);
                    split1h(acc[mt][nt][1] * alpha * s0, h1, l1);
                    split1h(acc[mt][nt][2] * alpha * s1, h2, l2);
                    split1h(acc[mt][nt][3] * alpha * s1, h3, l3);
                    __half2 oh01 = {h0, h1}, ol01 = {l0, l1};
                    __half2 oh23 = {h2, h3}, ol23 = {l2, l3};
                    *reinterpret_cast<__half2*>(Ohb + (size_t)row * ldc + col) = oh01;
                    *reinterpret_cast<__half2*>(Olb + (size_t)row * ldc + col) = ol01;
                    *reinterpret_cast<__half2*>(Ohb + (size_t)(row + 8) * ldc + col) = oh23;
                    *reinterpret_cast<__half2*>(Olb + (size_t)(row + 8) * ldc + col) = ol23;
                }
            }
        }
    } else if (npok[0]) {
        // ---- standard epilogue ----
        float* Cb = C + bz * sC;
        #pragma unroll
        for (int mt = 0; mt < MT; mt++) {
            const int row = m0 + wy * (MT * 16) + mt * 16 + quad;
            #pragma unroll
            for (int nt = 0; nt < 2 * NP; nt++) {
                const int col = n0 + wx * (NP * 16) + nt * 8 + tq * 2;
                if (col >= n_valid) continue;
                float b0 = bias ? bias[col] : 0.0f;
                float b1 = bias ? bias[col + 1] : 0.0f;
                float2 v0 = make_float2(acc[mt][nt][0] * alpha + b0,
                                        acc[mt][nt][1] * alpha + b1);
                float2 v1 = make_float2(acc[mt][nt][2] * alpha + b0,
                                        acc[mt][nt][3] * alpha + b1);
                *reinterpret_cast<float2*>(Cb + (size_t)row * ldc + col) = v0;
                *reinterpret_cast<float2*>(Cb + (size_t)(row + 8) * ldc + col) = v1;
            }
        }
    }
}

// ---------------- reduce per-tile partials -> 1/rowsum ----------------------
__global__ __launch_bounds__(256) void reduce_psum(
    const float* __restrict__ psum, float* __restrict__ rowinv)
{
    int i = blockIdx.x * blockDim.x + threadIdx.x;
    if (i >= NH * SEQ) return;
    const int h = i / SEQ, r = i % SEQ;
    float s = 0.0f;
    #pragma unroll
    for (int x = 0; x < 16; x++)
        s += psum[((size_t)h * 16 + x) * SEQ + r];
    rowinv[i] = 1.0f / s;
}

// ---------------- RoPE + fp16 per-head layouts --------------------------------
// Q,K: single limb [h][s][80]. V^T: two limbs [h][d][s] (rows>=80 unused).
__global__ __launch_bounds__(256) void rope_split_fp16(
    const float* __restrict__ qkv, const float* __restrict__ cosp,
    const float* __restrict__ sinp,
    __half* __restrict__ Qh, __half* __restrict__ Kh,
    __half* __restrict__ Vth, __half* __restrict__ Vtl)
{
    int idx = blockIdx.x * blockDim.x + threadIdx.x;
    if (idx >= SEQ * DIM) return;
    const int d = idx % HD;
    const int h = (idx / HD) % NH;
    const int s = idx / DIM;

    const float c = cosp[s * HD + d];
    const float sn = sinp[s * HD + d];
    const int d2 = (d < HD / 2) ? d + HD / 2 : d - HD / 2;
    const float sign = (d < HD / 2) ? -1.0f : 1.0f;

    const size_t rowbase = (size_t)s * QKV_N + h * HD;
    const size_t oqk = ((size_t)h * SEQ + s) * HD + d;
    const size_t ovt = ((size_t)h * HDV + d) * SEQ + s;

    const float qv = qkv[rowbase + d];
    const float q2 = qkv[rowbase + d2];
    Qh[oqk] = __float2half(fmaf(qv, c, sign * q2 * sn));

    const float kv = qkv[rowbase + DIM + d];
    const float k2 = qkv[rowbase + DIM + d2];
    Kh[oqk] = __float2half(fmaf(kv, c, sign * k2 * sn));

    split1h(qkv[rowbase + 2 * DIM + d], Vth[ovt], Vtl[ovt]);
}

// ---------------- launch -----------------------------------------------------
extern "C" void kernel_launch(void* const* d_in, const int* in_sizes, int n_in,
                              void* d_out, int out_size)
{
    const float* hidden = (const float*)d_in[0];
    const float* cosp   = (const float*)d_in[2];
    const float* sinp   = (const float*)d_in[3];
    const float* w_qkv  = (const float*)d_in[4];
    const float* b_qkv  = (const float*)d_in[5];
    const float* w_proj = (const float*)d_in[6];
    const float* b_proj = (const float*)d_in[7];
    float* out = (float*)d_out;

    float *qkv, *psum, *rowinv;
    cudaGetSymbolAddress((void**)&qkv, g_qkv);
    cudaGetSymbolAddress((void**)&psum, g_psum);
    cudaGetSymbolAddress((void**)&rowinv, g_rowinv);

    __half *hh, *hl, *wqh, *wph, *qh, *kh, *vth, *vtl, *ph, *oh, *ol;
    cudaGetSymbolAddress((void**)&hh, g_hid_h);
    cudaGetSymbolAddress((void**)&hl, g_hid_l);
    cudaGetSymbolAddress((void**)&wqh, g_wqkv_h);
    cudaGetSymbolAddress((void**)&wph, g_wproj_h);
    cudaGetSymbolAddress((void**)&qh, g_qh);
    cudaGetSymbolAddress((void**)&kh, g_kh);
    cudaGetSymbolAddress((void**)&vth, g_vth);
    cudaGetSymbolAddress((void**)&vtl, g_vtl);
    cudaGetSymbolAddress((void**)&ph, g_ph);
    cudaGetSymbolAddress((void**)&oh, g_oh);
    cudaGetSymbolAddress((void**)&ol, g_ol);

    const int SM21 = 3 * 3 * MM_TILE_B;   // (2,1): 3 tiles/stage
    const int SM11 = 3 * 2 * MM_TILE_B;   // (1,1): 2 tiles/stage
    const int SM12 = 3 * 3 * MM_TILE_B;   // (1,2): 3 tiles/stage
    cudaFuncSetAttribute(gemm_fp16<2, 1>,
                         cudaFuncAttributeMaxDynamicSharedMemorySize, SM21);
    cudaFuncSetAttribute(gemm_fp16<1, 1>,
                         cudaFuncAttributeMaxDynamicSharedMemorySize, SM11);
    cudaFuncSetAttribute(gemm_fp16<1, 2>,
                         cudaFuncAttributeMaxDynamicSharedMemorySize, SM12);

    // 0) prepare fp16 operands
    split_fp16<<<(SEQ * DIM + 255) / 256, 256>>>(hidden, hh, hl, SEQ * DIM);
    round_fp16<<<(QKV_N * DIM + 255) / 256, 256>>>(w_qkv, wqh, QKV_N * DIM);
    round_fp16<<<(DIM * DIM + 255) / 256, 256>>>(w_proj, wph, DIM * DIM);

    // 1) QKV = hidden @ w_qkv^T + b_qkv   (A two-limb, B one-limb, 4x2 warps)
    {
        dim3 grid(QKV_N / 128, SEQ / 128, 1);
        gemm_fp16<2, 1><<<grid, 256, SM21>>>(
            hh, hl, wqh, b_qkv, qkv,
            DIM, 0, 0, 0, QKV_N, 1.0f, QKV_N,
            nullptr, nullptr, nullptr, nullptr, nullptr);
    }
    // 2) RoPE + per-head fp16 layouts (K=80 unpadded)
    rope_split_fp16<<<(SEQ * DIM + 255) / 256, 256>>>(qkv, cosp, sinp,
                                                      qh, kh, vth, vtl);

    // 3) fused scores + exp: Ph = fp16(exp(scale*Q@K^T)*PSCALE), row partials
    //    single-limb both sides
    {
        dim3 grid(SEQ / 128, SEQ / 128, NH);
        gemm_fp16<1, 1><<<grid, 256, SM11>>>(
            qh, nullptr, kh, nullptr, nullptr,
            HD, (size_t)SEQ * HD, (size_t)SEQ * HD,
            (size_t)SEQ * SEQ, SEQ, ATTN_SCALE, SEQ,
            ph, psum, nullptr, nullptr, nullptr);
    }
    // 4) rowsum partials -> 1/rowsum
    reduce_psum<<<(NH * SEQ + 255) / 256, 256>>>(psum, rowinv);

    // 5) O(h/l) = split((Ph @ (Vh+Vl)) * rowinv)   (A one-limb, B two-limb)
    {
        dim3 grid(1, SEQ / 128, NH);
        gemm_fp16<1, 2><<<grid, 256, SM12>>>(
            ph, vtl, vth, nullptr, nullptr,
            SEQ, (size_t)SEQ * SEQ, (size_t)HDV * SEQ,
            (size_t)HD, DIM, 1.0f, HD,
            nullptr, nullptr, rowinv, oh, ol);
    }
    // 6) out = O @ w_proj^T + b_proj   (A two-limb, B one-limb, 4x2 warps)
    {
        dim3 grid(DIM / 128, SEQ / 128, 1);
        gemm_fp16<2, 1><<<grid, 256, SM21>>>(
            oh, ol, wph, b_proj, out,
            DIM, 0, 0, 0, DIM, 1.0f, DIM,
            nullptr, nullptr, nullptr, nullptr, nullptr);
    }
}

// round 15
// speedup vs baseline: 1.9217x; 1.2143x over previous
#include <cuda_runtime.h>
#include <cuda_fp16.h>
#include <math.h>
#include <cstdint>

#define SEQ 2048
#define NH  16
#define HD  80
#define HDV 128             // padded head dim for V^T (one 128-col N tile)
#define DIM 1280            // NH*HD
#define QKV_N 3840          // 3*DIM
#define ATTN_SCALE 0.11180339887498949f   // 80^-0.5
#define PSCALE 0.0625f      // 2^-4 headroom for fp16 exp storage (cancels in rowinv)

// ---------------- scratch (device globals; no allocations allowed) ----------
__device__ float g_qkv[SEQ * QKV_N];          // 31.5 MB
__device__ float g_psum[NH * 16 * SEQ];       // per-(head, n-tile) row partial sums
__device__ float g_rowinv[NH * SEQ];          // 1 / rowsum (of scaled exp)

__device__ __half g_hid_h[SEQ * DIM];         // hidden: single fp16 limb
__device__ __half g_wqkv_h[QKV_N * DIM];      // weights: single fp16 limb
__device__ __half g_wproj_h[DIM * DIM];
__device__ __half g_qh[NH * SEQ * HD];        // Q: single limb
__device__ __half g_kh[NH * SEQ * HD];        // K: single limb
__device__ __half g_vth[NH * HDV * SEQ];      // V^T: two limbs (rows >= HD unused)
__device__ __half g_vtl[NH * HDV * SEQ];
__device__ __half g_ph[(size_t)NH * SEQ * SEQ];  // 64 MB (scaled unnormalized expS)
__device__ __half g_oh[SEQ * DIM];            // O: single limb

// ================= helpers ====================================================
__device__ __forceinline__ uint32_t smem_u32(const void* p) {
    uint32_t a;
    asm("{ .reg .u64 t; cvta.to.shared.u64 t, %1; cvt.u32.u64 %0, t; }" : "=r"(a) : "l"(p));
    return a;
}
#define CP_ASYNC16(dst, src) \
    asm volatile("cp.async.cg.shared.global [%0], [%1], 16;" :: "r"(dst), "l"(src) : "memory")
#define CP_COMMIT() asm volatile("cp.async.commit_group;" ::: "memory")
#define CP_WAIT1()  asm volatile("cp.async.wait_group 1;" ::: "memory")

#define LDSM_X4(r0, r1, r2, r3, addr) \
    asm volatile("ldmatrix.sync.aligned.m8n8.x4.shared.b16 {%0,%1,%2,%3}, [%4];" \
        : "=r"(r0), "=r"(r1), "=r"(r2), "=r"(r3) : "r"(addr))

#define MMA16816(c, a, b0, b1) \
    asm volatile("mma.sync.aligned.m16n8k16.row.col.f32.f16.f16.f32 " \
        "{%0,%1,%2,%3}, {%4,%5,%6,%7}, {%8,%9}, {%0,%1,%2,%3};" \
        : "+f"((c)[0]), "+f"((c)[1]), "+f"((c)[2]), "+f"((c)[3]) \
        : "r"((a)[0]), "r"((a)[1]), "r"((a)[2]), "r"((a)[3]), "r"(b0), "r"(b1))

__device__ __forceinline__ void split1h(float v, __half& h, __half& l) {
    h = __float2half(v);
    l = __float2half(v - __half2float(h));
}

// ================= fp32 -> fp16 prep ==========================================
__global__ __launch_bounds__(256) void round_fp16(
    const float* __restrict__ x, __half* __restrict__ hi, int n)
{
    int i = blockIdx.x * blockDim.x + threadIdx.x;
    if (i >= n) return;
    hi[i] = __float2half(x[i]);
}

// ================= mma.sync fp16 limb GEMM (3-stage pipeline) ================
// C = alpha * A(MxK) @ B(NxK)^T (+bias), limb product with ALIMBS/BLIMBS in {1,2}:
//   (2,1): (A0+X1A)*B0   (1,2): A0*(B0+X1B)   (1,1): A0*B0
// X1 is the lo-limb pointer (A side if ALIMBS==2, B side if BLIMBS==2).
// K%16==0 (tail = half chunk). Epilogues:
//   psum != null : e = expf(alpha*acc)*PSCALE -> Ph (fp16), row partials -> psum
//   Oh   != null : fp16(acc*alpha*rowinv[row]) -> Oh (single limb)
//   else         : C = alpha*acc + bias, cols < n_valid
#define MM_TILE_B 10240        // 128 rows * 80 bytes (40 halves, padded from 32)

template<int ALIMBS, int BLIMBS>
__global__ __launch_bounds__(256, 2) void gemm_fp16(
    const __half* __restrict__ A0, const __half* __restrict__ X1,
    const __half* __restrict__ B0,
    const float* __restrict__ bias, float* __restrict__ C,
    int K, size_t sA, size_t sB, size_t sC, int ldc, float alpha, int n_valid,
    __half* __restrict__ Ph, float* __restrict__ psum,
    const float* __restrict__ rowinv, __half* __restrict__ Oh)
{
    constexpr int NWY = (ALIMBS == 2) ? 4 : 2;
    constexpr int NWX = 8 / NWY;
    constexpr int MT  = 128 / (NWY * 16);     // 2 or 4
    constexpr int NP  = 128 / (NWX * 16);     // 4 or 2
    constexpr int NTILES = ALIMBS + BLIMBS;
    constexpr int BUF_B = NTILES * MM_TILE_B;

    extern __shared__ char sm[];
    const uint32_t sbase = smem_u32(sm);
    const int tid = threadIdx.x;
    const int lane = tid & 31;
    const int wid = tid >> 5;
    const int wy = wid / NWX;
    const int wx = wid % NWX;
    const int m0 = blockIdx.y * 128;
    const int n0 = blockIdx.x * 128;
    const int bz = blockIdx.z;
    const int NC = (K + 31) >> 5;     // chunks; last may be half (16)

    bool npok[NP];
    #pragma unroll
    for (int np = 0; np < NP; np++)
        npok[np] = (n0 + wx * (NP * 16) + np * 16) < n_valid;

    const __half* srcs[NTILES];
    int rbases[NTILES];
    srcs[0] = A0 + bz * sA; rbases[0] = m0;
    if constexpr (ALIMBS == 2) { srcs[1] = X1 + bz * sA; rbases[1] = m0; }
    srcs[ALIMBS] = B0 + bz * sB; rbases[ALIMBS] = n0;
    if constexpr (BLIMBS == 2) { srcs[ALIMBS + 1] = X1 + bz * sB; rbases[ALIMBS + 1] = n0; }

    float acc[MT][2 * NP][4];
    #pragma unroll
    for (int i = 0; i < MT; i++)
        #pragma unroll
        for (int j = 0; j < 2 * NP; j++)
            #pragma unroll
            for (int k = 0; k < 4; k++) acc[i][j][k] = 0.0f;

    auto load_chunk = [&](int c, int b) {
        const int k0 = c << 5;
        const bool hc = (k0 + 32 > K);
        #pragma unroll
        for (int t = 0; t < NTILES; t++) {
            const __half* src = srcs[t];
            const int rbase = rbases[t];
            const uint32_t tb = sbase + b * BUF_B + t * MM_TILE_B;
            if (!hc) {
                #pragma unroll
                for (int i = 0; i < 2; i++) {
                    const int g = tid + i * 256;       // 0..511
                    const int row = g >> 2, q = g & 3;
                    const uint32_t dst = tb + row * 80 + q * 16;
                    const void* s = (const void*)(src + (size_t)(rbase + row) * K + k0 + q * 8);
                    CP_ASYNC16(dst, s);
                }
            } else {
                const int row = tid >> 1, q = tid & 1;  // 16 cols only
                const uint32_t dst = tb + row * 80 + q * 16;
                const void* s = (const void*)(src + (size_t)(rbase + row) * K + k0 + q * 8);
                CP_ASYNC16(dst, s);
            }
        }
    };

    // ---- prologue: stage chunks 0 and 1 ----
    load_chunk(0, 0);
    CP_COMMIT();
    if (NC > 1) load_chunk(1, 1);
    CP_COMMIT();

    int bc = 0, lb = 2;
    for (int c = 0; c < NC; c++) {
        CP_WAIT1();
        __syncthreads();

        if (c + 2 < NC) load_chunk(c + 2, lb);
        CP_COMMIT();

        const bool hc = ((c << 5) + 32 > K);
        const uint32_t bufb = sbase + bc * BUF_B;
        if (npok[0]) {
            #pragma unroll
            for (int ks = 0; ks < 2; ks++) {
                if (ks == 1 && hc) break;
                const int fcol = ks * 16 + (lane >> 4) * 8;
                uint32_t b0f[NP][4], b1f[NP][4];
                #pragma unroll
                for (int np = 0; np < NP; np++) {
                    if (!npok[np]) continue;
                    const int r = wx * (NP * 16) + np * 16 + (lane & 15);
                    const uint32_t bd = bufb + ALIMBS * MM_TILE_B + r * 80 + fcol * 2;
                    LDSM_X4(b0f[np][0], b0f[np][1], b0f[np][2], b0f[np][3], bd);
                    if constexpr (BLIMBS == 2) {
                        LDSM_X4(b1f[np][0], b1f[np][1], b1f[np][2], b1f[np][3],
                                bd + MM_TILE_B);
                    }
                }
                #pragma unroll
                for (int mt = 0; mt < MT; mt++) {
                    const int r = wy * (MT * 16) + mt * 16 + (lane & 15);
                    const uint32_t ad = bufb + r * 80 + fcol * 2;
                    uint32_t a0f[4], a1f[4];
                    LDSM_X4(a0f[0], a0f[1], a0f[2], a0f[3], ad);
                    if constexpr (ALIMBS == 2) {
                        LDSM_X4(a1f[0], a1f[1], a1f[2], a1f[3], ad + MM_TILE_B);
                    }
                    #pragma unroll
                    for (int np = 0; np < NP; np++) {
                        if (!npok[np]) continue;
                        MMA16816(acc[mt][np * 2],     a0f, b0f[np][0], b0f[np][2]);
                        MMA16816(acc[mt][np * 2 + 1], a0f, b0f[np][1], b0f[np][3]);
                    }
                    if constexpr (ALIMBS == 2) {
                        #pragma unroll
                        for (int np = 0; np < NP; np++) {
                            if (!npok[np]) continue;
                            MMA16816(acc[mt][np * 2],     a1f, b0f[np][0], b0f[np][2]);
                            MMA16816(acc[mt][np * 2 + 1], a1f, b0f[np][1], b0f[np][3]);
                        }
                    } else if constexpr (BLIMBS == 2) {
                        #pragma unroll
                        for (int np = 0; np < NP; np++) {
                            if (!npok[np]) continue;
                            MMA16816(acc[mt][np * 2],     a0f, b1f[np][0], b1f[np][2]);
                            MMA16816(acc[mt][np * 2 + 1], a0f, b1f[np][1], b1f[np][3]);
                        }
                    }
                }
            }
        }
        bc = (bc == 2) ? 0 : bc + 1;
        lb = (lb == 2) ? 0 : lb + 1;
    }
    __syncthreads();                  // protect epilogue smem reuse

    const int quad = lane >> 2, tq = lane & 3;

    if (psum) {
        // ---- exp epilogue (fused unnormalized softmax, single-limb fp16 P) ----
        const int Mtot = gridDim.y * 128;
        __half* Phb = Ph + (size_t)bz * sC;
        float rs[MT][2];
        #pragma unroll
        for (int mt = 0; mt < MT; mt++) { rs[mt][0] = 0.0f; rs[mt][1] = 0.0f; }

        #pragma unroll
        for (int mt = 0; mt < MT; mt++) {
            const int row = m0 + wy * (MT * 16) + mt * 16 + quad;
            #pragma unroll
            for (int nt = 0; nt < 2 * NP; nt++) {
                const int col = n0 + wx * (NP * 16) + nt * 8 + tq * 2;
                float e0 = __expf(acc[mt][nt][0] * alpha) * PSCALE;
                float e1 = __expf(acc[mt][nt][1] * alpha) * PSCALE;
                float e2 = __expf(acc[mt][nt][2] * alpha) * PSCALE;
                float e3 = __expf(acc[mt][nt][3] * alpha) * PSCALE;
                rs[mt][0] += e0 + e1;
                rs[mt][1] += e2 + e3;
                __half2 p01 = {__float2half(e0), __float2half(e1)};
                __half2 p23 = {__float2half(e2), __float2half(e3)};
                *reinterpret_cast<__half2*>(Phb + (size_t)row * ldc + col) = p01;
                *reinterpret_cast<__half2*>(Phb + (size_t)(row + 8) * ldc + col) = p23;
            }
            #pragma unroll
            for (int j = 0; j < 2; j++) {
                rs[mt][j] += __shfl_xor_sync(0xffffffff, rs[mt][j], 1);
                rs[mt][j] += __shfl_xor_sync(0xffffffff, rs[mt][j], 2);
            }
        }
        float* red = reinterpret_cast<float*>(sm);
        if (tq == 0) {
            #pragma unroll
            for (int mt = 0; mt < MT; mt++) {
                red[(wy * (MT * 16) + mt * 16 + quad) * NWX + wx] = rs[mt][0];
                red[(wy * (MT * 16) + mt * 16 + quad + 8) * NWX + wx] = rs[mt][1];
            }
        }
        __syncthreads();
        if (tid < 128) {
            float s = 0.0f;
            #pragma unroll
            for (int x = 0; x < NWX; x++) s += red[tid * NWX + x];
            psum[((size_t)bz * gridDim.x + blockIdx.x) * Mtot + m0 + tid] = s;
        }
    } else if (Oh) {
        // ---- normalize + fp16 single-limb epilogue (PV output) ----
        if (npok[0]) {
            const float* rinv = rowinv + (size_t)bz * (gridDim.y * 128);
            __half* Ohb = Oh + (size_t)bz * sC;
            #pragma unroll
            for (int mt = 0; mt < MT; mt++) {
                const int row = m0 + wy * (MT * 16) + mt * 16 + quad;
                const float s0 = rinv[row];
                const float s1 = rinv[row + 8];
                #pragma unroll
                for (int nt = 0; nt < 2 * NP; nt++) {
                    const int col = n0 + wx * (NP * 16) + nt * 8 + tq * 2;
                    if (col >= n_valid) continue;
                    __half2 o01 = {__float2half(acc[mt][nt][0] * alpha * s0),
                                   __float2half(acc[mt][nt][1] * alpha * s0)};
                    __half2 o23 = {__float2half(acc[mt][nt][2] * alpha * s1),
                                   __float2half(acc[mt][nt][3] * alpha * s1)};
                    *reinterpret_cast<__half2*>(Ohb + (size_t)row * ldc + col) = o01;
                    *reinterpret_cast<__half2*>(Ohb + (size_t)(row + 8) * ldc + col) = o23;
                }
            }
        }
    } else if (npok[0]) {
        // ---- standard epilogue ----
        float* Cb = C + bz * sC;
        #pragma unroll
        for (int mt = 0; mt < MT; mt++) {
            const int row = m0 + wy * (MT * 16) + mt * 16 + quad;
            #pragma unroll
            for (int nt = 0; nt < 2 * NP; nt++) {
                const int col = n0 + wx * (NP * 16) + nt * 8 + tq * 2;
                if (col >= n_valid) continue;
                float b0 = bias ? bias[col] : 0.0f;
                float b1 = bias ? bias[col + 1] : 0.0f;
                float2 v0 = make_float2(acc[mt][nt][0] * alpha + b0,
                                        acc[mt][nt][1] * alpha + b1);
                float2 v1 = make_float2(acc[mt][nt][2] * alpha + b0,
                                        acc[mt][nt][3] * alpha + b1);
                *reinterpret_cast<float2*>(Cb + (size_t)row * ldc + col) = v0;
                *reinterpret_cast<float2*>(Cb + (size_t)(row + 8) * ldc + col) = v1;
            }
        }
    }
}

// ---------------- reduce per-tile partials -> 1/rowsum ----------------------
__global__ __launch_bounds__(256) void reduce_psum(
    const float* __restrict__ psum, float* __restrict__ rowinv)
{
    int i = blockIdx.x * blockDim.x + threadIdx.x;
    if (i >= NH * SEQ) return;
    const int h = i / SEQ, r = i % SEQ;
    float s = 0.0f;
    #pragma unroll
    for (int x = 0; x < 16; x++)
        s += psum[((size_t)h * 16 + x) * SEQ + r];
    rowinv[i] = 1.0f / s;
}

// ---------------- RoPE + fp16 per-head layouts --------------------------------
// Q,K: single limb [h][s][80]. V^T: two limbs [h][d][s] (rows>=80 unused).
__global__ __launch_bounds__(256) void rope_split_fp16(
    const float* __restrict__ qkv, const float* __restrict__ cosp,
    const float* __restrict__ sinp,
    __half* __restrict__ Qh, __half* __restrict__ Kh,
    __half* __restrict__ Vth, __half* __restrict__ Vtl)
{
    int idx = blockIdx.x * blockDim.x + threadIdx.x;
    if (idx >= SEQ * DIM) return;
    const int d = idx % HD;
    const int h = (idx / HD) % NH;
    const int s = idx / DIM;

    const float c = cosp[s * HD + d];
    const float sn = sinp[s * HD + d];
    const int d2 = (d < HD / 2) ? d + HD / 2 : d - HD / 2;
    const float sign = (d < HD / 2) ? -1.0f : 1.0f;

    const size_t rowbase = (size_t)s * QKV_N + h * HD;
    const size_t oqk = ((size_t)h * SEQ + s) * HD + d;
    const size_t ovt = ((size_t)h * HDV + d) * SEQ + s;

    const float qv = qkv[rowbase + d];
    const float q2 = qkv[rowbase + d2];
    Qh[oqk] = __float2half(fmaf(qv, c, sign * q2 * sn));

    const float kv = qkv[rowbase + DIM + d];
    const float k2 = qkv[rowbase + DIM + d2];
    Kh[oqk] = __float2half(fmaf(kv, c, sign * k2 * sn));

    split1h(qkv[rowbase + 2 * DIM + d], Vth[ovt], Vtl[ovt]);
}

// ---------------- launch -----------------------------------------------------
extern "C" void kernel_launch(void* const* d_in, const int* in_sizes, int n_in,
                              void* d_out, int out_size)
{
    const float* hidden = (const float*)d_in[0];
    const float* cosp   = (const float*)d_in[2];
    const float* sinp   = (const float*)d_in[3];
    const float* w_qkv  = (const float*)d_in[4];
    const float* b_qkv  = (const float*)d_in[5];
    const float* w_proj = (const float*)d_in[6];
    const float* b_proj = (const float*)d_in[7];
    float* out = (float*)d_out;

    float *qkv, *psum, *rowinv;
    cudaGetSymbolAddress((void**)&qkv, g_qkv);
    cudaGetSymbolAddress((void**)&psum, g_psum);
    cudaGetSymbolAddress((void**)&rowinv, g_rowinv);

    __half *hh, *wqh, *wph, *qh, *kh, *vth, *vtl, *ph, *oh;
    cudaGetSymbolAddress((void**)&hh, g_hid_h);
    cudaGetSymbolAddress((void**)&wqh, g_wqkv_h);
    cudaGetSymbolAddress((void**)&wph, g_wproj_h);
    cudaGetSymbolAddress((void**)&qh, g_qh);
    cudaGetSymbolAddress((void**)&kh, g_kh);
    cudaGetSymbolAddress((void**)&vth, g_vth);
    cudaGetSymbolAddress((void**)&vtl, g_vtl);
    cudaGetSymbolAddress((void**)&ph, g_ph);
    cudaGetSymbolAddress((void**)&oh, g_oh);

    const int SM11 = 3 * 2 * MM_TILE_B;   // (1,1): 2 tiles/stage
    const int SM12 = 3 * 3 * MM_TILE_B;   // (1,2): 3 tiles/stage
    cudaFuncSetAttribute(gemm_fp16<1, 1>,
                         cudaFuncAttributeMaxDynamicSharedMemorySize, SM11);
    cudaFuncSetAttribute(gemm_fp16<1, 2>,
                         cudaFuncAttributeMaxDynamicSharedMemorySize, SM12);

    // 0) prepare fp16 operands (all single-limb except V)
    round_fp16<<<(SEQ * DIM + 255) / 256, 256>>>(hidden, hh, SEQ * DIM);
    round_fp16<<<(QKV_N * DIM + 255) / 256, 256>>>(w_qkv, wqh, QKV_N * DIM);
    round_fp16<<<(DIM * DIM + 255) / 256, 256>>>(w_proj, wph, DIM * DIM);

    // 1) QKV = hidden @ w_qkv^T + b_qkv   (1x1 limb)
    {
        dim3 grid(QKV_N / 128, SEQ / 128, 1);
        gemm_fp16<1, 1><<<grid, 256, SM11>>>(
            hh, nullptr, wqh, b_qkv, qkv,
            DIM, 0, 0, 0, QKV_N, 1.0f, QKV_N,
            nullptr, nullptr, nullptr, nullptr);
    }
    // 2) RoPE + per-head fp16 layouts (K=80 unpadded)
    rope_split_fp16<<<(SEQ * DIM + 255) / 256, 256>>>(qkv, cosp, sinp,
                                                      qh, kh, vth, vtl);

    // 3) fused scores + exp: Ph = fp16(exp(scale*Q@K^T)*PSCALE), row partials
    {
        dim3 grid(SEQ / 128, SEQ / 128, NH);
        gemm_fp16<1, 1><<<grid, 256, SM11>>>(
            qh, nullptr, kh, nullptr, nullptr,
            HD, (size_t)SEQ * HD, (size_t)SEQ * HD,
            (size_t)SEQ * SEQ, SEQ, ATTN_SCALE, SEQ,
            ph, psum, nullptr, nullptr);
    }
    // 4) rowsum partials -> 1/rowsum
    reduce_psum<<<(NH * SEQ + 255) / 256, 256>>>(psum, rowinv);

    // 5) Oh = fp16((Ph @ (Vh+Vl)) * rowinv)   (A one-limb, B two-limb)
    {
        dim3 grid(1, SEQ / 128, NH);
        gemm_fp16<1, 2><<<grid, 256, SM12>>>(
            ph, vtl, vth, nullptr, nullptr,
            SEQ, (size_t)SEQ * SEQ, (size_t)HDV * SEQ,
            (size_t)HD, DIM, 1.0f, HD,
            nullptr, nullptr, rowinv, oh);
    }
    // 6) out = O @ w_proj^T + b_proj   (1x1 limb)
    {
        dim3 grid(DIM / 128, SEQ / 128, 1);
        gemm_fp16<1, 1><<<grid, 256, SM11>>>(
            oh, nullptr, wph, b_proj, out,
            DIM, 0, 0, 0, DIM, 1.0f, DIM,
            nullptr, nullptr, nullptr, nullptr);
    }
}

// round 16
// speedup vs baseline: 2.2296x; 1.1603x over previous
#include <cuda_runtime.h>
#include <cuda_fp16.h>
#include <math.h>
#include <cstdint>

#define SEQ 2048
#define NH  16
#define HD  80
#define HDV 128             // padded head dim for V^T (one 128-col N tile)
#define DIM 1280            // NH*HD
#define QKV_N 3840          // 3*DIM
#define ATTN_SCALE 0.11180339887498949f   // 80^-0.5
#define PSCALE 0.0625f      // 2^-4 headroom for fp16 exp storage (cancels in rowinv)

// ---------------- scratch (device globals; no allocations allowed) ----------
__device__ float g_qkv[SEQ * QKV_N];          // 31.5 MB
__device__ float g_psum[NH * 16 * SEQ];       // per-(head, n-tile) row partial sums
__device__ float g_rowinv[NH * SEQ];          // 1 / rowsum (of scaled exp)

__device__ __half g_hid_h[SEQ * DIM];         // hidden: single fp16 limb
__device__ __half g_wqkv_h[QKV_N * DIM];      // weights: single fp16 limb
__device__ __half g_wproj_h[DIM * DIM];
__device__ __half g_qh[NH * SEQ * HD];        // Q: single limb
__device__ __half g_kh[NH * SEQ * HD];        // K: single limb
__device__ __half g_vth[NH * HDV * SEQ];      // V^T: single limb (rows >= HD unused)
__device__ __half g_ph[(size_t)NH * SEQ * SEQ];  // 64 MB (scaled unnormalized expS)
__device__ __half g_oh[SEQ * DIM];            // O: single limb

// ================= helpers ====================================================
__device__ __forceinline__ uint32_t smem_u32(const void* p) {
    uint32_t a;
    asm("{ .reg .u64 t; cvta.to.shared.u64 t, %1; cvt.u32.u64 %0, t; }" : "=r"(a) : "l"(p));
    return a;
}
#define CP_ASYNC16(dst, src) \
    asm volatile("cp.async.cg.shared.global [%0], [%1], 16;" :: "r"(dst), "l"(src) : "memory")
#define CP_COMMIT() asm volatile("cp.async.commit_group;" ::: "memory")
#define CP_WAIT1()  asm volatile("cp.async.wait_group 1;" ::: "memory")

#define LDSM_X4(r0, r1, r2, r3, addr) \
    asm volatile("ldmatrix.sync.aligned.m8n8.x4.shared.b16 {%0,%1,%2,%3}, [%4];" \
        : "=r"(r0), "=r"(r1), "=r"(r2), "=r"(r3) : "r"(addr))

#define MMA16816(c, a, b0, b1) \
    asm volatile("mma.sync.aligned.m16n8k16.row.col.f32.f16.f16.f32 " \
        "{%0,%1,%2,%3}, {%4,%5,%6,%7}, {%8,%9}, {%0,%1,%2,%3};" \
        : "+f"((c)[0]), "+f"((c)[1]), "+f"((c)[2]), "+f"((c)[3]) \
        : "r"((a)[0]), "r"((a)[1]), "r"((a)[2]), "r"((a)[3]), "r"(b0), "r"(b1))

// ================= fp32 -> fp16 prep ==========================================
__global__ __launch_bounds__(256) void round_fp16(
    const float* __restrict__ x, __half* __restrict__ hi, int n)
{
    int i = blockIdx.x * blockDim.x + threadIdx.x;
    if (i >= n) return;
    hi[i] = __float2half(x[i]);
}

// ================= mma.sync fp16 limb GEMM (3-stage pipeline) ================
// C = alpha * A(MxK) @ B(NxK)^T (+bias), ALIMBS/BLIMBS in {1,2}:
//   (2,1): (A0+X1A)*B0   (1,2): A0*(B0+X1B)   (1,1): A0*B0
// K%16==0 (tail = half chunk, loaded via direct addressing). Epilogues:
//   psum != null : e = expf(alpha*acc)*PSCALE -> Ph (fp16), row partials -> psum
//   Oh   != null : fp16(acc*alpha*rowinv[row]) -> Oh (single limb)
//   else         : C = alpha*acc + bias, cols < n_valid
// Full-chunk loads use per-thread incremental global pointers (+32 halves/chunk)
// and precomputed smem offsets to keep per-chunk ALU work minimal.
#define MM_TILE_B 10240        // 128 rows * 80 bytes (40 halves, padded from 32)

template<int ALIMBS, int BLIMBS>
__global__ __launch_bounds__(256, 2) void gemm_fp16(
    const __half* __restrict__ A0, const __half* __restrict__ X1,
    const __half* __restrict__ B0,
    const float* __restrict__ bias, float* __restrict__ C,
    int K, size_t sA, size_t sB, size_t sC, int ldc, float alpha, int n_valid,
    __half* __restrict__ Ph, float* __restrict__ psum,
    const float* __restrict__ rowinv, __half* __restrict__ Oh)
{
    constexpr int NWY = (ALIMBS == 2) ? 4 : 2;
    constexpr int NWX = 8 / NWY;
    constexpr int MT  = 128 / (NWY * 16);     // 2 or 4
    constexpr int NP  = 128 / (NWX * 16);     // 4 or 2
    constexpr int NTILES = ALIMBS + BLIMBS;
    constexpr int BUF_B = NTILES * MM_TILE_B;

    extern __shared__ char sm[];
    const uint32_t sbase = smem_u32(sm);
    const int tid = threadIdx.x;
    const int lane = tid & 31;
    const int wid = tid >> 5;
    const int wy = wid / NWX;
    const int wx = wid % NWX;
    const int m0 = blockIdx.y * 128;
    const int n0 = blockIdx.x * 128;
    const int bz = blockIdx.z;
    const int NC = (K + 31) >> 5;     // chunks; last may be half (16)

    bool npok[NP];
    #pragma unroll
    for (int np = 0; np < NP; np++)
        npok[np] = (n0 + wx * (NP * 16) + np * 16) < n_valid;

    const __half* srcs[NTILES];
    int rbases[NTILES];
    srcs[0] = A0 + bz * sA; rbases[0] = m0;
    if constexpr (ALIMBS == 2) { srcs[1] = X1 + bz * sA; rbases[1] = m0; }
    srcs[ALIMBS] = B0 + bz * sB; rbases[ALIMBS] = n0;
    if constexpr (BLIMBS == 2) { srcs[ALIMBS + 1] = X1 + bz * sB; rbases[ALIMBS + 1] = n0; }

    // ---- loader state: per-thread incremental global pointers ----
    const int row0 = tid >> 2,        q0 = tid & 3;
    const int row1 = (tid + 256) >> 2, q1 = (tid + 256) & 3;
    const __half* gp[NTILES][2];
    uint32_t doff[NTILES][2];
    #pragma unroll
    for (int t = 0; t < NTILES; t++) {
        gp[t][0] = srcs[t] + (size_t)(rbases[t] + row0) * K + q0 * 8;
        gp[t][1] = srcs[t] + (size_t)(rbases[t] + row1) * K + q1 * 8;
        doff[t][0] = (uint32_t)(t * MM_TILE_B + row0 * 80 + q0 * 16);
        doff[t][1] = (uint32_t)(t * MM_TILE_B + row1 * 80 + q1 * 16);
    }

    float acc[MT][2 * NP][4];
    #pragma unroll
    for (int i = 0; i < MT; i++)
        #pragma unroll
        for (int j = 0; j < 2 * NP; j++)
            #pragma unroll
            for (int k = 0; k < 4; k++) acc[i][j][k] = 0.0f;

    // full chunk: incremental pointers; half chunk (tail): direct addressing
    auto load_full = [&](int b) {
        const uint32_t base = sbase + b * BUF_B;
        #pragma unroll
        for (int t = 0; t < NTILES; t++) {
            CP_ASYNC16(base + doff[t][0], (const void*)gp[t][0]);
            CP_ASYNC16(base + doff[t][1], (const void*)gp[t][1]);
            gp[t][0] += 32;
            gp[t][1] += 32;
        }
    };
    auto load_half = [&](int c, int b) {
        const int k0 = c << 5;
        const int row = tid >> 1, q = tid & 1;
        #pragma unroll
        for (int t = 0; t < NTILES; t++) {
            const uint32_t dst = sbase + b * BUF_B + t * MM_TILE_B + row * 80 + q * 16;
            const void* s = (const void*)(srcs[t] + (size_t)(rbases[t] + row) * K + k0 + q * 8);
            CP_ASYNC16(dst, s);
        }
    };
    auto load_chunk = [&](int c, int b) {
        if ((c << 5) + 32 > K) load_half(c, b);
        else load_full(b);
    };

    // ---- prologue: stage chunks 0 and 1 ----
    load_chunk(0, 0);
    CP_COMMIT();
    if (NC > 1) load_chunk(1, 1);
    CP_COMMIT();

    int bc = 0, lb = 2;
    for (int c = 0; c < NC; c++) {
        CP_WAIT1();
        __syncthreads();

        if (c + 2 < NC) load_chunk(c + 2, lb);
        CP_COMMIT();

        const bool hc = ((c << 5) + 32 > K);
        const uint32_t bufb = sbase + bc * BUF_B;
        if (npok[0]) {
            #pragma unroll
            for (int ks = 0; ks < 2; ks++) {
                if (ks == 1 && hc) break;
                const int fcol = ks * 16 + (lane >> 4) * 8;
                uint32_t b0f[NP][4], b1f[NP][4];
                #pragma unroll
                for (int np = 0; np < NP; np++) {
                    if (!npok[np]) continue;
                    const int r = wx * (NP * 16) + np * 16 + (lane & 15);
                    const uint32_t bd = bufb + ALIMBS * MM_TILE_B + r * 80 + fcol * 2;
                    LDSM_X4(b0f[np][0], b0f[np][1], b0f[np][2], b0f[np][3], bd);
                    if constexpr (BLIMBS == 2) {
                        LDSM_X4(b1f[np][0], b1f[np][1], b1f[np][2], b1f[np][3],
                                bd + MM_TILE_B);
                    }
                }
                #pragma unroll
                for (int mt = 0; mt < MT; mt++) {
                    const int r = wy * (MT * 16) + mt * 16 + (lane & 15);
                    const uint32_t ad = bufb + r * 80 + fcol * 2;
                    uint32_t a0f[4], a1f[4];
                    LDSM_X4(a0f[0], a0f[1], a0f[2], a0f[3], ad);
                    if constexpr (ALIMBS == 2) {
                        LDSM_X4(a1f[0], a1f[1], a1f[2], a1f[3], ad + MM_TILE_B);
                    }
                    #pragma unroll
                    for (int np = 0; np < NP; np++) {
                        if (!npok[np]) continue;
                        MMA16816(acc[mt][np * 2],     a0f, b0f[np][0], b0f[np][2]);
                        MMA16816(acc[mt][np * 2 + 1], a0f, b0f[np][1], b0f[np][3]);
                    }
                    if constexpr (ALIMBS == 2) {
                        #pragma unroll
                        for (int np = 0; np < NP; np++) {
                            if (!npok[np]) continue;
                            MMA16816(acc[mt][np * 2],     a1f, b0f[np][0], b0f[np][2]);
                            MMA16816(acc[mt][np * 2 + 1], a1f, b0f[np][1], b0f[np][3]);
                        }
                    } else if constexpr (BLIMBS == 2) {
                        #pragma unroll
                        for (int np = 0; np < NP; np++) {
                            if (!npok[np]) continue;
                            MMA16816(acc[mt][np * 2],     a0f, b1f[np][0], b1f[np][2]);
                            MMA16816(acc[mt][np * 2 + 1], a0f, b1f[np][1], b1f[np][3]);
                        }
                    }
                }
            }
        }
        bc = (bc == 2) ? 0 : bc + 1;
        lb = (lb == 2) ? 0 : lb + 1;
    }
    __syncthreads();                  // protect epilogue smem reuse

    const int quad = lane >> 2, tq = lane & 3;

    if (psum) {
        // ---- exp epilogue (fused unnormalized softmax, single-limb fp16 P) ----
        const int Mtot = gridDim.y * 128;
        __half* Phb = Ph + (size_t)bz * sC;
        float rs[MT][2];
        #pragma unroll
        for (int mt = 0; mt < MT; mt++) { rs[mt][0] = 0.0f; rs[mt][1] = 0.0f; }

        #pragma unroll
        for (int mt = 0; mt < MT; mt++) {
            const int row = m0 + wy * (MT * 16) + mt * 16 + quad;
            #pragma unroll
            for (int nt = 0; nt < 2 * NP; nt++) {
                const int col = n0 + wx * (NP * 16) + nt * 8 + tq * 2;
                float e0 = __expf(acc[mt][nt][0] * alpha) * PSCALE;
                float e1 = __expf(acc[mt][nt][1] * alpha) * PSCALE;
                float e2 = __expf(acc[mt][nt][2] * alpha) * PSCALE;
                float e3 = __expf(acc[mt][nt][3] * alpha) * PSCALE;
                rs[mt][0] += e0 + e1;
                rs[mt][1] += e2 + e3;
                __half2 p01 = {__float2half(e0), __float2half(e1)};
                __half2 p23 = {__float2half(e2), __float2half(e3)};
                *reinterpret_cast<__half2*>(Phb + (size_t)row * ldc + col) = p01;
                *reinterpret_cast<__half2*>(Phb + (size_t)(row + 8) * ldc + col) = p23;
            }
            #pragma unroll
            for (int j = 0; j < 2; j++) {
                rs[mt][j] += __shfl_xor_sync(0xffffffff, rs[mt][j], 1);
                rs[mt][j] += __shfl_xor_sync(0xffffffff, rs[mt][j], 2);
            }
        }
        float* red = reinterpret_cast<float*>(sm);
        if (tq == 0) {
            #pragma unroll
            for (int mt = 0; mt < MT; mt++) {
                red[(wy * (MT * 16) + mt * 16 + quad) * NWX + wx] = rs[mt][0];
                red[(wy * (MT * 16) + mt * 16 + quad + 8) * NWX + wx] = rs[mt][1];
            }
        }
        __syncthreads();
        if (tid < 128) {
            float s = 0.0f;
            #pragma unroll
            for (int x = 0; x < NWX; x++) s += red[tid * NWX + x];
            psum[((size_t)bz * gridDim.x + blockIdx.x) * Mtot + m0 + tid] = s;
        }
    } else if (Oh) {
        // ---- normalize + fp16 single-limb epilogue (PV output) ----
        if (npok[0]) {
            const float* rinv = rowinv + (size_t)bz * (gridDim.y * 128);
            __half* Ohb = Oh + (size_t)bz * sC;
            #pragma unroll
            for (int mt = 0; mt < MT; mt++) {
                const int row = m0 + wy * (MT * 16) + mt * 16 + quad;
                const float s0 = rinv[row];
                const float s1 = rinv[row + 8];
                #pragma unroll
                for (int nt = 0; nt < 2 * NP; nt++) {
                    const int col = n0 + wx * (NP * 16) + nt * 8 + tq * 2;
                    if (col >= n_valid) continue;
                    __half2 o01 = {__float2half(acc[mt][nt][0] * alpha * s0),
                                   __float2half(acc[mt][nt][1] * alpha * s0)};
                    __half2 o23 = {__float2half(acc[mt][nt][2] * alpha * s1),
                                   __float2half(acc[mt][nt][3] * alpha * s1)};
                    *reinterpret_cast<__half2*>(Ohb + (size_t)row * ldc + col) = o01;
                    *reinterpret_cast<__half2*>(Ohb + (size_t)(row + 8) * ldc + col) = o23;
                }
            }
        }
    } else if (npok[0]) {
        // ---- standard epilogue ----
        float* Cb = C + bz * sC;
        #pragma unroll
        for (int mt = 0; mt < MT; mt++) {
            const int row = m0 + wy * (MT * 16) + mt * 16 + quad;
            #pragma unroll
            for (int nt = 0; nt < 2 * NP; nt++) {
                const int col = n0 + wx * (NP * 16) + nt * 8 + tq * 2;
                if (col >= n_valid) continue;
                float b0 = bias ? bias[col] : 0.0f;
                float b1 = bias ? bias[col + 1] : 0.0f;
                float2 v0 = make_float2(acc[mt][nt][0] * alpha + b0,
                                        acc[mt][nt][1] * alpha + b1);
                float2 v1 = make_float2(acc[mt][nt][2] * alpha + b0,
                                        acc[mt][nt][3] * alpha + b1);
                *reinterpret_cast<float2*>(Cb + (size_t)row * ldc + col) = v0;
                *reinterpret_cast<float2*>(Cb + (size_t)(row + 8) * ldc + col) = v1;
            }
        }
    }
}

// ---------------- reduce per-tile partials -> 1/rowsum ----------------------
__global__ __launch_bounds__(256) void reduce_psum(
    const float* __restrict__ psum, float* __restrict__ rowinv)
{
    int i = blockIdx.x * blockDim.x + threadIdx.x;
    if (i >= NH * SEQ) return;
    const int h = i / SEQ, r = i % SEQ;
    float s = 0.0f;
    #pragma unroll
    for (int x = 0; x < 16; x++)
        s += psum[((size_t)h * 16 + x) * SEQ + r];
    rowinv[i] = 1.0f / s;
}

// ---------------- RoPE + fp16 per-head layouts --------------------------------
// Q,K: single limb [h][s][80]. V^T: single limb [h][d][s] (rows>=80 unused).
__global__ __launch_bounds__(256) void rope_split_fp16(
    const float* __restrict__ qkv, const float* __restrict__ cosp,
    const float* __restrict__ sinp,
    __half* __restrict__ Qh, __half* __restrict__ Kh,
    __half* __restrict__ Vth)
{
    int idx = blockIdx.x * blockDim.x + threadIdx.x;
    if (idx >= SEQ * DIM) return;
    const int d = idx % HD;
    const int h = (idx / HD) % NH;
    const int s = idx / DIM;

    const float c = cosp[s * HD + d];
    const float sn = sinp[s * HD + d];
    const int d2 = (d < HD / 2) ? d + HD / 2 : d - HD / 2;
    const float sign = (d < HD / 2) ? -1.0f : 1.0f;

    const size_t rowbase = (size_t)s * QKV_N + h * HD;
    const size_t oqk = ((size_t)h * SEQ + s) * HD + d;
    const size_t ovt = ((size_t)h * HDV + d) * SEQ + s;

    const float qv = qkv[rowbase + d];
    const float q2 = qkv[rowbase + d2];
    Qh[oqk] = __float2half(fmaf(qv, c, sign * q2 * sn));

    const float kv = qkv[rowbase + DIM + d];
    const float k2 = qkv[rowbase + DIM + d2];
    Kh[oqk] = __float2half(fmaf(kv, c, sign * k2 * sn));

    Vth[ovt] = __float2half(qkv[rowbase + 2 * DIM + d]);
}

// ---------------- launch -----------------------------------------------------
extern "C" void kernel_launch(void* const* d_in, const int* in_sizes, int n_in,
                              void* d_out, int out_size)
{
    const float* hidden = (const float*)d_in[0];
    const float* cosp   = (const float*)d_in[2];
    const float* sinp   = (const float*)d_in[3];
    const float* w_qkv  = (const float*)d_in[4];
    const float* b_qkv  = (const float*)d_in[5];
    const float* w_proj = (const float*)d_in[6];
    const float* b_proj = (const float*)d_in[7];
    float* out = (float*)d_out;

    float *qkv, *psum, *rowinv;
    cudaGetSymbolAddress((void**)&qkv, g_qkv);
    cudaGetSymbolAddress((void**)&psum, g_psum);
    cudaGetSymbolAddress((void**)&rowinv, g_rowinv);

    __half *hh, *wqh, *wph, *qh, *kh, *vth, *ph, *oh;
    cudaGetSymbolAddress((void**)&hh, g_hid_h);
    cudaGetSymbolAddress((void**)&wqh, g_wqkv_h);
    cudaGetSymbolAddress((void**)&wph, g_wproj_h);
    cudaGetSymbolAddress((void**)&qh, g_qh);
    cudaGetSymbolAddress((void**)&kh, g_kh);
    cudaGetSymbolAddress((void**)&vth, g_vth);
    cudaGetSymbolAddress((void**)&ph, g_ph);
    cudaGetSymbolAddress((void**)&oh, g_oh);

    const int SM11 = 3 * 2 * MM_TILE_B;   // (1,1): 2 tiles/stage
    cudaFuncSetAttribute(gemm_fp16<1, 1>,
                         cudaFuncAttributeMaxDynamicSharedMemorySize, SM11);

    // 0) prepare fp16 operands (all single-limb)
    round_fp16<<<(SEQ * DIM + 255) / 256, 256>>>(hidden, hh, SEQ * DIM);
    round_fp16<<<(QKV_N * DIM + 255) / 256, 256>>>(w_qkv, wqh, QKV_N * DIM);
    round_fp16<<<(DIM * DIM + 255) / 256, 256>>>(w_proj, wph, DIM * DIM);

    // 1) QKV = hidden @ w_qkv^T + b_qkv   (1x1 limb)
    {
        dim3 grid(QKV_N / 128, SEQ / 128, 1);
        gemm_fp16<1, 1><<<grid, 256, SM11>>>(
            hh, nullptr, wqh, b_qkv, qkv,
            DIM, 0, 0, 0, QKV_N, 1.0f, QKV_N,
            nullptr, nullptr, nullptr, nullptr);
    }
    // 2) RoPE + per-head fp16 layouts (K=80 unpadded)
    rope_split_fp16<<<(SEQ * DIM + 255) / 256, 256>>>(qkv, cosp, sinp,
                                                      qh, kh, vth);

    // 3) fused scores + exp: Ph = fp16(exp(scale*Q@K^T)*PSCALE), row partials
    {
        dim3 grid(SEQ / 128, SEQ / 128, NH);
        gemm_fp16<1, 1><<<grid, 256, SM11>>>(
            qh, nullptr, kh, nullptr, nullptr,
            HD, (size_t)SEQ * HD, (size_t)SEQ * HD,
            (size_t)SEQ * SEQ, SEQ, ATTN_SCALE, SEQ,
            ph, psum, nullptr, nullptr);
    }
    // 4) rowsum partials -> 1/rowsum
    reduce_psum<<<(NH * SEQ + 255) / 256, 256>>>(psum, rowinv);

    // 5) Oh = fp16((Ph @ Vh) * rowinv)   (1x1 limb)
    {
        dim3 grid(1, SEQ / 128, NH);
        gemm_fp16<1, 1><<<grid, 256, SM11>>>(
            ph, nullptr, vth, nullptr, nullptr,
            SEQ, (size_t)SEQ * SEQ, (size_t)HDV * SEQ,
            (size_t)HD, DIM, 1.0f, HD,
            nullptr, nullptr, rowinv, oh);
    }
    // 6) out = O @ w_proj^T + b_proj   (1x1 limb)
    {
        dim3 grid(DIM / 128, SEQ / 128, 1);
        gemm_fp16<1, 1><<<grid, 256, SM11>>>(
            oh, nullptr, wph, b_proj, out,
            DIM, 0, 0, 0, DIM, 1.0f, DIM,
            nullptr, nullptr, nullptr, nullptr);
    }
}

// round 17
// speedup vs baseline: 2.2648x; 1.0158x over previous
#include <cuda_runtime.h>
#include <cuda_fp16.h>
#include <math.h>
#include <cstdint>

#define SEQ 2048
#define NH  16
#define HD  80
#define HDV 128             // padded head dim for V^T (one 128-col N tile)
#define DIM 1280            // NH*HD
#define QKV_N 3840          // 3*DIM
#define ATTN_SCALE 0.11180339887498949f   // 80^-0.5
#define PSCALE 0.0625f      // 2^-4 headroom for fp16 exp storage (cancels in rowinv)

// ---------------- scratch (device globals; no allocations allowed) ----------
__device__ float g_qkv[SEQ * QKV_N];          // 31.5 MB
__device__ float g_psum[NH * 16 * SEQ];       // per-(head, n-tile) row partial sums
__device__ float g_rowinv[NH * SEQ];          // 1 / rowsum (of scaled exp)

__device__ __half g_hid_h[SEQ * DIM];         // hidden: single fp16 limb
__device__ __half g_wqkv_h[QKV_N * DIM];      // weights: single fp16 limb
__device__ __half g_wproj_h[DIM * DIM];
__device__ __half g_qh[NH * SEQ * HD];        // Q: single limb
__device__ __half g_kh[NH * SEQ * HD];        // K: single limb
__device__ __half g_vth[NH * HDV * SEQ];      // V^T: single limb (rows >= HD unused)
__device__ __half g_ph[(size_t)NH * SEQ * SEQ];  // 64 MB (scaled unnormalized expS)
__device__ __half g_oh[SEQ * DIM];            // O: single limb

// ================= helpers ====================================================
__device__ __forceinline__ uint32_t smem_u32(const void* p) {
    uint32_t a;
    asm("{ .reg .u64 t; cvta.to.shared.u64 t, %1; cvt.u32.u64 %0, t; }" : "=r"(a) : "l"(p));
    return a;
}
#define CP_ASYNC16(dst, src) \
    asm volatile("cp.async.cg.shared.global [%0], [%1], 16;" :: "r"(dst), "l"(src) : "memory")
#define CP_COMMIT() asm volatile("cp.async.commit_group;" ::: "memory")
#define CP_WAIT1()  asm volatile("cp.async.wait_group 1;" ::: "memory")

#define LDSM_X4(r0, r1, r2, r3, addr) \
    asm volatile("ldmatrix.sync.aligned.m8n8.x4.shared.b16 {%0,%1,%2,%3}, [%4];" \
        : "=r"(r0), "=r"(r1), "=r"(r2), "=r"(r3) : "r"(addr))

#define MMA16816(c, a, b0, b1) \
    asm volatile("mma.sync.aligned.m16n8k16.row.col.f32.f16.f16.f32 " \
        "{%0,%1,%2,%3}, {%4,%5,%6,%7}, {%8,%9}, {%0,%1,%2,%3};" \
        : "+f"((c)[0]), "+f"((c)[1]), "+f"((c)[2]), "+f"((c)[3]) \
        : "r"((a)[0]), "r"((a)[1]), "r"((a)[2]), "r"((a)[3]), "r"(b0), "r"(b1))

// ================= fp32 -> fp16 prep ==========================================
__global__ __launch_bounds__(256) void round_fp16(
    const float* __restrict__ x, __half* __restrict__ hi, int n)
{
    int i = blockIdx.x * blockDim.x + threadIdx.x;
    if (i >= n) return;
    hi[i] = __float2half(x[i]);
}

// ================= mma.sync fp16 NT GEMM (64x64 warp tiles) ==================
// C = alpha * A(MxK) @ B(NxK)^T (+bias). CTA tile 128x128, 4 warps (2x2),
// warp tile 64x64 -> LDSM bytes/MMA minimized. 3-stage cp.async pipeline.
// K%16==0 (tail = half chunk). Epilogues:
//   psum != null : e = expf(alpha*acc)*PSCALE -> Ph (fp16), row partials -> psum
//   Oh   != null : fp16(acc*alpha*rowinv[row]) -> Oh
//   else         : C = alpha*acc + bias, cols < n_valid
#define MM_TILE_B 10240        // 128 rows * 80 bytes (40 halves, padded from 32)
#define MM_BUF_B  (2 * MM_TILE_B)
#define MM_SMEM   (3 * MM_BUF_B)    // 61440

__global__ __launch_bounds__(128, 2) void gemm_fp16(
    const __half* __restrict__ A0, const __half* __restrict__ B0,
    const float* __restrict__ bias, float* __restrict__ C,
    int K, size_t sA, size_t sB, size_t sC, int ldc, float alpha, int n_valid,
    __half* __restrict__ Ph, float* __restrict__ psum,
    const float* __restrict__ rowinv, __half* __restrict__ Oh)
{
    extern __shared__ char sm[];
    const uint32_t sbase = smem_u32(sm);
    const int tid = threadIdx.x;
    const int lane = tid & 31;
    const int wid = tid >> 5;      // 0..3
    const int wy = wid >> 1;       // 0..1
    const int wx = wid & 1;        // 0..1
    const int m0 = blockIdx.y * 128;
    const int n0 = blockIdx.x * 128;
    const int bz = blockIdx.z;
    const int NC = (K + 31) >> 5;  // chunks; last may be half (16)

    bool npok[4];
    #pragma unroll
    for (int np = 0; np < 4; np++)
        npok[np] = (n0 + wx * 64 + np * 16) < n_valid;

    const __half* srcs[2] = {A0 + bz * sA, B0 + bz * sB};
    const int rbases[2] = {m0, n0};

    float acc[4][8][4];
    #pragma unroll
    for (int i = 0; i < 4; i++)
        #pragma unroll
        for (int j = 0; j < 8; j++)
            #pragma unroll
            for (int k = 0; k < 4; k++) acc[i][j][k] = 0.0f;

    auto load_chunk = [&](int c, int b) {
        const int k0 = c << 5;
        const bool hc = (k0 + 32 > K);
        #pragma unroll
        for (int t = 0; t < 2; t++) {
            const __half* src = srcs[t];
            const int rbase = rbases[t];
            const uint32_t tb = sbase + b * MM_BUF_B + t * MM_TILE_B;
            if (!hc) {
                #pragma unroll
                for (int i = 0; i < 4; i++) {
                    const int g = tid + i * 128;       // 0..511
                    const int row = g >> 2, q = g & 3;
                    const uint32_t dst = tb + row * 80 + q * 16;
                    const void* s = (const void*)(src + (size_t)(rbase + row) * K + k0 + q * 8);
                    CP_ASYNC16(dst, s);
                }
            } else {
                #pragma unroll
                for (int i = 0; i < 2; i++) {
                    const int g = tid + i * 128;       // 0..255 (16 cols only)
                    const int row = g >> 1, q = g & 1;
                    const uint32_t dst = tb + row * 80 + q * 16;
                    const void* s = (const void*)(src + (size_t)(rbase + row) * K + k0 + q * 8);
                    CP_ASYNC16(dst, s);
                }
            }
        }
    };

    // ---- prologue: stage chunks 0 and 1 ----
    load_chunk(0, 0);
    CP_COMMIT();
    if (NC > 1) load_chunk(1, 1);
    CP_COMMIT();

    int bc = 0, lb = 2;
    for (int c = 0; c < NC; c++) {
        CP_WAIT1();
        __syncthreads();

        if (c + 2 < NC) load_chunk(c + 2, lb);
        CP_COMMIT();

        const bool hc = ((c << 5) + 32 > K);
        const uint32_t bufb = sbase + bc * MM_BUF_B;
        if (npok[0]) {
            #pragma unroll
            for (int ks = 0; ks < 2; ks++) {
                if (ks == 1 && hc) break;
                const int fcol = ks * 16 + (lane >> 4) * 8;
                uint32_t bf[4][4];
                #pragma unroll
                for (int np = 0; np < 4; np++) {
                    if (!npok[np]) continue;
                    const int r = wx * 64 + np * 16 + (lane & 15);
                    const uint32_t bd = bufb + MM_TILE_B + r * 80 + fcol * 2;
                    LDSM_X4(bf[np][0], bf[np][1], bf[np][2], bf[np][3], bd);
                }
                #pragma unroll
                for (int mt = 0; mt < 4; mt++) {
                    const int r = wy * 64 + mt * 16 + (lane & 15);
                    const uint32_t ad = bufb + r * 80 + fcol * 2;
                    uint32_t af[4];
                    LDSM_X4(af[0], af[1], af[2], af[3], ad);
                    #pragma unroll
                    for (int np = 0; np < 4; np++) {
                        if (!npok[np]) continue;
                        MMA16816(acc[mt][np * 2],     af, bf[np][0], bf[np][2]);
                        MMA16816(acc[mt][np * 2 + 1], af, bf[np][1], bf[np][3]);
                    }
                }
            }
        }
        bc = (bc == 2) ? 0 : bc + 1;
        lb = (lb == 2) ? 0 : lb + 1;
    }
    __syncthreads();                  // protect epilogue smem reuse

    const int quad = lane >> 2, tq = lane & 3;

    if (psum) {
        // ---- exp epilogue (fused unnormalized softmax, single-limb fp16 P) ----
        const int Mtot = gridDim.y * 128;
        __half* Phb = Ph + (size_t)bz * sC;
        float rs[4][2];
        #pragma unroll
        for (int mt = 0; mt < 4; mt++) { rs[mt][0] = 0.0f; rs[mt][1] = 0.0f; }

        #pragma unroll
        for (int mt = 0; mt < 4; mt++) {
            const int row = m0 + wy * 64 + mt * 16 + quad;
            #pragma unroll
            for (int nt = 0; nt < 8; nt++) {
                const int col = n0 + wx * 64 + nt * 8 + tq * 2;
                float e0 = __expf(acc[mt][nt][0] * alpha) * PSCALE;
                float e1 = __expf(acc[mt][nt][1] * alpha) * PSCALE;
                float e2 = __expf(acc[mt][nt][2] * alpha) * PSCALE;
                float e3 = __expf(acc[mt][nt][3] * alpha) * PSCALE;
                rs[mt][0] += e0 + e1;
                rs[mt][1] += e2 + e3;
                __half2 p01 = {__float2half(e0), __float2half(e1)};
                __half2 p23 = {__float2half(e2), __float2half(e3)};
                *reinterpret_cast<__half2*>(Phb + (size_t)row * ldc + col) = p01;
                *reinterpret_cast<__half2*>(Phb + (size_t)(row + 8) * ldc + col) = p23;
            }
            #pragma unroll
            for (int j = 0; j < 2; j++) {
                rs[mt][j] += __shfl_xor_sync(0xffffffff, rs[mt][j], 1);
                rs[mt][j] += __shfl_xor_sync(0xffffffff, rs[mt][j], 2);
            }
        }
        float* red = reinterpret_cast<float*>(sm);
        if (tq == 0) {
            #pragma unroll
            for (int mt = 0; mt < 4; mt++) {
                red[(wy * 64 + mt * 16 + quad) * 2 + wx] = rs[mt][0];
                red[(wy * 64 + mt * 16 + quad + 8) * 2 + wx] = rs[mt][1];
            }
        }
        __syncthreads();
        {
            float s = red[tid * 2] + red[tid * 2 + 1];
            psum[((size_t)bz * gridDim.x + blockIdx.x) * Mtot + m0 + tid] = s;
        }
    } else if (Oh) {
        // ---- normalize + fp16 epilogue (PV output) ----
        if (npok[0]) {
            const float* rinv = rowinv + (size_t)bz * (gridDim.y * 128);
            __half* Ohb = Oh + (size_t)bz * sC;
            #pragma unroll
            for (int mt = 0; mt < 4; mt++) {
                const int row = m0 + wy * 64 + mt * 16 + quad;
                const float s0 = rinv[row];
                const float s1 = rinv[row + 8];
                #pragma unroll
                for (int nt = 0; nt < 8; nt++) {
                    const int col = n0 + wx * 64 + nt * 8 + tq * 2;
                    if (col >= n_valid) continue;
                    __half2 o01 = {__float2half(acc[mt][nt][0] * alpha * s0),
                                   __float2half(acc[mt][nt][1] * alpha * s0)};
                    __half2 o23 = {__float2half(acc[mt][nt][2] * alpha * s1),
                                   __float2half(acc[mt][nt][3] * alpha * s1)};
                    *reinterpret_cast<__half2*>(Ohb + (size_t)row * ldc + col) = o01;
                    *reinterpret_cast<__half2*>(Ohb + (size_t)(row + 8) * ldc + col) = o23;
                }
            }
        }
    } else if (npok[0]) {
        // ---- standard epilogue ----
        float* Cb = C + bz * sC;
        #pragma unroll
        for (int mt = 0; mt < 4; mt++) {
            const int row = m0 + wy * 64 + mt * 16 + quad;
            #pragma unroll
            for (int nt = 0; nt < 8; nt++) {
                const int col = n0 + wx * 64 + nt * 8 + tq * 2;
                if (col >= n_valid) continue;
                float b0 = bias ? bias[col] : 0.0f;
                float b1 = bias ? bias[col + 1] : 0.0f;
                float2 v0 = make_float2(acc[mt][nt][0] * alpha + b0,
                                        acc[mt][nt][1] * alpha + b1);
                float2 v1 = make_float2(acc[mt][nt][2] * alpha + b0,
                                        acc[mt][nt][3] * alpha + b1);
                *reinterpret_cast<float2*>(Cb + (size_t)row * ldc + col) = v0;
                *reinterpret_cast<float2*>(Cb + (size_t)(row + 8) * ldc + col) = v1;
            }
        }
    }
}

// ---------------- reduce per-tile partials -> 1/rowsum ----------------------
__global__ __launch_bounds__(256) void reduce_psum(
    const float* __restrict__ psum, float* __restrict__ rowinv)
{
    int i = blockIdx.x * blockDim.x + threadIdx.x;
    if (i >= NH * SEQ) return;
    const int h = i / SEQ, r = i % SEQ;
    float s = 0.0f;
    #pragma unroll
    for (int x = 0; x < 16; x++)
        s += psum[((size_t)h * 16 + x) * SEQ + r];
    rowinv[i] = 1.0f / s;
}

// ---------------- RoPE + fp16 per-head layouts --------------------------------
// Q,K: single limb [h][s][80]. V^T: single limb [h][d][s] (rows>=80 unused).
__global__ __launch_bounds__(256) void rope_split_fp16(
    const float* __restrict__ qkv, const float* __restrict__ cosp,
    const float* __restrict__ sinp,
    __half* __restrict__ Qh, __half* __restrict__ Kh,
    __half* __restrict__ Vth)
{
    int idx = blockIdx.x * blockDim.x + threadIdx.x;
    if (idx >= SEQ * DIM) return;
    const int d = idx % HD;
    const int h = (idx / HD) % NH;
    const int s = idx / DIM;

    const float c = cosp[s * HD + d];
    const float sn = sinp[s * HD + d];
    const int d2 = (d < HD / 2) ? d + HD / 2 : d - HD / 2;
    const float sign = (d < HD / 2) ? -1.0f : 1.0f;

    const size_t rowbase = (size_t)s * QKV_N + h * HD;
    const size_t oqk = ((size_t)h * SEQ + s) * HD + d;
    const size_t ovt = ((size_t)h * HDV + d) * SEQ + s;

    const float qv = qkv[rowbase + d];
    const float q2 = qkv[rowbase + d2];
    Qh[oqk] = __float2half(fmaf(qv, c, sign * q2 * sn));

    const float kv = qkv[rowbase + DIM + d];
    const float k2 = qkv[rowbase + DIM + d2];
    Kh[oqk] = __float2half(fmaf(kv, c, sign * k2 * sn));

    Vth[ovt] = __float2half(qkv[rowbase + 2 * DIM + d]);
}

// ---------------- launch -----------------------------------------------------
extern "C" void kernel_launch(void* const* d_in, const int* in_sizes, int n_in,
                              void* d_out, int out_size)
{
    const float* hidden = (const float*)d_in[0];
    const float* cosp   = (const float*)d_in[2];
    const float* sinp   = (const float*)d_in[3];
    const float* w_qkv  = (const float*)d_in[4];
    const float* b_qkv  = (const float*)d_in[5];
    const float* w_proj = (const float*)d_in[6];
    const float* b_proj = (const float*)d_in[7];
    float* out = (float*)d_out;

    float *qkv, *psum, *rowinv;
    cudaGetSymbolAddress((void**)&qkv, g_qkv);
    cudaGetSymbolAddress((void**)&psum, g_psum);
    cudaGetSymbolAddress((void**)&rowinv, g_rowinv);

    __half *hh, *wqh, *wph, *qh, *kh, *vth, *ph, *oh;
    cudaGetSymbolAddress((void**)&hh, g_hid_h);
    cudaGetSymbolAddress((void**)&wqh, g_wqkv_h);
    cudaGetSymbolAddress((void**)&wph, g_wproj_h);
    cudaGetSymbolAddress((void**)&qh, g_qh);
    cudaGetSymbolAddress((void**)&kh, g_kh);
    cudaGetSymbolAddress((void**)&vth, g_vth);
    cudaGetSymbolAddress((void**)&ph, g_ph);
    cudaGetSymbolAddress((void**)&oh, g_oh);

    cudaFuncSetAttribute(gemm_fp16,
                         cudaFuncAttributeMaxDynamicSharedMemorySize, MM_SMEM);

    // 0) prepare fp16 operands (all single-limb)
    round_fp16<<<(SEQ * DIM + 255) / 256, 256>>>(hidden, hh, SEQ * DIM);
    round_fp16<<<(QKV_N * DIM + 255) / 256, 256>>>(w_qkv, wqh, QKV_N * DIM);
    round_fp16<<<(DIM * DIM + 255) / 256, 256>>>(w_proj, wph, DIM * DIM);

    // 1) QKV = hidden @ w_qkv^T + b_qkv
    {
        dim3 grid(QKV_N / 128, SEQ / 128, 1);
        gemm_fp16<<<grid, 128, MM_SMEM>>>(
            hh, wqh, b_qkv, qkv,
            DIM, 0, 0, 0, QKV_N, 1.0f, QKV_N,
            nullptr, nullptr, nullptr, nullptr);
    }
    // 2) RoPE + per-head fp16 layouts (K=80 unpadded)
    rope_split_fp16<<<(SEQ * DIM + 255) / 256, 256>>>(qkv, cosp, sinp,
                                                      qh, kh, vth);

    // 3) fused scores + exp: Ph = fp16(exp(scale*Q@K^T)*PSCALE), row partials
    {
        dim3 grid(SEQ / 128, SEQ / 128, NH);
        gemm_fp16<<<grid, 128, MM_SMEM>>>(
            qh, kh, nullptr, nullptr,
            HD, (size_t)SEQ * HD, (size_t)SEQ * HD,
            (size_t)SEQ * SEQ, SEQ, ATTN_SCALE, SEQ,
            ph, psum, nullptr, nullptr);
    }
    // 4) rowsum partials -> 1/rowsum
    reduce_psum<<<(NH * SEQ + 255) / 256, 256>>>(psum, rowinv);

    // 5) Oh = fp16((Ph @ Vh) * rowinv)
    {
        dim3 grid(1, SEQ / 128, NH);
        gemm_fp16<<<grid, 128, MM_SMEM>>>(
            ph, vth, nullptr, nullptr,
            SEQ, (size_t)SEQ * SEQ, (size_t)HDV * SEQ,
            (size_t)HD, DIM, 1.0f, HD,
            nullptr, nullptr, rowinv, oh);
    }
    // 6) out = O @ w_proj^T + b_proj
    {
        dim3 grid(DIM / 128, SEQ / 128, 1);
        gemm_fp16<<<grid, 128, MM_SMEM>>>(
            oh, wph, b_proj, out,
            DIM, 0, 0, 0, DIM, 1.0f, DIM,
            nullptr, nullptr, nullptr, nullptr);
    }
}